// round 3
// baseline (speedup 1.0000x reference)
#include <cuda_runtime.h>
#include <mma.h>
#include <cstddef>
#include <cstdint>

using namespace nvcuda;

#define LLAYERS 6
#define BB 4
#define NN 1024
#define DD 1024
#define HH 16
#define HDIM 64
#define FF 4096
#define MTOK (BB * NN)      /* 4096 */
#define LN_EPS 1e-5f

// ---------------- scratch (no allocations allowed) ----------------
__device__ float g_Q[(size_t)MTOK * DD];
__device__ float g_K[(size_t)MTOK * DD];
__device__ float g_V[(size_t)MTOK * DD];
__device__ float g_T[(size_t)MTOK * DD];
__device__ float g_Y[(size_t)MTOK * DD];
__device__ float g_Hb[(size_t)MTOK * FF];

// ---------------- cp.async helpers ----------------
__device__ __forceinline__ void cp16(void* sptr, const void* gptr) {
    uint32_t sa = (uint32_t)__cvta_generic_to_shared(sptr);
    asm volatile("cp.async.cg.shared.global [%0], [%1], 16;\n" :: "r"(sa), "l"(gptr));
}
#define CP_COMMIT() asm volatile("cp.async.commit_group;\n" ::: "memory")
#define CP_WAIT0()  asm volatile("cp.async.wait_group 0;\n" ::: "memory")

// =====================================================================
// TF32 TC GEMM v2: C[M,N] = A[M,K] @ W[N,K]^T + bias (+res) (+relu)
// 128x128 tile, BK=32, 2-stage cp.async pipeline, 256 thr = 8 warps,
// warp tile 64x32. tf32 convert at fragment level.
// =====================================================================
#define GBK 32
#define GST 36                       /* padded row stride (floats) */
#define GEMM_BUF (128 * GST)         /* floats per matrix per stage */
#define GEMM_SMEM_BYTES (4 * GEMM_BUF * 4)   /* A0,W0,A1,W1 = 73728 B */

__global__ __launch_bounds__(256, 2) void gemm_nt_tc(
    const float* __restrict__ A, const float* __restrict__ W,
    const float* __restrict__ bias, const float* __restrict__ res,
    float* __restrict__ C, int M, int N, int K, int doRelu)
{
    extern __shared__ float dyn[];
    __shared__ float stage[8][16 * 16];

    const int tid  = threadIdx.x;
    const int warp = tid >> 5;
    const int lane = tid & 31;
    const int wm   = warp >> 2;   // 0..1 -> m offset wm*64
    const int wn   = warp & 3;    // 0..3 -> n offset wn*32

    const float* Ab = A + (size_t)blockIdx.y * 128 * K;
    const float* Wb = W + (size_t)blockIdx.x * 128 * K;

    // chunk mapping for one 128x32 tile: 1024 x 16B chunks, 4 per thread
    const int crow[4] = { (tid + 0) >> 3, (tid + 256) >> 3,
                          (tid + 512) >> 3, (tid + 768) >> 3 };
    const int ccol = (tid & 7) << 2;

    wmma::fragment<wmma::accumulator, 16, 16, 8, float> acc[4][2];
#pragma unroll
    for (int i = 0; i < 4; i++)
#pragma unroll
        for (int j = 0; j < 2; j++) wmma::fill_fragment(acc[i][j], 0.f);

    const int KT = K / GBK;

    // issue stage 0
    {
        float* As = dyn;
        float* Ws = dyn + GEMM_BUF;
#pragma unroll
        for (int s = 0; s < 4; s++) {
            cp16(&As[crow[s] * GST + ccol], Ab + (size_t)crow[s] * K + ccol);
            cp16(&Ws[crow[s] * GST + ccol], Wb + (size_t)crow[s] * K + ccol);
        }
        CP_COMMIT();
    }

    for (int kt = 0; kt < KT; kt++) {
        CP_WAIT0();
        __syncthreads();

        if (kt + 1 < KT) {
            float* As = dyn + ((kt + 1) & 1) * 2 * GEMM_BUF;
            float* Ws = As + GEMM_BUF;
            int k0 = (kt + 1) * GBK;
#pragma unroll
            for (int s = 0; s < 4; s++) {
                cp16(&As[crow[s] * GST + ccol], Ab + (size_t)crow[s] * K + k0 + ccol);
                cp16(&Ws[crow[s] * GST + ccol], Wb + (size_t)crow[s] * K + k0 + ccol);
            }
            CP_COMMIT();
        }

        const float* As = dyn + (kt & 1) * 2 * GEMM_BUF;
        const float* Ws = As + GEMM_BUF;
#pragma unroll
        for (int kk = 0; kk < GBK; kk += 8) {
            wmma::fragment<wmma::matrix_a, 16, 16, 8, wmma::precision::tf32,
                           wmma::row_major> af[4];
            wmma::fragment<wmma::matrix_b, 16, 16, 8, wmma::precision::tf32,
                           wmma::col_major> bf[2];
#pragma unroll
            for (int i = 0; i < 4; i++) {
                wmma::load_matrix_sync(af[i], &As[(wm * 64 + i * 16) * GST + kk], GST);
#pragma unroll
                for (int e = 0; e < af[i].num_elements; e++)
                    af[i].x[e] = wmma::__float_to_tf32(af[i].x[e]);
            }
#pragma unroll
            for (int j = 0; j < 2; j++) {
                wmma::load_matrix_sync(bf[j], &Ws[(wn * 32 + j * 16) * GST + kk], GST);
#pragma unroll
                for (int e = 0; e < bf[j].num_elements; e++)
                    bf[j].x[e] = wmma::__float_to_tf32(bf[j].x[e]);
            }
#pragma unroll
            for (int i = 0; i < 4; i++)
#pragma unroll
                for (int j = 0; j < 2; j++)
                    wmma::mma_sync(acc[i][j], af[i], bf[j], acc[i][j]);
        }
        __syncthreads();
    }

    // epilogue: per-warp 16x16 staging, fused bias/res/relu
#pragma unroll
    for (int i = 0; i < 4; i++) {
#pragma unroll
        for (int j = 0; j < 2; j++) {
            wmma::store_matrix_sync(stage[warp], acc[i][j], 16, wmma::mem_row_major);
            __syncwarp();
            int r0 = blockIdx.y * 128 + wm * 64 + i * 16;
            int c0 = blockIdx.x * 128 + wn * 32 + j * 16;
#pragma unroll
            for (int e = 0; e < 2; e++) {
                int idx = lane + e * 32;       // 0..63 float4 units
                int rr  = idx >> 2;
                int cc  = (idx & 3) << 2;
                float4 v  = *(float4*)&stage[warp][rr * 16 + cc];
                float4 b4 = *(const float4*)(bias + c0 + cc);
                v.x += b4.x; v.y += b4.y; v.z += b4.z; v.w += b4.w;
                size_t row = (size_t)(r0 + rr);
                if (res) {
                    float4 r = *(const float4*)(res + row * N + c0 + cc);
                    v.x += r.x; v.y += r.y; v.z += r.z; v.w += r.w;
                }
                if (doRelu) {
                    v.x = fmaxf(v.x, 0.f); v.y = fmaxf(v.y, 0.f);
                    v.z = fmaxf(v.z, 0.f); v.w = fmaxf(v.w, 0.f);
                }
                *(float4*)(C + row * N + c0 + cc) = v;
            }
            __syncwarp();
        }
    }
}

// =====================================================================
// Fused attention: per block = one z = (b,h), one 32-row i-tile.
// Phase 1: S[32,1024] = (Q*0.125) @ K^T  (TC, S lives in smem)
// Phase 2: exact softmax over rows (mask added), values stored as tf32
// Phase 3: O[32,64] = P @ V (TC), scale rows by 1/sum, write T
// grid: (N/32 i-tiles, B*H). 256 threads = 8 warps (2 x 4).
// =====================================================================
#define SROWS 32
#define SST 1028                       /* 1024 + 4 pad: stride%32 == 4 */
#define KST 68                         /* 64 + 4 pad */
#define ATT_S_OFF   0
#define ATT_Q_OFF   (SROWS * SST)                 /* 32x68, reused as O stage */
#define ATT_KV_OFF  (ATT_Q_OFF + SROWS * KST)     /* 64x68 */
#define ATT_INV_OFF (ATT_KV_OFF + 64 * KST)       /* 32 floats */
#define ATT_SMEM_BYTES ((ATT_INV_OFF + 32) * 4)

__global__ __launch_bounds__(256, 1) void attn_fused(
    const float* __restrict__ Q, const float* __restrict__ Kb,
    const float* __restrict__ V, float* __restrict__ T,
    const float* __restrict__ mask)
{
    extern __shared__ float dyn[];
    float* Ssm = dyn + ATT_S_OFF;
    float* Qs  = dyn + ATT_Q_OFF;
    float* KVs = dyn + ATT_KV_OFF;
    float* inv = dyn + ATT_INV_OFF;

    const int z = blockIdx.y;
    const int b = z >> 4, h = z & 15;
    const float* Qz = Q  + (size_t)b * NN * DD + h * HDIM;
    const float* Kz = Kb + (size_t)b * NN * DD + h * HDIM;
    const float* Vz = V  + (size_t)b * NN * DD + h * HDIM;
    float*       Tz = T  + (size_t)b * NN * DD + h * HDIM;
    const int i0 = blockIdx.x * SROWS;

    const int tid  = threadIdx.x;
    const int warp = tid >> 5;
    const int wm   = warp >> 2;   // 0..1
    const int wn   = warp & 3;    // 0..3

    // ---- load Q tile (scaled, tf32) ----
#pragma unroll
    for (int s = 0; s < 2; s++) {
        int idx = tid + s * 256;          // 512 float4 units of 32x64
        int row = idx >> 4;
        int cq  = (idx & 15) << 2;
        float4 q = *(const float4*)(Qz + (size_t)(i0 + row) * DD + cq);
        Qs[row * KST + cq + 0] = wmma::__float_to_tf32(q.x * 0.125f);
        Qs[row * KST + cq + 1] = wmma::__float_to_tf32(q.y * 0.125f);
        Qs[row * KST + cq + 2] = wmma::__float_to_tf32(q.z * 0.125f);
        Qs[row * KST + cq + 3] = wmma::__float_to_tf32(q.w * 0.125f);
    }
    __syncthreads();

    // pre-load Q fragments (constant across j-tiles)
    wmma::fragment<wmma::matrix_a, 16, 16, 8, wmma::precision::tf32,
                   wmma::row_major> qf[8];
#pragma unroll
    for (int kk = 0; kk < 8; kk++)
        wmma::load_matrix_sync(qf[kk], &Qs[(wm * 16) * KST + kk * 8], KST);

    // ---- phase 1: S = Qs @ K^T ----
    for (int j0 = 0; j0 < NN / 64; j0++) {
        __syncthreads();   // prior consumers of KVs done
#pragma unroll
        for (int s = 0; s < 4; s++) {
            int idx = tid + s * 256;       // 1024 float4 units of 64x64
            int row = idx >> 4;
            int cq  = (idx & 15) << 2;
            float4 k = *(const float4*)(Kz + (size_t)(j0 * 64 + row) * DD + cq);
            KVs[row * KST + cq + 0] = wmma::__float_to_tf32(k.x);
            KVs[row * KST + cq + 1] = wmma::__float_to_tf32(k.y);
            KVs[row * KST + cq + 2] = wmma::__float_to_tf32(k.z);
            KVs[row * KST + cq + 3] = wmma::__float_to_tf32(k.w);
        }
        __syncthreads();

        wmma::fragment<wmma::accumulator, 16, 16, 8, float> sacc;
        wmma::fill_fragment(sacc, 0.f);
#pragma unroll
        for (int kk = 0; kk < 8; kk++) {
            wmma::fragment<wmma::matrix_b, 16, 16, 8, wmma::precision::tf32,
                           wmma::col_major> bf;
            wmma::load_matrix_sync(bf, &KVs[(wn * 16) * KST + kk * 8], KST);
            wmma::mma_sync(sacc, qf[kk], bf, sacc);
        }
        wmma::store_matrix_sync(&Ssm[(wm * 16) * SST + j0 * 64 + wn * 16],
                                sacc, SST, wmma::mem_row_major);
    }
    __syncthreads();

    // ---- phase 2: softmax (exact, mask folded) ----
    {
        const int r = tid >> 3;          // 0..31
        const int g = tid & 7;           // 0..7
        const float* mrow = mask + (size_t)(i0 + r) * NN;
        float* srow = &Ssm[r * SST];

        float m = -1e30f;
#pragma unroll 8
        for (int s = 0; s < 32; s++) {
            int c = s * 32 + g * 4;
            float4 v = *(float4*)(srow + c);
            float4 mk = *(const float4*)(mrow + c);
            v.x += mk.x; v.y += mk.y; v.z += mk.z; v.w += mk.w;
            *(float4*)(srow + c) = v;
            m = fmaxf(m, fmaxf(fmaxf(v.x, v.y), fmaxf(v.z, v.w)));
        }
#pragma unroll
        for (int o = 4; o > 0; o >>= 1)
            m = fmaxf(m, __shfl_xor_sync(0xffffffffu, m, o, 8));

        float sum = 0.f;
#pragma unroll 8
        for (int s = 0; s < 32; s++) {
            int c = s * 32 + g * 4;
            float4 v = *(float4*)(srow + c);
            v.x = __expf(v.x - m); v.y = __expf(v.y - m);
            v.z = __expf(v.z - m); v.w = __expf(v.w - m);
            sum += v.x + v.y + v.z + v.w;
            v.x = wmma::__float_to_tf32(v.x);
            v.y = wmma::__float_to_tf32(v.y);
            v.z = wmma::__float_to_tf32(v.z);
            v.w = wmma::__float_to_tf32(v.w);
            *(float4*)(srow + c) = v;
        }
#pragma unroll
        for (int o = 4; o > 0; o >>= 1)
            sum += __shfl_xor_sync(0xffffffffu, sum, o, 8);
        if (g == 0) inv[r] = 1.f / sum;
    }
    __syncthreads();

    // ---- phase 3: O = P @ V ----
    wmma::fragment<wmma::accumulator, 16, 16, 8, float> oacc;
    wmma::fill_fragment(oacc, 0.f);

    for (int j0 = 0; j0 < NN / 64; j0++) {
        __syncthreads();
#pragma unroll
        for (int s = 0; s < 4; s++) {
            int idx = tid + s * 256;
            int row = idx >> 4;
            int cq  = (idx & 15) << 2;
            float4 v = *(const float4*)(Vz + (size_t)(j0 * 64 + row) * DD + cq);
            KVs[row * KST + cq + 0] = wmma::__float_to_tf32(v.x);
            KVs[row * KST + cq + 1] = wmma::__float_to_tf32(v.y);
            KVs[row * KST + cq + 2] = wmma::__float_to_tf32(v.z);
            KVs[row * KST + cq + 3] = wmma::__float_to_tf32(v.w);
        }
        __syncthreads();
#pragma unroll
        for (int kk = 0; kk < 8; kk++) {
            wmma::fragment<wmma::matrix_a, 16, 16, 8, wmma::precision::tf32,
                           wmma::row_major> pf;
            wmma::fragment<wmma::matrix_b, 16, 16, 8, wmma::precision::tf32,
                           wmma::row_major> vf;
            wmma::load_matrix_sync(pf, &Ssm[(wm * 16) * SST + j0 * 64 + kk * 8], SST);
            wmma::load_matrix_sync(vf, &KVs[(kk * 8) * KST + wn * 16], KST);
            wmma::mma_sync(oacc, pf, vf, oacc);
        }
    }
    __syncthreads();

    // ---- epilogue: stage O (reuse Qs), scale by 1/sum, write T ----
    wmma::store_matrix_sync(&Qs[(wm * 16) * KST + wn * 16], oacc, KST,
                            wmma::mem_row_major);
    __syncthreads();
#pragma unroll
    for (int s = 0; s < 2; s++) {
        int idx = tid + s * 256;
        int row = idx >> 4;
        int cq  = (idx & 15) << 2;
        float sc = inv[row];
        float4 o = *(float4*)(&Qs[row * KST + cq]);
        o.x *= sc; o.y *= sc; o.z *= sc; o.w *= sc;
        *(float4*)(Tz + (size_t)(i0 + row) * DD + cq) = o;
    }
}

// =====================================================================
// LayerNorm over last dim (1024). One block per row. In-place safe.
// =====================================================================
__global__ __launch_bounds__(256) void layernorm_row(
    const float* __restrict__ X, const float* __restrict__ g,
    const float* __restrict__ bta, float* __restrict__ Y)
{
    __shared__ float red[256];
    const size_t base = (size_t)blockIdx.x * DD;
    const int tid = threadIdx.x;
    float4 v = *(const float4*)(X + base + tid * 4);

    red[tid] = v.x + v.y + v.z + v.w; __syncthreads();
    for (int s = 128; s > 0; s >>= 1) {
        if (tid < s) red[tid] += red[tid + s];
        __syncthreads();
    }
    float mean = red[0] * (1.f / DD); __syncthreads();

    float dx = v.x - mean, dy = v.y - mean, dz = v.z - mean, dw = v.w - mean;
    red[tid] = dx * dx + dy * dy + dz * dz + dw * dw; __syncthreads();
    for (int s = 128; s > 0; s >>= 1) {
        if (tid < s) red[tid] += red[tid + s];
        __syncthreads();
    }
    float inv = rsqrtf(red[0] * (1.f / DD) + LN_EPS);

    float4 gg = *(const float4*)(g + tid * 4);
    float4 bb = *(const float4*)(bta + tid * 4);
    float4 o;
    o.x = dx * inv * gg.x + bb.x;
    o.y = dy * inv * gg.y + bb.y;
    o.z = dz * inv * gg.z + bb.z;
    o.w = dw * inv * gg.w + bb.w;
    *(float4*)(Y + base + tid * 4) = o;
}

// =====================================================================
// Host orchestration
// =====================================================================
extern "C" void kernel_launch(void* const* d_in, const int* in_sizes, int n_in,
                              void* d_out, int out_size)
{
    const float* feats    = (const float*)d_in[0];
    const float* enc      = (const float*)d_in[1];
    const float* trg_mask = (const float*)d_in[2];
    const float* src_mask = (const float*)d_in[3];
    const float* wq1 = (const float*)d_in[4];  const float* bq1 = (const float*)d_in[5];
    const float* wk1 = (const float*)d_in[6];  const float* bk1 = (const float*)d_in[7];
    const float* wv1 = (const float*)d_in[8];  const float* bv1 = (const float*)d_in[9];
    const float* wo1 = (const float*)d_in[10]; const float* bo1 = (const float*)d_in[11];
    const float* wq2 = (const float*)d_in[12]; const float* bq2 = (const float*)d_in[13];
    const float* wk2 = (const float*)d_in[14]; const float* bk2 = (const float*)d_in[15];
    const float* wv2 = (const float*)d_in[16]; const float* bv2 = (const float*)d_in[17];
    const float* wo2 = (const float*)d_in[18]; const float* bo2 = (const float*)d_in[19];
    const float* wf1 = (const float*)d_in[20]; const float* bf1 = (const float*)d_in[21];
    const float* wf2 = (const float*)d_in[22]; const float* bf2 = (const float*)d_in[23];
    const float* g1  = (const float*)d_in[24]; const float* be1 = (const float*)d_in[25];
    const float* g2  = (const float*)d_in[26]; const float* be2 = (const float*)d_in[27];
    const float* g3  = (const float*)d_in[28]; const float* be3 = (const float*)d_in[29];
    float* out = (float*)d_out;

    static int attr_done = 0;
    if (!attr_done) {
        cudaFuncSetAttribute(gemm_nt_tc,
            cudaFuncAttributeMaxDynamicSharedMemorySize, GEMM_SMEM_BYTES);
        cudaFuncSetAttribute(attn_fused,
            cudaFuncAttributeMaxDynamicSharedMemorySize, ATT_SMEM_BYTES);
        attr_done = 1;
    }

    float *Q, *K, *V, *T, *Y, *Hb;
    cudaGetSymbolAddress((void**)&Q,  g_Q);
    cudaGetSymbolAddress((void**)&K,  g_K);
    cudaGetSymbolAddress((void**)&V,  g_V);
    cudaGetSymbolAddress((void**)&T,  g_T);
    cudaGetSymbolAddress((void**)&Y,  g_Y);
    cudaGetSymbolAddress((void**)&Hb, g_Hb);

    dim3 blk(256);
    dim3 gD(DD / 128, MTOK / 128);   // 4096 x 1024 outputs
    dim3 gF(FF / 128, MTOK / 128);   // 4096 x 4096 outputs
    dim3 gA(NN / SROWS, BB * HH);    // fused attention

    const float* X = enc;            // decoder state entering layer l
    for (int l = 0; l < LLAYERS; l++) {
        const float* feat = feats + (size_t)l * MTOK * DD;
        const size_t wOff = (size_t)l * DD * DD;
        const size_t vOff = (size_t)l * DD;

        // ---- attn1: cross-attention (q from feat, k/v from enc, src_mask) ----
        gemm_nt_tc<<<gD, blk, GEMM_SMEM_BYTES>>>(feat, wq1 + wOff, bq1 + vOff, nullptr, Q, MTOK, DD, DD, 0);
        gemm_nt_tc<<<gD, blk, GEMM_SMEM_BYTES>>>(enc,  wk1 + wOff, bk1 + vOff, nullptr, K, MTOK, DD, DD, 0);
        gemm_nt_tc<<<gD, blk, GEMM_SMEM_BYTES>>>(enc,  wv1 + wOff, bv1 + vOff, nullptr, V, MTOK, DD, DD, 0);
        attn_fused<<<gA, blk, ATT_SMEM_BYTES>>>(Q, K, V, T, src_mask);
        gemm_nt_tc<<<gD, blk, GEMM_SMEM_BYTES>>>(T, wo1 + wOff, bo1 + vOff, feat, Y, MTOK, DD, DD, 0);
        layernorm_row<<<MTOK, blk>>>(Y, g1 + vOff, be1 + vOff, Y);

        // ---- attn2: attention to previous decoder output (trg_mask) ----
        gemm_nt_tc<<<gD, blk, GEMM_SMEM_BYTES>>>(Y, wq2 + wOff, bq2 + vOff, nullptr, Q, MTOK, DD, DD, 0);
        gemm_nt_tc<<<gD, blk, GEMM_SMEM_BYTES>>>(X, wk2 + wOff, bk2 + vOff, nullptr, K, MTOK, DD, DD, 0);
        gemm_nt_tc<<<gD, blk, GEMM_SMEM_BYTES>>>(X, wv2 + wOff, bv2 + vOff, nullptr, V, MTOK, DD, DD, 0);
        attn_fused<<<gA, blk, ATT_SMEM_BYTES>>>(Q, K, V, T, trg_mask);
        gemm_nt_tc<<<gD, blk, GEMM_SMEM_BYTES>>>(T, wo2 + wOff, bo2 + vOff, Y, Y, MTOK, DD, DD, 0);
        layernorm_row<<<MTOK, blk>>>(Y, g2 + vOff, be2 + vOff, Y);

        // ---- FFN ----
        gemm_nt_tc<<<gF, blk, GEMM_SMEM_BYTES>>>(Y, wf1 + (size_t)l * FF * DD, bf1 + (size_t)l * FF,
                                                 nullptr, Hb, MTOK, FF, DD, 1);
        gemm_nt_tc<<<gD, blk, GEMM_SMEM_BYTES>>>(Hb, wf2 + (size_t)l * DD * FF, bf2 + vOff, Y, Y,
                                                 MTOK, DD, FF, 0);
        float* outl = out + (size_t)l * MTOK * DD;
        layernorm_row<<<MTOK, blk>>>(Y, g3 + vOff, be3 + vOff, outl);

        X = outl;   // next layer reads decoder state from the output slab
    }
    (void)in_sizes; (void)n_in; (void)out_size;
}

// round 4
// speedup vs baseline: 1.0369x; 1.0369x over previous
#include <cuda_runtime.h>
#include <mma.h>
#include <cstddef>
#include <cstdint>

using namespace nvcuda;

#define LLAYERS 6
#define BB 4
#define NN 1024
#define DD 1024
#define HH 16
#define HDIM 64
#define FF 4096
#define MTOK (BB * NN)      /* 4096 */
#define LN_EPS 1e-5f

// ---------------- scratch (no allocations allowed) ----------------
__device__ float g_Q[(size_t)MTOK * DD];
__device__ float g_K[(size_t)MTOK * DD];
__device__ float g_V[(size_t)MTOK * DD];
__device__ float g_T[(size_t)MTOK * DD];
__device__ float g_Y[(size_t)MTOK * DD];
__device__ float g_Hb[(size_t)MTOK * FF];

// ---------------- cp.async helpers ----------------
__device__ __forceinline__ void cp16(void* sptr, const void* gptr) {
    uint32_t sa = (uint32_t)__cvta_generic_to_shared(sptr);
    asm volatile("cp.async.cg.shared.global [%0], [%1], 16;\n" :: "r"(sa), "l"(gptr));
}
#define CP_COMMIT() asm volatile("cp.async.commit_group;\n" ::: "memory")
#define CP_WAIT0()  asm volatile("cp.async.wait_group 0;\n" ::: "memory")

// =====================================================================
// TF32 TC GEMM v2: C[M,N] = A[M,K] @ W[N,K]^T + bias (+res) (+relu)
// 128x128 tile, BK=32, 2-stage cp.async pipeline, 256 thr = 8 warps,
// warp tile 64x32. tf32 convert at fragment level. (unchanged from R3)
// =====================================================================
#define GBK 32
#define GST 36
#define GEMM_BUF (128 * GST)
#define GEMM_SMEM_BYTES (4 * GEMM_BUF * 4)   /* 73728 B */

__global__ __launch_bounds__(256, 2) void gemm_nt_tc(
    const float* __restrict__ A, const float* __restrict__ W,
    const float* __restrict__ bias, const float* __restrict__ res,
    float* __restrict__ C, int M, int N, int K, int doRelu)
{
    extern __shared__ float dyn[];
    __shared__ float stage[8][16 * 16];

    const int tid  = threadIdx.x;
    const int warp = tid >> 5;
    const int lane = tid & 31;
    const int wm   = warp >> 2;
    const int wn   = warp & 3;

    const float* Ab = A + (size_t)blockIdx.y * 128 * K;
    const float* Wb = W + (size_t)blockIdx.x * 128 * K;

    const int crow[4] = { (tid + 0) >> 3, (tid + 256) >> 3,
                          (tid + 512) >> 3, (tid + 768) >> 3 };
    const int ccol = (tid & 7) << 2;

    wmma::fragment<wmma::accumulator, 16, 16, 8, float> acc[4][2];
#pragma unroll
    for (int i = 0; i < 4; i++)
#pragma unroll
        for (int j = 0; j < 2; j++) wmma::fill_fragment(acc[i][j], 0.f);

    const int KT = K / GBK;

    {
        float* As = dyn;
        float* Ws = dyn + GEMM_BUF;
#pragma unroll
        for (int s = 0; s < 4; s++) {
            cp16(&As[crow[s] * GST + ccol], Ab + (size_t)crow[s] * K + ccol);
            cp16(&Ws[crow[s] * GST + ccol], Wb + (size_t)crow[s] * K + ccol);
        }
        CP_COMMIT();
    }

    for (int kt = 0; kt < KT; kt++) {
        CP_WAIT0();
        __syncthreads();

        if (kt + 1 < KT) {
            float* As = dyn + ((kt + 1) & 1) * 2 * GEMM_BUF;
            float* Ws = As + GEMM_BUF;
            int k0 = (kt + 1) * GBK;
#pragma unroll
            for (int s = 0; s < 4; s++) {
                cp16(&As[crow[s] * GST + ccol], Ab + (size_t)crow[s] * K + k0 + ccol);
                cp16(&Ws[crow[s] * GST + ccol], Wb + (size_t)crow[s] * K + k0 + ccol);
            }
            CP_COMMIT();
        }

        const float* As = dyn + (kt & 1) * 2 * GEMM_BUF;
        const float* Ws = As + GEMM_BUF;
#pragma unroll
        for (int kk = 0; kk < GBK; kk += 8) {
            wmma::fragment<wmma::matrix_a, 16, 16, 8, wmma::precision::tf32,
                           wmma::row_major> af[4];
            wmma::fragment<wmma::matrix_b, 16, 16, 8, wmma::precision::tf32,
                           wmma::col_major> bf[2];
#pragma unroll
            for (int i = 0; i < 4; i++) {
                wmma::load_matrix_sync(af[i], &As[(wm * 64 + i * 16) * GST + kk], GST);
#pragma unroll
                for (int e = 0; e < af[i].num_elements; e++)
                    af[i].x[e] = wmma::__float_to_tf32(af[i].x[e]);
            }
#pragma unroll
            for (int j = 0; j < 2; j++) {
                wmma::load_matrix_sync(bf[j], &Ws[(wn * 32 + j * 16) * GST + kk], GST);
#pragma unroll
                for (int e = 0; e < bf[j].num_elements; e++)
                    bf[j].x[e] = wmma::__float_to_tf32(bf[j].x[e]);
            }
#pragma unroll
            for (int i = 0; i < 4; i++)
#pragma unroll
                for (int j = 0; j < 2; j++)
                    wmma::mma_sync(acc[i][j], af[i], bf[j], acc[i][j]);
        }
        __syncthreads();
    }

#pragma unroll
    for (int i = 0; i < 4; i++) {
#pragma unroll
        for (int j = 0; j < 2; j++) {
            wmma::store_matrix_sync(stage[warp], acc[i][j], 16, wmma::mem_row_major);
            __syncwarp();
            int r0 = blockIdx.y * 128 + wm * 64 + i * 16;
            int c0 = blockIdx.x * 128 + wn * 32 + j * 16;
#pragma unroll
            for (int e = 0; e < 2; e++) {
                int idx = lane + e * 32;
                int rr  = idx >> 2;
                int cc  = (idx & 3) << 2;
                float4 v  = *(float4*)&stage[warp][rr * 16 + cc];
                float4 b4 = *(const float4*)(bias + c0 + cc);
                v.x += b4.x; v.y += b4.y; v.z += b4.z; v.w += b4.w;
                size_t row = (size_t)(r0 + rr);
                if (res) {
                    float4 r = *(const float4*)(res + row * N + c0 + cc);
                    v.x += r.x; v.y += r.y; v.z += r.z; v.w += r.w;
                }
                if (doRelu) {
                    v.x = fmaxf(v.x, 0.f); v.y = fmaxf(v.y, 0.f);
                    v.z = fmaxf(v.z, 0.f); v.w = fmaxf(v.w, 0.f);
                }
                *(float4*)(C + row * N + c0 + cc) = v;
            }
            __syncwarp();
        }
    }
}

// =====================================================================
// Flash attention (one-pass online softmax, no S materialization).
// Per block: one z=(b,h), 64 Q rows. 256 threads = 8 warps (4x2 on the
// 64x64 S tile). Each thread permanently owns row r=tid>>2, cols
// (tid&3)*16.. of all per-row state.
// smem: Q,K,V,S/stage,O tiles @ 64x68 = 87 KB -> 2 CTAs/SM.
// grid: (N/64, B*H)
// =====================================================================
#define AT_ST 68
#define ATT_TILE (64 * AT_ST)
#define ATT_SMEM_BYTES (5 * ATT_TILE * 4)   /* 87040 B */

__global__ __launch_bounds__(256, 2) void attn_flash(
    const float* __restrict__ Q, const float* __restrict__ Kb,
    const float* __restrict__ V, float* __restrict__ T,
    const float* __restrict__ mask)
{
    extern __shared__ float dyn[];
    float* Qs = dyn;
    float* Ks = dyn + ATT_TILE;
    float* Vs = dyn + 2 * ATT_TILE;
    float* Ss = dyn + 3 * ATT_TILE;
    float* Os = dyn + 4 * ATT_TILE;

    const int z = blockIdx.y;
    const int b = z >> 4, h = z & 15;
    const float* Qz = Q  + (size_t)b * NN * DD + h * HDIM;
    const float* Kz = Kb + (size_t)b * NN * DD + h * HDIM;
    const float* Vz = V  + (size_t)b * NN * DD + h * HDIM;
    float*       Tz = T  + (size_t)b * NN * DD + h * HDIM;
    const int i0 = blockIdx.x * 64;

    const int tid  = threadIdx.x;
    const int warp = tid >> 5;
    const int wm   = warp >> 1;   // 0..3 -> S rows wm*16
    const int wn   = warp & 1;    // 0..1 -> S cols wn*32

    // ---- load Q (scaled by 1/8, tf32); zero O ----
#pragma unroll
    for (int s = 0; s < 4; s++) {
        int idx = tid + s * 256;       // 1024 float4 units of 64x64
        int row = idx >> 4;
        int cq  = (idx & 15) << 2;
        float4 q = *(const float4*)(Qz + (size_t)(i0 + row) * DD + cq);
        Qs[row * AT_ST + cq + 0] = wmma::__float_to_tf32(q.x * 0.125f);
        Qs[row * AT_ST + cq + 1] = wmma::__float_to_tf32(q.y * 0.125f);
        Qs[row * AT_ST + cq + 2] = wmma::__float_to_tf32(q.z * 0.125f);
        Qs[row * AT_ST + cq + 3] = wmma::__float_to_tf32(q.w * 0.125f);
    }
    for (int i = tid; i < ATT_TILE; i += 256) Os[i] = 0.f;
    __syncthreads();

    const int r  = tid >> 2;           // owned row 0..63
    const int gq = tid & 3;            // col segment gq*16
    const float* mrow = mask + (size_t)(i0 + r) * NN;
    float* orow = &Os[r * AT_ST + gq * 16];
    float* prow = &Ss[r * AT_ST + gq * 16];

    float m_run = -1e30f, s_run = 0.f;

    for (int j0 = 0; j0 < NN / 64; j0++) {
        // ---- load K,V tiles ----
#pragma unroll
        for (int s = 0; s < 4; s++) {
            int idx = tid + s * 256;
            int row = idx >> 4;
            int cq  = (idx & 15) << 2;
            const float* kp = Kz + (size_t)(j0 * 64 + row) * DD + cq;
            const float* vp = Vz + (size_t)(j0 * 64 + row) * DD + cq;
            float4 k = *(const float4*)kp;
            float4 v = *(const float4*)vp;
            Ks[row * AT_ST + cq + 0] = wmma::__float_to_tf32(k.x);
            Ks[row * AT_ST + cq + 1] = wmma::__float_to_tf32(k.y);
            Ks[row * AT_ST + cq + 2] = wmma::__float_to_tf32(k.z);
            Ks[row * AT_ST + cq + 3] = wmma::__float_to_tf32(k.w);
            Vs[row * AT_ST + cq + 0] = wmma::__float_to_tf32(v.x);
            Vs[row * AT_ST + cq + 1] = wmma::__float_to_tf32(v.y);
            Vs[row * AT_ST + cq + 2] = wmma::__float_to_tf32(v.z);
            Vs[row * AT_ST + cq + 3] = wmma::__float_to_tf32(v.w);
        }
        __syncthreads();

        // ---- S tile = Qs @ Ks^T (warp 16x32) ----
        {
            wmma::fragment<wmma::accumulator, 16, 16, 8, float> sacc[2];
            wmma::fill_fragment(sacc[0], 0.f);
            wmma::fill_fragment(sacc[1], 0.f);
#pragma unroll
            for (int kk = 0; kk < 8; kk++) {
                wmma::fragment<wmma::matrix_a, 16, 16, 8, wmma::precision::tf32,
                               wmma::row_major> af;
                wmma::load_matrix_sync(af, &Qs[(wm * 16) * AT_ST + kk * 8], AT_ST);
#pragma unroll
                for (int j = 0; j < 2; j++) {
                    wmma::fragment<wmma::matrix_b, 16, 16, 8, wmma::precision::tf32,
                                   wmma::col_major> bf;
                    wmma::load_matrix_sync(bf,
                        &Ks[(wn * 32 + j * 16) * AT_ST + kk * 8], AT_ST);
                    wmma::mma_sync(sacc[j], af, bf, sacc[j]);
                }
            }
#pragma unroll
            for (int j = 0; j < 2; j++)
                wmma::store_matrix_sync(
                    &Ss[(wm * 16) * AT_ST + wn * 32 + j * 16], sacc[j],
                    AT_ST, wmma::mem_row_major);
        }
        __syncthreads();

        // ---- online softmax update for (row r, cols gq*16..) ----
        {
            float v[16];
            float tmax = -1e30f;
#pragma unroll
            for (int t = 0; t < 4; t++) {
                float4 sv = *(float4*)(prow + t * 4);
                float4 mk = *(const float4*)(mrow + j0 * 64 + gq * 16 + t * 4);
                v[t * 4 + 0] = sv.x + mk.x; v[t * 4 + 1] = sv.y + mk.y;
                v[t * 4 + 2] = sv.z + mk.z; v[t * 4 + 3] = sv.w + mk.w;
                tmax = fmaxf(tmax, fmaxf(fmaxf(v[t*4+0], v[t*4+1]),
                                         fmaxf(v[t*4+2], v[t*4+3])));
            }
            tmax = fmaxf(tmax, __shfl_xor_sync(0xffffffffu, tmax, 1, 4));
            tmax = fmaxf(tmax, __shfl_xor_sync(0xffffffffu, tmax, 2, 4));
            float m_new = fmaxf(m_run, tmax);
            float corr  = __expf(m_run - m_new);

            float tsum = 0.f;
#pragma unroll
            for (int t = 0; t < 16; t++) {
                float p = __expf(v[t] - m_new);
                tsum += p;
                v[t] = wmma::__float_to_tf32(p);
            }
#pragma unroll
            for (int t = 0; t < 4; t++) {
                float4 p4; p4.x = v[t*4+0]; p4.y = v[t*4+1];
                p4.z = v[t*4+2]; p4.w = v[t*4+3];
                *(float4*)(prow + t * 4) = p4;
            }
            tsum += __shfl_xor_sync(0xffffffffu, tsum, 1, 4);
            tsum += __shfl_xor_sync(0xffffffffu, tsum, 2, 4);
            s_run = s_run * corr + tsum;
            m_run = m_new;

            // rescale owned O segment
#pragma unroll
            for (int t = 0; t < 4; t++) {
                float4 o = *(float4*)(orow + t * 4);
                o.x *= corr; o.y *= corr; o.z *= corr; o.w *= corr;
                *(float4*)(orow + t * 4) = o;
            }
        }
        __syncthreads();

        // ---- PV: warp (wm,wn) computes O-part rows wm*16, cols wn*32 ----
        {
            wmma::fragment<wmma::accumulator, 16, 16, 8, float> oacc[2];
            wmma::fill_fragment(oacc[0], 0.f);
            wmma::fill_fragment(oacc[1], 0.f);
#pragma unroll
            for (int kk = 0; kk < 8; kk++) {
                wmma::fragment<wmma::matrix_a, 16, 16, 8, wmma::precision::tf32,
                               wmma::row_major> pf;
                wmma::load_matrix_sync(pf, &Ss[(wm * 16) * AT_ST + kk * 8], AT_ST);
#pragma unroll
                for (int j = 0; j < 2; j++) {
                    wmma::fragment<wmma::matrix_b, 16, 16, 8, wmma::precision::tf32,
                                   wmma::row_major> vf;
                    wmma::load_matrix_sync(vf,
                        &Vs[(kk * 8) * AT_ST + wn * 32 + j * 16], AT_ST);
                    wmma::mma_sync(oacc[j], pf, vf, oacc[j]);
                }
            }
            __syncthreads();   // all P reads done before overwrite
#pragma unroll
            for (int j = 0; j < 2; j++)
                wmma::store_matrix_sync(
                    &Ss[(wm * 16) * AT_ST + wn * 32 + j * 16], oacc[j],
                    AT_ST, wmma::mem_row_major);
        }
        __syncthreads();

        // ---- O += PV part (owned segment) ----
#pragma unroll
        for (int t = 0; t < 4; t++) {
            float4 o = *(float4*)(orow + t * 4);
            float4 p = *(float4*)(prow + t * 4);
            o.x += p.x; o.y += p.y; o.z += p.z; o.w += p.w;
            *(float4*)(orow + t * 4) = o;
        }
        // (next iteration's post-load __syncthreads orders Ss reuse)
    }

    // ---- epilogue: scale by 1/sum, write out ----
    float inv = 1.f / s_run;
#pragma unroll
    for (int t = 0; t < 4; t++) {
        float4 o = *(float4*)(orow + t * 4);
        o.x *= inv; o.y *= inv; o.z *= inv; o.w *= inv;
        *(float4*)(Tz + (size_t)(i0 + r) * DD + gq * 16 + t * 4) = o;
    }
}

// =====================================================================
// LayerNorm over last dim (1024). One block per row. In-place safe.
// =====================================================================
__global__ __launch_bounds__(256) void layernorm_row(
    const float* __restrict__ X, const float* __restrict__ g,
    const float* __restrict__ bta, float* __restrict__ Y)
{
    __shared__ float red[256];
    const size_t base = (size_t)blockIdx.x * DD;
    const int tid = threadIdx.x;
    float4 v = *(const float4*)(X + base + tid * 4);

    red[tid] = v.x + v.y + v.z + v.w; __syncthreads();
    for (int s = 128; s > 0; s >>= 1) {
        if (tid < s) red[tid] += red[tid + s];
        __syncthreads();
    }
    float mean = red[0] * (1.f / DD); __syncthreads();

    float dx = v.x - mean, dy = v.y - mean, dz = v.z - mean, dw = v.w - mean;
    red[tid] = dx * dx + dy * dy + dz * dz + dw * dw; __syncthreads();
    for (int s = 128; s > 0; s >>= 1) {
        if (tid < s) red[tid] += red[tid + s];
        __syncthreads();
    }
    float inv = rsqrtf(red[0] * (1.f / DD) + LN_EPS);

    float4 gg = *(const float4*)(g + tid * 4);
    float4 bb = *(const float4*)(bta + tid * 4);
    float4 o;
    o.x = dx * inv * gg.x + bb.x;
    o.y = dy * inv * gg.y + bb.y;
    o.z = dz * inv * gg.z + bb.z;
    o.w = dw * inv * gg.w + bb.w;
    *(float4*)(Y + base + tid * 4) = o;
}

// =====================================================================
// Host orchestration
// =====================================================================
extern "C" void kernel_launch(void* const* d_in, const int* in_sizes, int n_in,
                              void* d_out, int out_size)
{
    const float* feats    = (const float*)d_in[0];
    const float* enc      = (const float*)d_in[1];
    const float* trg_mask = (const float*)d_in[2];
    const float* src_mask = (const float*)d_in[3];
    const float* wq1 = (const float*)d_in[4];  const float* bq1 = (const float*)d_in[5];
    const float* wk1 = (const float*)d_in[6];  const float* bk1 = (const float*)d_in[7];
    const float* wv1 = (const float*)d_in[8];  const float* bv1 = (const float*)d_in[9];
    const float* wo1 = (const float*)d_in[10]; const float* bo1 = (const float*)d_in[11];
    const float* wq2 = (const float*)d_in[12]; const float* bq2 = (const float*)d_in[13];
    const float* wk2 = (const float*)d_in[14]; const float* bk2 = (const float*)d_in[15];
    const float* wv2 = (const float*)d_in[16]; const float* bv2 = (const float*)d_in[17];
    const float* wo2 = (const float*)d_in[18]; const float* bo2 = (const float*)d_in[19];
    const float* wf1 = (const float*)d_in[20]; const float* bf1 = (const float*)d_in[21];
    const float* wf2 = (const float*)d_in[22]; const float* bf2 = (const float*)d_in[23];
    const float* g1  = (const float*)d_in[24]; const float* be1 = (const float*)d_in[25];
    const float* g2  = (const float*)d_in[26]; const float* be2 = (const float*)d_in[27];
    const float* g3  = (const float*)d_in[28]; const float* be3 = (const float*)d_in[29];
    float* out = (float*)d_out;

    static int attr_done = 0;
    if (!attr_done) {
        cudaFuncSetAttribute(gemm_nt_tc,
            cudaFuncAttributeMaxDynamicSharedMemorySize, GEMM_SMEM_BYTES);
        cudaFuncSetAttribute(attn_flash,
            cudaFuncAttributeMaxDynamicSharedMemorySize, ATT_SMEM_BYTES);
        attr_done = 1;
    }

    float *Q, *K, *V, *T, *Y, *Hb;
    cudaGetSymbolAddress((void**)&Q,  g_Q);
    cudaGetSymbolAddress((void**)&K,  g_K);
    cudaGetSymbolAddress((void**)&V,  g_V);
    cudaGetSymbolAddress((void**)&T,  g_T);
    cudaGetSymbolAddress((void**)&Y,  g_Y);
    cudaGetSymbolAddress((void**)&Hb, g_Hb);

    dim3 blk(256);
    dim3 gD(DD / 128, MTOK / 128);   // 4096 x 1024 outputs
    dim3 gF(FF / 128, MTOK / 128);   // 4096 x 4096 outputs
    dim3 gA(NN / 64, BB * HH);       // flash attention

    const float* X = enc;            // decoder state entering layer l
    for (int l = 0; l < LLAYERS; l++) {
        const float* feat = feats + (size_t)l * MTOK * DD;
        const size_t wOff = (size_t)l * DD * DD;
        const size_t vOff = (size_t)l * DD;

        // ---- attn1: cross-attention (q from feat, k/v from enc, src_mask) ----
        gemm_nt_tc<<<gD, blk, GEMM_SMEM_BYTES>>>(feat, wq1 + wOff, bq1 + vOff, nullptr, Q, MTOK, DD, DD, 0);
        gemm_nt_tc<<<gD, blk, GEMM_SMEM_BYTES>>>(enc,  wk1 + wOff, bk1 + vOff, nullptr, K, MTOK, DD, DD, 0);
        gemm_nt_tc<<<gD, blk, GEMM_SMEM_BYTES>>>(enc,  wv1 + wOff, bv1 + vOff, nullptr, V, MTOK, DD, DD, 0);
        attn_flash<<<gA, blk, ATT_SMEM_BYTES>>>(Q, K, V, T, src_mask);
        gemm_nt_tc<<<gD, blk, GEMM_SMEM_BYTES>>>(T, wo1 + wOff, bo1 + vOff, feat, Y, MTOK, DD, DD, 0);
        layernorm_row<<<MTOK, blk>>>(Y, g1 + vOff, be1 + vOff, Y);

        // ---- attn2: attention to previous decoder output (trg_mask) ----
        gemm_nt_tc<<<gD, blk, GEMM_SMEM_BYTES>>>(Y, wq2 + wOff, bq2 + vOff, nullptr, Q, MTOK, DD, DD, 0);
        gemm_nt_tc<<<gD, blk, GEMM_SMEM_BYTES>>>(X, wk2 + wOff, bk2 + vOff, nullptr, K, MTOK, DD, DD, 0);
        gemm_nt_tc<<<gD, blk, GEMM_SMEM_BYTES>>>(X, wv2 + wOff, bv2 + vOff, nullptr, V, MTOK, DD, DD, 0);
        attn_flash<<<gA, blk, ATT_SMEM_BYTES>>>(Q, K, V, T, trg_mask);
        gemm_nt_tc<<<gD, blk, GEMM_SMEM_BYTES>>>(T, wo2 + wOff, bo2 + vOff, Y, Y, MTOK, DD, DD, 0);
        layernorm_row<<<MTOK, blk>>>(Y, g2 + vOff, be2 + vOff, Y);

        // ---- FFN ----
        gemm_nt_tc<<<gF, blk, GEMM_SMEM_BYTES>>>(Y, wf1 + (size_t)l * FF * DD, bf1 + (size_t)l * FF,
                                                 nullptr, Hb, MTOK, FF, DD, 1);
        gemm_nt_tc<<<gD, blk, GEMM_SMEM_BYTES>>>(Hb, wf2 + (size_t)l * DD * FF, bf2 + vOff, Y, Y,
                                                 MTOK, DD, FF, 0);
        float* outl = out + (size_t)l * MTOK * DD;
        layernorm_row<<<MTOK, blk>>>(Y, g3 + vOff, be3 + vOff, outl);

        X = outl;   // next layer reads decoder state from the output slab
    }
    (void)in_sizes; (void)n_in; (void)out_size;
}

// round 6
// speedup vs baseline: 3.2759x; 3.1594x over previous
#include <cuda_runtime.h>
#include <cuda_fp16.h>
#include <mma.h>
#include <cstddef>
#include <cstdint>

using namespace nvcuda;

#define LLAYERS 6
#define BB 4
#define NN 1024
#define DD 1024
#define HH 16
#define HDIM 64
#define FF 4096
#define MTOK (BB * NN)      /* 4096 */
#define LN_EPS 1e-5f

// ---------------- scratch (no allocations allowed) ----------------
__device__ float  g_Y[(size_t)MTOK * DD];
// fp16 weight/activation mirrors
__device__ __half h_wq1[(size_t)LLAYERS * DD * DD];
__device__ __half h_wk1[(size_t)LLAYERS * DD * DD];
__device__ __half h_wv1[(size_t)LLAYERS * DD * DD];
__device__ __half h_wo1[(size_t)LLAYERS * DD * DD];
__device__ __half h_wq2[(size_t)LLAYERS * DD * DD];
__device__ __half h_wk2[(size_t)LLAYERS * DD * DD];
__device__ __half h_wv2[(size_t)LLAYERS * DD * DD];
__device__ __half h_wo2[(size_t)LLAYERS * DD * DD];
__device__ __half h_wf1[(size_t)LLAYERS * FF * DD];
__device__ __half h_wf2[(size_t)LLAYERS * DD * FF];
__device__ __half h_feats[(size_t)LLAYERS * MTOK * DD];
__device__ __half h_enc[(size_t)MTOK * DD];
__device__ __half h_Q[(size_t)MTOK * DD];
__device__ __half h_K[(size_t)MTOK * DD];
__device__ __half h_V[(size_t)MTOK * DD];
__device__ __half h_T[(size_t)MTOK * DD];
__device__ __half h_Yh[(size_t)MTOK * DD];
__device__ __half h_X[(size_t)MTOK * DD];
__device__ __half h_Hb[(size_t)MTOK * FF];

// ---------------- cp.async helpers ----------------
__device__ __forceinline__ void cp16(void* sptr, const void* gptr) {
    uint32_t sa = (uint32_t)__cvta_generic_to_shared(sptr);
    asm volatile("cp.async.cg.shared.global [%0], [%1], 16;\n" :: "r"(sa), "l"(gptr));
}
#define CP_COMMIT() asm volatile("cp.async.commit_group;\n" ::: "memory")
#define CP_WAIT_0() asm volatile("cp.async.wait_group 0;\n" ::: "memory")
#define CP_WAIT_1() asm volatile("cp.async.wait_group 1;\n" ::: "memory")

// =====================================================================
// f32 -> f16 conversion (grid-stride free; n multiple of 2048)
// =====================================================================
__global__ __launch_bounds__(256) void cvt_f2h(
    const float* __restrict__ s, __half* __restrict__ d, long n)
{
    long i = ((long)blockIdx.x * 256 + threadIdx.x) * 8;
    if (i >= n) return;
    float4 a = *(const float4*)(s + i);
    float4 b = *(const float4*)(s + i + 4);
    uint4 u;
    ((__half2*)&u)[0] = __floats2half2_rn(a.x, a.y);
    ((__half2*)&u)[1] = __floats2half2_rn(a.z, a.w);
    ((__half2*)&u)[2] = __floats2half2_rn(b.x, b.y);
    ((__half2*)&u)[3] = __floats2half2_rn(b.z, b.w);
    *(uint4*)(d + i) = u;
}

// =====================================================================
// f16 TC GEMM: C = A[M,K] @ W[N,K]^T + bias (+res f32) (+relu)
// Outputs: C (f32, optional) and/or Ch (f16, optional).
// 128x128 CTA tile, BK=64, 2-stage cp.async, 8 warps, warp tile 64x32,
// m16n16k16 f16 MMA with f32 accumulate.
// =====================================================================
#define GBKH 64
#define GSTH 72                     /* padded row stride (halves) */
#define GBUFH (128 * GSTH)          /* halves per matrix per stage */
#define GEMM_SMEM_BYTES (4 * GBUFH * 2)   /* 73728 B */

__global__ __launch_bounds__(256, 2) void gemm_h(
    const __half* __restrict__ A, const __half* __restrict__ W,
    const float* __restrict__ bias, const float* __restrict__ res,
    float* __restrict__ C, __half* __restrict__ Ch,
    int M, int N, int K, int doRelu)
{
    extern __shared__ char dynb[];
    __half* hsm = (__half*)dynb;
    __shared__ float stage[8][16 * 16];

    const int tid  = threadIdx.x;
    const int warp = tid >> 5;
    const int lane = tid & 31;
    const int wm   = warp >> 2;   // 0..1 -> m offset wm*64
    const int wn   = warp & 3;    // 0..3 -> n offset wn*32

    const __half* Ab = A + (size_t)blockIdx.y * 128 * K;
    const __half* Wb = W + (size_t)blockIdx.x * 128 * K;
    const int KT = K / GBKH;

    wmma::fragment<wmma::accumulator, 16, 16, 16, float> acc[4][2];
#pragma unroll
    for (int i = 0; i < 4; i++)
#pragma unroll
        for (int j = 0; j < 2; j++) wmma::fill_fragment(acc[i][j], 0.f);

    // issue stage 0
    {
        __half* As = hsm;
        __half* Ws = hsm + GBUFH;
#pragma unroll
        for (int t = 0; t < 4; t++) {
            int c = tid + t * 256;            // 0..1023 chunks (128 rows x 8)
            int row = c >> 3, col8 = c & 7;
            cp16(As + row * GSTH + col8 * 8, Ab + (size_t)row * K + col8 * 8);
            cp16(Ws + row * GSTH + col8 * 8, Wb + (size_t)row * K + col8 * 8);
        }
        CP_COMMIT();
    }

    for (int kt = 0; kt < KT; kt++) {
        if (kt + 1 < KT) {
            __half* As = hsm + ((kt + 1) & 1) * 2 * GBUFH;
            __half* Ws = As + GBUFH;
            const int k0 = (kt + 1) * GBKH;
#pragma unroll
            for (int t = 0; t < 4; t++) {
                int c = tid + t * 256;
                int row = c >> 3, col8 = c & 7;
                cp16(As + row * GSTH + col8 * 8, Ab + (size_t)row * K + k0 + col8 * 8);
                cp16(Ws + row * GSTH + col8 * 8, Wb + (size_t)row * K + k0 + col8 * 8);
            }
            CP_COMMIT();
            CP_WAIT_1();
        } else {
            CP_WAIT_0();
        }
        __syncthreads();

        const __half* As = hsm + (kt & 1) * 2 * GBUFH;
        const __half* Ws = As + GBUFH;
#pragma unroll
        for (int kk = 0; kk < 4; kk++) {
            wmma::fragment<wmma::matrix_a, 16, 16, 16, __half, wmma::row_major> af[4];
            wmma::fragment<wmma::matrix_b, 16, 16, 16, __half, wmma::col_major> bf[2];
#pragma unroll
            for (int i = 0; i < 4; i++)
                wmma::load_matrix_sync(af[i], &As[(wm * 64 + i * 16) * GSTH + kk * 16], GSTH);
#pragma unroll
            for (int j = 0; j < 2; j++)
                wmma::load_matrix_sync(bf[j], &Ws[(wn * 32 + j * 16) * GSTH + kk * 16], GSTH);
#pragma unroll
            for (int i = 0; i < 4; i++)
#pragma unroll
                for (int j = 0; j < 2; j++)
                    wmma::mma_sync(acc[i][j], af[i], bf[j], acc[i][j]);
        }
        __syncthreads();
    }

    // epilogue: per-warp 16x16 staging, fused bias/res/relu; f32 and/or f16 out
#pragma unroll
    for (int i = 0; i < 4; i++) {
#pragma unroll
        for (int j = 0; j < 2; j++) {
            wmma::store_matrix_sync(stage[warp], acc[i][j], 16, wmma::mem_row_major);
            __syncwarp();
            int r0 = blockIdx.y * 128 + wm * 64 + i * 16;
            int c0 = blockIdx.x * 128 + wn * 32 + j * 16;
#pragma unroll
            for (int e = 0; e < 2; e++) {
                int idx = lane + e * 32;       // 0..63 float4 units
                int rr  = idx >> 2;
                int cc  = (idx & 3) << 2;
                float4 v  = *(float4*)&stage[warp][rr * 16 + cc];
                float4 b4 = *(const float4*)(bias + c0 + cc);
                v.x += b4.x; v.y += b4.y; v.z += b4.z; v.w += b4.w;
                size_t row = (size_t)(r0 + rr);
                if (res) {
                    float4 r = *(const float4*)(res + row * N + c0 + cc);
                    v.x += r.x; v.y += r.y; v.z += r.z; v.w += r.w;
                }
                if (doRelu) {
                    v.x = fmaxf(v.x, 0.f); v.y = fmaxf(v.y, 0.f);
                    v.z = fmaxf(v.z, 0.f); v.w = fmaxf(v.w, 0.f);
                }
                if (C) *(float4*)(C + row * N + c0 + cc) = v;
                if (Ch) {
                    __half2 p0 = __floats2half2_rn(v.x, v.y);
                    __half2 p1 = __floats2half2_rn(v.z, v.w);
                    uint2 u;
                    ((__half2*)&u)[0] = p0; ((__half2*)&u)[1] = p1;
                    *(uint2*)(Ch + row * N + c0 + cc) = u;
                }
            }
            __syncwarp();
        }
    }
}

// =====================================================================
// Flash attention, f16 operands, f32 accumulation.
// Block: one z=(b,h), 64 Q rows. 256 threads = 8 warps: wm=warp>>1 row
// group, wn=warp&1 col group (S tile 64x64, warp tile 16x32).
// K/V tiles double-buffered via cp.async; P aliased into S buffer; O in
// f32 smem, each thread owns row (tid>>2), cols (tid&3)*16.
// =====================================================================
#define ATQ 0
#define ATK(s) (9216 + (s) * 9216)
#define ATV(s) (27648 + (s) * 9216)
#define ATS 46080
#define ATO 63488
#define ATT_SMEM_BYTES 80896
#define AST 72    /* f16 tile stride (halves) */
#define FST 68    /* f32 tile stride (floats) */

__global__ __launch_bounds__(256, 2) void attn_h(
    const __half* __restrict__ Q, const __half* __restrict__ Kb,
    const __half* __restrict__ V, __half* __restrict__ T,
    const float* __restrict__ mask)
{
    extern __shared__ char dynb[];
    __half* Qs = (__half*)(dynb + ATQ);
    float*  Sf = (float*)(dynb + ATS);
    __half* Ph = (__half*)(dynb + ATS);   // alias: P (f16) overwrites S (f32)
    float*  Os = (float*)(dynb + ATO);

    const int z = blockIdx.y;
    const int b = z >> 4, hh = z & 15;
    const __half* Qz = Q  + (size_t)b * NN * DD + hh * HDIM;
    const __half* Kz = Kb + (size_t)b * NN * DD + hh * HDIM;
    const __half* Vz = V  + (size_t)b * NN * DD + hh * HDIM;
    __half*       Tz = T  + (size_t)b * NN * DD + hh * HDIM;
    const int i0 = blockIdx.x * 64;

    const int tid  = threadIdx.x;
    const int warp = tid >> 5;
    const int wm   = warp >> 1;   // 0..3
    const int wn   = warp & 1;    // 0..1

    const int r  = tid >> 2;      // owned row 0..63
    const int gq = tid & 3;       // col segment gq*16
    const float* mrow = mask + (size_t)(i0 + r) * NN;
    float* orow = &Os[r * FST + gq * 16];

    // group 0: Q tile (64x64 halves, 512 x 16B chunks -> 2/thread)
#pragma unroll
    for (int t = 0; t < 2; t++) {
        int c = tid + t * 256;
        int row = c >> 3, col8 = c & 7;
        cp16(Qs + row * AST + col8 * 8, Qz + (size_t)(i0 + row) * DD + col8 * 8);
    }
    CP_COMMIT();
    // group 1: K/V tile 0
    {
        __half* Ks = (__half*)(dynb + ATK(0));
        __half* Vs = (__half*)(dynb + ATV(0));
#pragma unroll
        for (int t = 0; t < 2; t++) {
            int c = tid + t * 256;
            int row = c >> 3, col8 = c & 7;
            cp16(Ks + row * AST + col8 * 8, Kz + (size_t)row * DD + col8 * 8);
            cp16(Vs + row * AST + col8 * 8, Vz + (size_t)row * DD + col8 * 8);
        }
        CP_COMMIT();
    }

    // zero owned O segment
#pragma unroll
    for (int t = 0; t < 16; t++) orow[t] = 0.f;

    CP_WAIT_1();        // Q ready
    __syncthreads();

    // preload Q fragments (constant across j-tiles)
    wmma::fragment<wmma::matrix_a, 16, 16, 16, __half, wmma::row_major> qf[4];
#pragma unroll
    for (int kk = 0; kk < 4; kk++)
        wmma::load_matrix_sync(qf[kk], &Qs[(wm * 16) * AST + kk * 16], AST);

    float m_run = -1e30f, s_run = 0.f;
    const int J = NN / 64;

    for (int j0 = 0; j0 < J; j0++) {
        // prefetch next K/V tile into other stage
        if (j0 + 1 < J) {
            __half* Ks = (__half*)(dynb + ATK((j0 + 1) & 1));
            __half* Vs = (__half*)(dynb + ATV((j0 + 1) & 1));
            const size_t rbase = (size_t)(j0 + 1) * 64;
#pragma unroll
            for (int t = 0; t < 2; t++) {
                int c = tid + t * 256;
                int row = c >> 3, col8 = c & 7;
                cp16(Ks + row * AST + col8 * 8, Kz + (rbase + row) * DD + col8 * 8);
                cp16(Vs + row * AST + col8 * 8, Vz + (rbase + row) * DD + col8 * 8);
            }
            CP_COMMIT();
            CP_WAIT_1();
        } else {
            CP_WAIT_0();
        }
        __syncthreads();                          // [1] tile ready; prev Sf reads done

        const __half* Ks = (__half*)(dynb + ATK(j0 & 1));
        const __half* Vs = (__half*)(dynb + ATV(j0 & 1));

        // ---- S = Q @ K^T (f32 accum) ----
        {
            wmma::fragment<wmma::accumulator, 16, 16, 16, float> sacc[2];
            wmma::fill_fragment(sacc[0], 0.f);
            wmma::fill_fragment(sacc[1], 0.f);
#pragma unroll
            for (int kk = 0; kk < 4; kk++) {
#pragma unroll
                for (int j = 0; j < 2; j++) {
                    wmma::fragment<wmma::matrix_b, 16, 16, 16, __half, wmma::col_major> bf;
                    wmma::load_matrix_sync(bf, &Ks[(wn * 32 + j * 16) * AST + kk * 16], AST);
                    wmma::mma_sync(sacc[j], qf[kk], bf, sacc[j]);
                }
            }
#pragma unroll
            for (int j = 0; j < 2; j++)
                wmma::store_matrix_sync(&Sf[(wm * 16) * FST + wn * 32 + j * 16],
                                        sacc[j], FST, wmma::mem_row_major);
        }
        __syncthreads();                          // [2] S visible

        // ---- online softmax (scale 0.125 folded here) ----
        float v[16];
        {
            const float* srow = &Sf[r * FST + gq * 16];
            float tmax = -1e30f;
#pragma unroll
            for (int t = 0; t < 4; t++) {
                float4 sv = *(const float4*)(srow + t * 4);
                float4 mk = *(const float4*)(mrow + j0 * 64 + gq * 16 + t * 4);
                v[t*4+0] = sv.x * 0.125f + mk.x;
                v[t*4+1] = sv.y * 0.125f + mk.y;
                v[t*4+2] = sv.z * 0.125f + mk.z;
                v[t*4+3] = sv.w * 0.125f + mk.w;
                tmax = fmaxf(tmax, fmaxf(fmaxf(v[t*4+0], v[t*4+1]),
                                         fmaxf(v[t*4+2], v[t*4+3])));
            }
            tmax = fmaxf(tmax, __shfl_xor_sync(0xffffffffu, tmax, 1, 4));
            tmax = fmaxf(tmax, __shfl_xor_sync(0xffffffffu, tmax, 2, 4));
            float m_new = fmaxf(m_run, tmax);
            float corr  = __expf(m_run - m_new);

            float tsum = 0.f;
#pragma unroll
            for (int t = 0; t < 16; t++) {
                v[t] = __expf(v[t] - m_new);
                tsum += v[t];
            }
            tsum += __shfl_xor_sync(0xffffffffu, tsum, 1, 4);
            tsum += __shfl_xor_sync(0xffffffffu, tsum, 2, 4);
            s_run = s_run * corr + tsum;
            m_run = m_new;

            // rescale owned O segment (own floats, no hazard)
#pragma unroll
            for (int t = 0; t < 4; t++) {
                float4 o = *(float4*)(orow + t * 4);
                o.x *= corr; o.y *= corr; o.z *= corr; o.w *= corr;
                *(float4*)(orow + t * 4) = o;
            }
        }
        __syncthreads();                          // [3] all S reads done

        // write P (f16) into S-alias
        {
            uint4 u0, u1;
#pragma unroll
            for (int t = 0; t < 4; t++) {
                ((__half2*)&u0)[t] = __floats2half2_rn(v[t*2+0], v[t*2+1]);
                ((__half2*)&u1)[t] = __floats2half2_rn(v[8+t*2+0], v[8+t*2+1]);
            }
            uint4* pd = (uint4*)(Ph + r * AST + gq * 16);
            pd[0] = u0; pd[1] = u1;
        }
        __syncthreads();                          // [4] P visible

        // ---- PV (f32 accum) ----
        {
            wmma::fragment<wmma::accumulator, 16, 16, 16, float> oacc[2];
            wmma::fill_fragment(oacc[0], 0.f);
            wmma::fill_fragment(oacc[1], 0.f);
#pragma unroll
            for (int kk = 0; kk < 4; kk++) {
                wmma::fragment<wmma::matrix_a, 16, 16, 16, __half, wmma::row_major> pf;
                wmma::load_matrix_sync(pf, &Ph[(wm * 16) * AST + kk * 16], AST);
#pragma unroll
                for (int j = 0; j < 2; j++) {
                    wmma::fragment<wmma::matrix_b, 16, 16, 16, __half, wmma::row_major> vf;
                    wmma::load_matrix_sync(vf, &Vs[(kk * 16) * AST + wn * 32 + j * 16], AST);
                    wmma::mma_sync(oacc[j], pf, vf, oacc[j]);
                }
            }
            __syncthreads();                      // [5] all P/V reads done
#pragma unroll
            for (int j = 0; j < 2; j++)
                wmma::store_matrix_sync(&Sf[(wm * 16) * FST + wn * 32 + j * 16],
                                        oacc[j], FST, wmma::mem_row_major);
        }
        __syncthreads();                          // [6] PV result visible

        // O += PV (owned segment)
        {
            const float* prow = &Sf[r * FST + gq * 16];
#pragma unroll
            for (int t = 0; t < 4; t++) {
                float4 o = *(float4*)(orow + t * 4);
                float4 p = *(const float4*)(prow + t * 4);
                o.x += p.x; o.y += p.y; o.z += p.z; o.w += p.w;
                *(float4*)(orow + t * 4) = o;
            }
        }
        // next iteration's sync [1] orders these Sf reads vs next S store
    }

    // ---- epilogue: scale by 1/sum, write f16 ----
    float inv = 1.f / s_run;
    uint4 u0, u1;
    float ov[16];
#pragma unroll
    for (int t = 0; t < 16; t++) ov[t] = orow[t] * inv;
#pragma unroll
    for (int t = 0; t < 4; t++) {
        ((__half2*)&u0)[t] = __floats2half2_rn(ov[t*2+0], ov[t*2+1]);
        ((__half2*)&u1)[t] = __floats2half2_rn(ov[8+t*2+0], ov[8+t*2+1]);
    }
    uint4* td = (uint4*)(Tz + (size_t)(i0 + r) * DD + gq * 16);
    td[0] = u0; td[1] = u1;
}

// =====================================================================
// LayerNorm over last dim (1024); f32 out + optional f16 out.
// =====================================================================
__global__ __launch_bounds__(256) void layernorm_row(
    const float* __restrict__ X, const float* __restrict__ g,
    const float* __restrict__ bta, float* __restrict__ Y,
    __half* __restrict__ Yh)
{
    __shared__ float red[256];
    const size_t base = (size_t)blockIdx.x * DD;
    const int tid = threadIdx.x;
    float4 v = *(const float4*)(X + base + tid * 4);

    red[tid] = v.x + v.y + v.z + v.w; __syncthreads();
    for (int s = 128; s > 0; s >>= 1) {
        if (tid < s) red[tid] += red[tid + s];
        __syncthreads();
    }
    float mean = red[0] * (1.f / DD); __syncthreads();

    float dx = v.x - mean, dy = v.y - mean, dz = v.z - mean, dw = v.w - mean;
    red[tid] = dx * dx + dy * dy + dz * dz + dw * dw; __syncthreads();
    for (int s = 128; s > 0; s >>= 1) {
        if (tid < s) red[tid] += red[tid + s];
        __syncthreads();
    }
    float inv = rsqrtf(red[0] * (1.f / DD) + LN_EPS);

    float4 gg = *(const float4*)(g + tid * 4);
    float4 bb = *(const float4*)(bta + tid * 4);
    float4 o;
    o.x = dx * inv * gg.x + bb.x;
    o.y = dy * inv * gg.y + bb.y;
    o.z = dz * inv * gg.z + bb.z;
    o.w = dw * inv * gg.w + bb.w;
    *(float4*)(Y + base + tid * 4) = o;
    if (Yh) {
        uint2 u;
        ((__half2*)&u)[0] = __floats2half2_rn(o.x, o.y);
        ((__half2*)&u)[1] = __floats2half2_rn(o.z, o.w);
        *(uint2*)(Yh + base + tid * 4) = u;
    }
}

// =====================================================================
// Host orchestration
// =====================================================================
static inline void cvt(const float* src, __half* dst, long n) {
    cvt_f2h<<<(unsigned)(n / 2048), 256>>>(src, dst, n);
}

extern "C" void kernel_launch(void* const* d_in, const int* in_sizes, int n_in,
                              void* d_out, int out_size)
{
    const float* feats    = (const float*)d_in[0];
    const float* enc      = (const float*)d_in[1];
    const float* trg_mask = (const float*)d_in[2];
    const float* src_mask = (const float*)d_in[3];
    const float* wq1 = (const float*)d_in[4];  const float* bq1 = (const float*)d_in[5];
    const float* wk1 = (const float*)d_in[6];  const float* bk1 = (const float*)d_in[7];
    const float* wv1 = (const float*)d_in[8];  const float* bv1 = (const float*)d_in[9];
    const float* wo1 = (const float*)d_in[10]; const float* bo1 = (const float*)d_in[11];
    const float* wq2 = (const float*)d_in[12]; const float* bq2 = (const float*)d_in[13];
    const float* wk2 = (const float*)d_in[14]; const float* bk2 = (const float*)d_in[15];
    const float* wv2 = (const float*)d_in[16]; const float* bv2 = (const float*)d_in[17];
    const float* wo2 = (const float*)d_in[18]; const float* bo2 = (const float*)d_in[19];
    const float* wf1 = (const float*)d_in[20]; const float* bf1 = (const float*)d_in[21];
    const float* wf2 = (const float*)d_in[22]; const float* bf2 = (const float*)d_in[23];
    const float* g1  = (const float*)d_in[24]; const float* be1 = (const float*)d_in[25];
    const float* g2  = (const float*)d_in[26]; const float* be2 = (const float*)d_in[27];
    const float* g3  = (const float*)d_in[28]; const float* be3 = (const float*)d_in[29];
    float* out = (float*)d_out;

    static int attr_done = 0;
    if (!attr_done) {
        cudaFuncSetAttribute(gemm_h,
            cudaFuncAttributeMaxDynamicSharedMemorySize, GEMM_SMEM_BYTES);
        cudaFuncSetAttribute(attn_h,
            cudaFuncAttributeMaxDynamicSharedMemorySize, ATT_SMEM_BYTES);
        attr_done = 1;
    }

    float* Y;
    cudaGetSymbolAddress((void**)&Y, g_Y);
    __half *pwq1, *pwk1, *pwv1, *pwo1, *pwq2, *pwk2, *pwv2, *pwo2;
    __half *pwf1, *pwf2, *pfeats, *penc;
    __half *pQ, *pK, *pV, *pT, *pYh, *pX, *pHb;
    cudaGetSymbolAddress((void**)&pwq1, h_wq1);
    cudaGetSymbolAddress((void**)&pwk1, h_wk1);
    cudaGetSymbolAddress((void**)&pwv1, h_wv1);
    cudaGetSymbolAddress((void**)&pwo1, h_wo1);
    cudaGetSymbolAddress((void**)&pwq2, h_wq2);
    cudaGetSymbolAddress((void**)&pwk2, h_wk2);
    cudaGetSymbolAddress((void**)&pwv2, h_wv2);
    cudaGetSymbolAddress((void**)&pwo2, h_wo2);
    cudaGetSymbolAddress((void**)&pwf1, h_wf1);
    cudaGetSymbolAddress((void**)&pwf2, h_wf2);
    cudaGetSymbolAddress((void**)&pfeats, h_feats);
    cudaGetSymbolAddress((void**)&penc, h_enc);
    cudaGetSymbolAddress((void**)&pQ, h_Q);
    cudaGetSymbolAddress((void**)&pK, h_K);
    cudaGetSymbolAddress((void**)&pV, h_V);
    cudaGetSymbolAddress((void**)&pT, h_T);
    cudaGetSymbolAddress((void**)&pYh, h_Yh);
    cudaGetSymbolAddress((void**)&pX, h_X);
    cudaGetSymbolAddress((void**)&pHb, h_Hb);

    // ---- one-time-per-call f32 -> f16 conversions ----
    const long nDD = (long)LLAYERS * DD * DD;
    const long nFD = (long)LLAYERS * FF * DD;
    cvt(wq1, pwq1, nDD); cvt(wk1, pwk1, nDD); cvt(wv1, pwv1, nDD); cvt(wo1, pwo1, nDD);
    cvt(wq2, pwq2, nDD); cvt(wk2, pwk2, nDD); cvt(wv2, pwv2, nDD); cvt(wo2, pwo2, nDD);
    cvt(wf1, pwf1, nFD); cvt(wf2, pwf2, nFD);
    cvt(feats, pfeats, (long)LLAYERS * MTOK * DD);
    cvt(enc, penc, (long)MTOK * DD);

    dim3 blk(256);
    dim3 gD(DD / 128, MTOK / 128);   // 8 x 32
    dim3 gF(FF / 128, MTOK / 128);   // 32 x 32
    dim3 gA(NN / 64, BB * HH);       // 16 x 64

    const float*  Xres = enc;        // unused as residual; X f16 path below
    const __half* Xh = penc;         // decoder state (f16) entering layer l
    (void)Xres;

    for (int l = 0; l < LLAYERS; l++) {
        const float*  feat   = feats + (size_t)l * MTOK * DD;
        const __half* feat_h = pfeats + (size_t)l * MTOK * DD;
        const size_t wOff = (size_t)l * DD * DD;
        const size_t fOff = (size_t)l * FF * DD;
        const size_t vOff = (size_t)l * DD;

        // ---- attn1: cross-attention (q from feat, k/v from enc, src_mask) ----
        gemm_h<<<gD, blk, GEMM_SMEM_BYTES>>>(feat_h, pwq1 + wOff, bq1 + vOff, nullptr,
                                             nullptr, pQ, MTOK, DD, DD, 0);
        gemm_h<<<gD, blk, GEMM_SMEM_BYTES>>>(penc, pwk1 + wOff, bk1 + vOff, nullptr,
                                             nullptr, pK, MTOK, DD, DD, 0);
        gemm_h<<<gD, blk, GEMM_SMEM_BYTES>>>(penc, pwv1 + wOff, bv1 + vOff, nullptr,
                                             nullptr, pV, MTOK, DD, DD, 0);
        attn_h<<<gA, blk, ATT_SMEM_BYTES>>>(pQ, pK, pV, pT, src_mask);
        gemm_h<<<gD, blk, GEMM_SMEM_BYTES>>>(pT, pwo1 + wOff, bo1 + vOff, feat,
                                             Y, nullptr, MTOK, DD, DD, 0);
        layernorm_row<<<MTOK, blk>>>(Y, g1 + vOff, be1 + vOff, Y, pYh);

        // ---- attn2: attention to previous decoder output (trg_mask) ----
        gemm_h<<<gD, blk, GEMM_SMEM_BYTES>>>(pYh, pwq2 + wOff, bq2 + vOff, nullptr,
                                             nullptr, pQ, MTOK, DD, DD, 0);
        gemm_h<<<gD, blk, GEMM_SMEM_BYTES>>>(Xh, pwk2 + wOff, bk2 + vOff, nullptr,
                                             nullptr, pK, MTOK, DD, DD, 0);
        gemm_h<<<gD, blk, GEMM_SMEM_BYTES>>>(Xh, pwv2 + wOff, bv2 + vOff, nullptr,
                                             nullptr, pV, MTOK, DD, DD, 0);
        attn_h<<<gA, blk, ATT_SMEM_BYTES>>>(pQ, pK, pV, pT, trg_mask);
        gemm_h<<<gD, blk, GEMM_SMEM_BYTES>>>(pT, pwo2 + wOff, bo2 + vOff, Y,
                                             Y, nullptr, MTOK, DD, DD, 0);
        layernorm_row<<<MTOK, blk>>>(Y, g2 + vOff, be2 + vOff, Y, pYh);

        // ---- FFN ----
        gemm_h<<<gF, blk, GEMM_SMEM_BYTES>>>(pYh, pwf1 + fOff, bf1 + (size_t)l * FF,
                                             nullptr, nullptr, pHb, MTOK, FF, DD, 1);
        gemm_h<<<gD, blk, GEMM_SMEM_BYTES>>>(pHb, pwf2 + fOff, bf2 + vOff, Y,
                                             Y, nullptr, MTOK, DD, FF, 0);
        float* outl = out + (size_t)l * MTOK * DD;
        layernorm_row<<<MTOK, blk>>>(Y, g3 + vOff, be3 + vOff, outl, pX);

        Xh = pX;   // next layer reads decoder state (f16)
    }
    (void)in_sizes; (void)n_in; (void)out_size;
}

// round 7
// speedup vs baseline: 3.3161x; 1.0123x over previous
#include <cuda_runtime.h>
#include <cuda_fp16.h>
#include <mma.h>
#include <cstddef>
#include <cstdint>

using namespace nvcuda;

#define LLAYERS 6
#define BB 4
#define NN 1024
#define DD 1024
#define HH 16
#define HDIM 64
#define FF 4096
#define MTOK (BB * NN)      /* 4096 */
#define LN_EPS 1e-5f

// ---------------- scratch (no allocations allowed) ----------------
__device__ float  g_Y[(size_t)MTOK * DD];
// fp16 mirrors
__device__ __half h_wq1[(size_t)LLAYERS * DD * DD];
__device__ __half h_wo1[(size_t)LLAYERS * DD * DD];
__device__ __half h_wq2[(size_t)LLAYERS * DD * DD];
__device__ __half h_wo2[(size_t)LLAYERS * DD * DD];
__device__ __half h_wf1[(size_t)LLAYERS * FF * DD];
__device__ __half h_wf2[(size_t)LLAYERS * DD * FF];
__device__ __half h_feats[(size_t)LLAYERS * MTOK * DD];
__device__ __half h_enc[(size_t)MTOK * DD];
// packed KV weights / biases
__device__ __half h_KV1w[(size_t)LLAYERS * 2 * DD * DD];
__device__ __half h_KV2w[(size_t)LLAYERS * 2 * DD * DD];
__device__ float  g_bKV1[(size_t)LLAYERS * 2 * DD];
__device__ float  g_bKV2[(size_t)LLAYERS * 2 * DD];
// activations
__device__ __half h_KV1[(size_t)MTOK * LLAYERS * 2 * DD];  // [4096, 12288]
__device__ __half h_Q1[(size_t)LLAYERS * MTOK * DD];
__device__ __half h_KV2[(size_t)MTOK * 2 * DD];            // [4096, 2048]
__device__ __half h_Q[(size_t)MTOK * DD];
__device__ __half h_T[(size_t)MTOK * DD];
__device__ __half h_Yh[(size_t)MTOK * DD];
__device__ __half h_X[(size_t)MTOK * DD];
__device__ __half h_Hb[(size_t)MTOK * FF];

// ---------------- cp.async helpers ----------------
__device__ __forceinline__ void cp16(void* sptr, const void* gptr) {
    uint32_t sa = (uint32_t)__cvta_generic_to_shared(sptr);
    asm volatile("cp.async.cg.shared.global [%0], [%1], 16;\n" :: "r"(sa), "l"(gptr));
}
#define CP_COMMIT() asm volatile("cp.async.commit_group;\n" ::: "memory")
#define CP_WAIT_0() asm volatile("cp.async.wait_group 0;\n" ::: "memory")
#define CP_WAIT_1() asm volatile("cp.async.wait_group 1;\n" ::: "memory")

// =====================================================================
// Conversion / packing kernels
// =====================================================================
__global__ __launch_bounds__(256) void cvt_f2h(
    const float* __restrict__ s, __half* __restrict__ d, long n)
{
    long i = ((long)blockIdx.x * 256 + threadIdx.x) * 8;
    if (i >= n) return;
    float4 a = *(const float4*)(s + i);
    float4 b = *(const float4*)(s + i + 4);
    uint4 u;
    ((__half2*)&u)[0] = __floats2half2_rn(a.x, a.y);
    ((__half2*)&u)[1] = __floats2half2_rn(a.z, a.w);
    ((__half2*)&u)[2] = __floats2half2_rn(b.x, b.y);
    ((__half2*)&u)[3] = __floats2half2_rn(b.z, b.w);
    *(uint4*)(d + i) = u;
}

// dst[l][0:perL] = a[l], dst[l][perL:2perL] = b[l]  (f32 -> f16)
__global__ __launch_bounds__(256) void pack_w(
    const float* __restrict__ a, const float* __restrict__ b,
    __half* __restrict__ dst, long perL)
{
    long i = ((long)blockIdx.x * 256 + threadIdx.x) * 8;
    long l = i / (2 * perL);
    long r = i - l * 2 * perL;
    const float* src = (r < perL) ? a + l * perL + r : b + l * perL + (r - perL);
    float4 x = *(const float4*)(src);
    float4 y = *(const float4*)(src + 4);
    uint4 u;
    ((__half2*)&u)[0] = __floats2half2_rn(x.x, x.y);
    ((__half2*)&u)[1] = __floats2half2_rn(x.z, x.w);
    ((__half2*)&u)[2] = __floats2half2_rn(y.x, y.y);
    ((__half2*)&u)[3] = __floats2half2_rn(y.z, y.w);
    *(uint4*)(dst + i) = u;
}

__global__ __launch_bounds__(256) void pack_b(
    const float* __restrict__ a, const float* __restrict__ b,
    float* __restrict__ dst, long perL)
{
    long i = ((long)blockIdx.x * 256 + threadIdx.x) * 4;
    long l = i / (2 * perL);
    long r = i - l * 2 * perL;
    const float* src = (r < perL) ? a + l * perL + r : b + l * perL + (r - perL);
    *(float4*)(dst + i) = *(const float4*)src;
}

// =====================================================================
// f16 TC GEMM: C = A[M,K] @ W[N,K]^T + bias (+res f32) (+relu)
// Optional layer batching via blockIdx.z strides; output row stride ldc.
// 128x128 CTA tile, BK=64, 2-stage cp.async, 8 warps, warp tile 64x32.
// =====================================================================
#define GBKH 64
#define GSTH 72
#define GBUFH (128 * GSTH)
#define GEMM_SMEM_BYTES (4 * GBUFH * 2)   /* 73728 B */

__global__ __launch_bounds__(256, 2) void gemm_h(
    const __half* __restrict__ A, const __half* __restrict__ W,
    const float* __restrict__ bias, const float* __restrict__ res,
    float* __restrict__ C, __half* __restrict__ Ch,
    int M, int N, int K, int doRelu, int ldc,
    long zA, long zW, long zB, long zC)
{
    extern __shared__ char dynb[];
    __half* hsm = (__half*)dynb;
    __shared__ float stage[8][16 * 16];

    const long lz = blockIdx.z;
    A += lz * zA; W += lz * zW; bias += lz * zB;
    if (C)  C  += lz * zC;
    if (Ch) Ch += lz * zC;

    const int tid  = threadIdx.x;
    const int warp = tid >> 5;
    const int lane = tid & 31;
    const int wm   = warp >> 2;
    const int wn   = warp & 3;

    const __half* Ab = A + (size_t)blockIdx.y * 128 * K;
    const __half* Wb = W + (size_t)blockIdx.x * 128 * K;
    const int KT = K / GBKH;

    wmma::fragment<wmma::accumulator, 16, 16, 16, float> acc[4][2];
#pragma unroll
    for (int i = 0; i < 4; i++)
#pragma unroll
        for (int j = 0; j < 2; j++) wmma::fill_fragment(acc[i][j], 0.f);

    {
        __half* As = hsm;
        __half* Ws = hsm + GBUFH;
#pragma unroll
        for (int t = 0; t < 4; t++) {
            int c = tid + t * 256;
            int row = c >> 3, col8 = c & 7;
            cp16(As + row * GSTH + col8 * 8, Ab + (size_t)row * K + col8 * 8);
            cp16(Ws + row * GSTH + col8 * 8, Wb + (size_t)row * K + col8 * 8);
        }
        CP_COMMIT();
    }

    for (int kt = 0; kt < KT; kt++) {
        if (kt + 1 < KT) {
            __half* As = hsm + ((kt + 1) & 1) * 2 * GBUFH;
            __half* Ws = As + GBUFH;
            const int k0 = (kt + 1) * GBKH;
#pragma unroll
            for (int t = 0; t < 4; t++) {
                int c = tid + t * 256;
                int row = c >> 3, col8 = c & 7;
                cp16(As + row * GSTH + col8 * 8, Ab + (size_t)row * K + k0 + col8 * 8);
                cp16(Ws + row * GSTH + col8 * 8, Wb + (size_t)row * K + k0 + col8 * 8);
            }
            CP_COMMIT();
            CP_WAIT_1();
        } else {
            CP_WAIT_0();
        }
        __syncthreads();

        const __half* As = hsm + (kt & 1) * 2 * GBUFH;
        const __half* Ws = As + GBUFH;
#pragma unroll
        for (int kk = 0; kk < 4; kk++) {
            wmma::fragment<wmma::matrix_a, 16, 16, 16, __half, wmma::row_major> af[4];
            wmma::fragment<wmma::matrix_b, 16, 16, 16, __half, wmma::col_major> bf[2];
#pragma unroll
            for (int i = 0; i < 4; i++)
                wmma::load_matrix_sync(af[i], &As[(wm * 64 + i * 16) * GSTH + kk * 16], GSTH);
#pragma unroll
            for (int j = 0; j < 2; j++)
                wmma::load_matrix_sync(bf[j], &Ws[(wn * 32 + j * 16) * GSTH + kk * 16], GSTH);
#pragma unroll
            for (int i = 0; i < 4; i++)
#pragma unroll
                for (int j = 0; j < 2; j++)
                    wmma::mma_sync(acc[i][j], af[i], bf[j], acc[i][j]);
        }
        __syncthreads();
    }

#pragma unroll
    for (int i = 0; i < 4; i++) {
#pragma unroll
        for (int j = 0; j < 2; j++) {
            wmma::store_matrix_sync(stage[warp], acc[i][j], 16, wmma::mem_row_major);
            __syncwarp();
            int r0 = blockIdx.y * 128 + wm * 64 + i * 16;
            int c0 = blockIdx.x * 128 + wn * 32 + j * 16;
#pragma unroll
            for (int e = 0; e < 2; e++) {
                int idx = lane + e * 32;
                int rr  = idx >> 2;
                int cc  = (idx & 3) << 2;
                float4 v  = *(float4*)&stage[warp][rr * 16 + cc];
                float4 b4 = *(const float4*)(bias + c0 + cc);
                v.x += b4.x; v.y += b4.y; v.z += b4.z; v.w += b4.w;
                size_t row = (size_t)(r0 + rr);
                if (res) {
                    float4 r = *(const float4*)(res + row * ldc + c0 + cc);
                    v.x += r.x; v.y += r.y; v.z += r.z; v.w += r.w;
                }
                if (doRelu) {
                    v.x = fmaxf(v.x, 0.f); v.y = fmaxf(v.y, 0.f);
                    v.z = fmaxf(v.z, 0.f); v.w = fmaxf(v.w, 0.f);
                }
                if (C) *(float4*)(C + row * ldc + c0 + cc) = v;
                if (Ch) {
                    uint2 u;
                    ((__half2*)&u)[0] = __floats2half2_rn(v.x, v.y);
                    ((__half2*)&u)[1] = __floats2half2_rn(v.z, v.w);
                    *(uint2*)(Ch + row * ldc + c0 + cc) = u;
                }
            }
            __syncwarp();
        }
    }
}

// =====================================================================
// Flash attention, f16 operands. 4 barriers per j-tile (separate P buf).
// K/V row stride = ldkv (supports packed KV blobs); Q/T stride = DD.
// =====================================================================
#define AST 72    /* f16 tile stride (halves) */
#define FST 68    /* f32 tile stride (floats) */
#define ATQ 0
#define ATK(s) (9216 + (s) * 9216)
#define ATV(s) (27648 + (s) * 9216)
#define ATS 46080
#define ATP 63488
#define ATO 72704
#define ATT_SMEM_BYTES 90112

__global__ __launch_bounds__(256, 2) void attn_h(
    const __half* __restrict__ Q, const __half* __restrict__ Kb,
    const __half* __restrict__ V, __half* __restrict__ T,
    const float* __restrict__ mask, int ldkv)
{
    extern __shared__ char dynb[];
    __half* Qs = (__half*)(dynb + ATQ);
    float*  Sf = (float*)(dynb + ATS);
    __half* Ph = (__half*)(dynb + ATP);
    float*  Os = (float*)(dynb + ATO);

    const int z = blockIdx.y;
    const int b = z >> 4, hh = z & 15;
    const __half* Qz = Q  + (size_t)b * NN * DD   + hh * HDIM;
    const __half* Kz = Kb + (size_t)b * NN * ldkv + hh * HDIM;
    const __half* Vz = V  + (size_t)b * NN * ldkv + hh * HDIM;
    __half*       Tz = T  + (size_t)b * NN * DD   + hh * HDIM;
    const int i0 = blockIdx.x * 64;

    const int tid  = threadIdx.x;
    const int warp = tid >> 5;
    const int wm   = warp >> 1;
    const int wn   = warp & 1;

    const int r  = tid >> 2;
    const int gq = tid & 3;
    const float* mrow = mask + (size_t)(i0 + r) * NN;
    float* orow = &Os[r * FST + gq * 16];

    // Q tile
#pragma unroll
    for (int t = 0; t < 2; t++) {
        int c = tid + t * 256;
        int row = c >> 3, col8 = c & 7;
        cp16(Qs + row * AST + col8 * 8, Qz + (size_t)(i0 + row) * DD + col8 * 8);
    }
    CP_COMMIT();
    // K/V tile 0
    {
        __half* Ks = (__half*)(dynb + ATK(0));
        __half* Vs = (__half*)(dynb + ATV(0));
#pragma unroll
        for (int t = 0; t < 2; t++) {
            int c = tid + t * 256;
            int row = c >> 3, col8 = c & 7;
            cp16(Ks + row * AST + col8 * 8, Kz + (size_t)row * ldkv + col8 * 8);
            cp16(Vs + row * AST + col8 * 8, Vz + (size_t)row * ldkv + col8 * 8);
        }
        CP_COMMIT();
    }

#pragma unroll
    for (int t = 0; t < 16; t++) orow[t] = 0.f;

    CP_WAIT_1();
    __syncthreads();

    wmma::fragment<wmma::matrix_a, 16, 16, 16, __half, wmma::row_major> qf[4];
#pragma unroll
    for (int kk = 0; kk < 4; kk++)
        wmma::load_matrix_sync(qf[kk], &Qs[(wm * 16) * AST + kk * 16], AST);

    float m_run = -1e30f, s_run = 0.f;
    const int J = NN / 64;

    for (int j0 = 0; j0 < J; j0++) {
        if (j0 + 1 < J) {
            __half* Ks = (__half*)(dynb + ATK((j0 + 1) & 1));
            __half* Vs = (__half*)(dynb + ATV((j0 + 1) & 1));
            const size_t rbase = (size_t)(j0 + 1) * 64;
#pragma unroll
            for (int t = 0; t < 2; t++) {
                int c = tid + t * 256;
                int row = c >> 3, col8 = c & 7;
                cp16(Ks + row * AST + col8 * 8, Kz + (rbase + row) * ldkv + col8 * 8);
                cp16(Vs + row * AST + col8 * 8, Vz + (rbase + row) * ldkv + col8 * 8);
            }
            CP_COMMIT();
            CP_WAIT_1();
        } else {
            CP_WAIT_0();
        }
        __syncthreads();                          // [1] tile ready; prev Sf reads done

        const __half* Ks = (__half*)(dynb + ATK(j0 & 1));
        const __half* Vs = (__half*)(dynb + ATV(j0 & 1));

        // ---- S = Q @ K^T ----
        {
            wmma::fragment<wmma::accumulator, 16, 16, 16, float> sacc[2];
            wmma::fill_fragment(sacc[0], 0.f);
            wmma::fill_fragment(sacc[1], 0.f);
#pragma unroll
            for (int kk = 0; kk < 4; kk++) {
#pragma unroll
                for (int j = 0; j < 2; j++) {
                    wmma::fragment<wmma::matrix_b, 16, 16, 16, __half, wmma::col_major> bf;
                    wmma::load_matrix_sync(bf, &Ks[(wn * 32 + j * 16) * AST + kk * 16], AST);
                    wmma::mma_sync(sacc[j], qf[kk], bf, sacc[j]);
                }
            }
#pragma unroll
            for (int j = 0; j < 2; j++)
                wmma::store_matrix_sync(&Sf[(wm * 16) * FST + wn * 32 + j * 16],
                                        sacc[j], FST, wmma::mem_row_major);
        }
        __syncthreads();                          // [2] S visible

        // ---- online softmax; write P into its own buffer ----
        {
            float v[16];
            const float* srow = &Sf[r * FST + gq * 16];
            float tmax = -1e30f;
#pragma unroll
            for (int t = 0; t < 4; t++) {
                float4 sv = *(const float4*)(srow + t * 4);
                float4 mk = *(const float4*)(mrow + j0 * 64 + gq * 16 + t * 4);
                v[t*4+0] = sv.x * 0.125f + mk.x;
                v[t*4+1] = sv.y * 0.125f + mk.y;
                v[t*4+2] = sv.z * 0.125f + mk.z;
                v[t*4+3] = sv.w * 0.125f + mk.w;
                tmax = fmaxf(tmax, fmaxf(fmaxf(v[t*4+0], v[t*4+1]),
                                         fmaxf(v[t*4+2], v[t*4+3])));
            }
            tmax = fmaxf(tmax, __shfl_xor_sync(0xffffffffu, tmax, 1, 4));
            tmax = fmaxf(tmax, __shfl_xor_sync(0xffffffffu, tmax, 2, 4));
            float m_new = fmaxf(m_run, tmax);
            float corr  = __expf(m_run - m_new);

            float tsum = 0.f;
#pragma unroll
            for (int t = 0; t < 16; t++) {
                v[t] = __expf(v[t] - m_new);
                tsum += v[t];
            }
            tsum += __shfl_xor_sync(0xffffffffu, tsum, 1, 4);
            tsum += __shfl_xor_sync(0xffffffffu, tsum, 2, 4);
            s_run = s_run * corr + tsum;
            m_run = m_new;

            uint4 u0, u1;
#pragma unroll
            for (int t = 0; t < 4; t++) {
                ((__half2*)&u0)[t] = __floats2half2_rn(v[t*2+0], v[t*2+1]);
                ((__half2*)&u1)[t] = __floats2half2_rn(v[8+t*2+0], v[8+t*2+1]);
            }
            uint4* pd = (uint4*)(Ph + r * AST + gq * 16);
            pd[0] = u0; pd[1] = u1;

#pragma unroll
            for (int t = 0; t < 4; t++) {
                float4 o = *(float4*)(orow + t * 4);
                o.x *= corr; o.y *= corr; o.z *= corr; o.w *= corr;
                *(float4*)(orow + t * 4) = o;
            }
        }
        __syncthreads();                          // [3] P visible; all S reads done

        // ---- PV -> Sf ----
        {
            wmma::fragment<wmma::accumulator, 16, 16, 16, float> oacc[2];
            wmma::fill_fragment(oacc[0], 0.f);
            wmma::fill_fragment(oacc[1], 0.f);
#pragma unroll
            for (int kk = 0; kk < 4; kk++) {
                wmma::fragment<wmma::matrix_a, 16, 16, 16, __half, wmma::row_major> pf;
                wmma::load_matrix_sync(pf, &Ph[(wm * 16) * AST + kk * 16], AST);
#pragma unroll
                for (int j = 0; j < 2; j++) {
                    wmma::fragment<wmma::matrix_b, 16, 16, 16, __half, wmma::row_major> vf;
                    wmma::load_matrix_sync(vf, &Vs[(kk * 16) * AST + wn * 32 + j * 16], AST);
                    wmma::mma_sync(oacc[j], pf, vf, oacc[j]);
                }
            }
#pragma unroll
            for (int j = 0; j < 2; j++)
                wmma::store_matrix_sync(&Sf[(wm * 16) * FST + wn * 32 + j * 16],
                                        oacc[j], FST, wmma::mem_row_major);
        }
        __syncthreads();                          // [4] PV result visible

        {
            const float* prow = &Sf[r * FST + gq * 16];
#pragma unroll
            for (int t = 0; t < 4; t++) {
                float4 o = *(float4*)(orow + t * 4);
                float4 p = *(const float4*)(prow + t * 4);
                o.x += p.x; o.y += p.y; o.z += p.z; o.w += p.w;
                *(float4*)(orow + t * 4) = o;
            }
        }
        // next iter's [1] orders these Sf reads vs next S stores
    }

    float inv = 1.f / s_run;
    float ov[16];
#pragma unroll
    for (int t = 0; t < 16; t++) ov[t] = orow[t] * inv;
    uint4 u0, u1;
#pragma unroll
    for (int t = 0; t < 4; t++) {
        ((__half2*)&u0)[t] = __floats2half2_rn(ov[t*2+0], ov[t*2+1]);
        ((__half2*)&u1)[t] = __floats2half2_rn(ov[8+t*2+0], ov[8+t*2+1]);
    }
    uint4* td = (uint4*)(Tz + (size_t)(i0 + r) * DD + gq * 16);
    td[0] = u0; td[1] = u1;
}

// =====================================================================
// LayerNorm over last dim (1024); f32 out + optional f16 out.
// =====================================================================
__global__ __launch_bounds__(256) void layernorm_row(
    const float* __restrict__ X, const float* __restrict__ g,
    const float* __restrict__ bta, float* __restrict__ Y,
    __half* __restrict__ Yh)
{
    __shared__ float red[256];
    const size_t base = (size_t)blockIdx.x * DD;
    const int tid = threadIdx.x;
    float4 v = *(const float4*)(X + base + tid * 4);

    red[tid] = v.x + v.y + v.z + v.w; __syncthreads();
    for (int s = 128; s > 0; s >>= 1) {
        if (tid < s) red[tid] += red[tid + s];
        __syncthreads();
    }
    float mean = red[0] * (1.f / DD); __syncthreads();

    float dx = v.x - mean, dy = v.y - mean, dz = v.z - mean, dw = v.w - mean;
    red[tid] = dx * dx + dy * dy + dz * dz + dw * dw; __syncthreads();
    for (int s = 128; s > 0; s >>= 1) {
        if (tid < s) red[tid] += red[tid + s];
        __syncthreads();
    }
    float inv = rsqrtf(red[0] * (1.f / DD) + LN_EPS);

    float4 gg = *(const float4*)(g + tid * 4);
    float4 bb = *(const float4*)(bta + tid * 4);
    float4 o;
    o.x = dx * inv * gg.x + bb.x;
    o.y = dy * inv * gg.y + bb.y;
    o.z = dz * inv * gg.z + bb.z;
    o.w = dw * inv * gg.w + bb.w;
    *(float4*)(Y + base + tid * 4) = o;
    if (Yh) {
        uint2 u;
        ((__half2*)&u)[0] = __floats2half2_rn(o.x, o.y);
        ((__half2*)&u)[1] = __floats2half2_rn(o.z, o.w);
        *(uint2*)(Yh + base + tid * 4) = u;
    }
}

// =====================================================================
// Host orchestration
// =====================================================================
static inline void cvt(const float* src, __half* dst, long n) {
    cvt_f2h<<<(unsigned)(n / 2048), 256>>>(src, dst, n);
}

extern "C" void kernel_launch(void* const* d_in, const int* in_sizes, int n_in,
                              void* d_out, int out_size)
{
    const float* feats    = (const float*)d_in[0];
    const float* enc      = (const float*)d_in[1];
    const float* trg_mask = (const float*)d_in[2];
    const float* src_mask = (const float*)d_in[3];
    const float* wq1 = (const float*)d_in[4];  const float* bq1 = (const float*)d_in[5];
    const float* wk1 = (const float*)d_in[6];  const float* bk1 = (const float*)d_in[7];
    const float* wv1 = (const float*)d_in[8];  const float* bv1 = (const float*)d_in[9];
    const float* wo1 = (const float*)d_in[10]; const float* bo1 = (const float*)d_in[11];
    const float* wq2 = (const float*)d_in[12]; const float* bq2 = (const float*)d_in[13];
    const float* wk2 = (const float*)d_in[14]; const float* bk2 = (const float*)d_in[15];
    const float* wv2 = (const float*)d_in[16]; const float* bv2 = (const float*)d_in[17];
    const float* wo2 = (const float*)d_in[18]; const float* bo2 = (const float*)d_in[19];
    const float* wf1 = (const float*)d_in[20]; const float* bf1 = (const float*)d_in[21];
    const float* wf2 = (const float*)d_in[22]; const float* bf2 = (const float*)d_in[23];
    const float* g1  = (const float*)d_in[24]; const float* be1 = (const float*)d_in[25];
    const float* g2  = (const float*)d_in[26]; const float* be2 = (const float*)d_in[27];
    const float* g3  = (const float*)d_in[28]; const float* be3 = (const float*)d_in[29];
    float* out = (float*)d_out;

    static int attr_done = 0;
    if (!attr_done) {
        cudaFuncSetAttribute(gemm_h,
            cudaFuncAttributeMaxDynamicSharedMemorySize, GEMM_SMEM_BYTES);
        cudaFuncSetAttribute(attn_h,
            cudaFuncAttributeMaxDynamicSharedMemorySize, ATT_SMEM_BYTES);
        attr_done = 1;
    }

    float* Y;
    cudaGetSymbolAddress((void**)&Y, g_Y);
    __half *pwq1, *pwo1, *pwq2, *pwo2, *pwf1, *pwf2, *pfeats, *penc;
    __half *pKV1w, *pKV2w, *pKV1, *pQ1, *pKV2, *pQ, *pT, *pYh, *pX, *pHb;
    float *pbKV1, *pbKV2;
    cudaGetSymbolAddress((void**)&pwq1, h_wq1);
    cudaGetSymbolAddress((void**)&pwo1, h_wo1);
    cudaGetSymbolAddress((void**)&pwq2, h_wq2);
    cudaGetSymbolAddress((void**)&pwo2, h_wo2);
    cudaGetSymbolAddress((void**)&pwf1, h_wf1);
    cudaGetSymbolAddress((void**)&pwf2, h_wf2);
    cudaGetSymbolAddress((void**)&pfeats, h_feats);
    cudaGetSymbolAddress((void**)&penc, h_enc);
    cudaGetSymbolAddress((void**)&pKV1w, h_KV1w);
    cudaGetSymbolAddress((void**)&pKV2w, h_KV2w);
    cudaGetSymbolAddress((void**)&pbKV1, g_bKV1);
    cudaGetSymbolAddress((void**)&pbKV2, g_bKV2);
    cudaGetSymbolAddress((void**)&pKV1, h_KV1);
    cudaGetSymbolAddress((void**)&pQ1, h_Q1);
    cudaGetSymbolAddress((void**)&pKV2, h_KV2);
    cudaGetSymbolAddress((void**)&pQ, h_Q);
    cudaGetSymbolAddress((void**)&pT, h_T);
    cudaGetSymbolAddress((void**)&pYh, h_Yh);
    cudaGetSymbolAddress((void**)&pX, h_X);
    cudaGetSymbolAddress((void**)&pHb, h_Hb);

    // ---- conversions + packing ----
    const long nDD = (long)LLAYERS * DD * DD;
    const long nFD = (long)LLAYERS * FF * DD;
    cvt(wq1, pwq1, nDD); cvt(wo1, pwo1, nDD);
    cvt(wq2, pwq2, nDD); cvt(wo2, pwo2, nDD);
    cvt(wf1, pwf1, nFD); cvt(wf2, pwf2, nFD);
    cvt(feats, pfeats, (long)LLAYERS * MTOK * DD);
    cvt(enc, penc, (long)MTOK * DD);
    pack_w<<<(unsigned)(2 * nDD / 2048), 256>>>(wk1, wv1, pKV1w, (long)DD * DD);
    pack_w<<<(unsigned)(2 * nDD / 2048), 256>>>(wk2, wv2, pKV2w, (long)DD * DD);
    pack_b<<<(unsigned)(2 * LLAYERS * DD / 1024), 256>>>(bk1, bv1, pbKV1, DD);
    pack_b<<<(unsigned)(2 * LLAYERS * DD / 1024), 256>>>(bk2, bv2, pbKV2, DD);

    dim3 blk(256);
    const int NKV1 = LLAYERS * 2 * DD;   // 12288
    dim3 gKV1(NKV1 / 128, MTOK / 128);         // 96 x 32
    dim3 gQ1(DD / 128, MTOK / 128, LLAYERS);   // 8 x 32 x 6
    dim3 gD(DD / 128, MTOK / 128);             // 8 x 32
    dim3 gKV2(2 * DD / 128, MTOK / 128);       // 16 x 32
    dim3 gF(FF / 128, MTOK / 128);             // 32 x 32
    dim3 gA(NN / 64, BB * HH);                 // 16 x 64

    // ---- loop-invariant GEMMs: KV1 (all layers) + Q1 (batched) ----
    gemm_h<<<gKV1, blk, GEMM_SMEM_BYTES>>>(penc, pKV1w, pbKV1, nullptr,
        nullptr, pKV1, MTOK, NKV1, DD, 0, NKV1, 0, 0, 0, 0);
    gemm_h<<<gQ1, blk, GEMM_SMEM_BYTES>>>(pfeats, pwq1, bq1, nullptr,
        nullptr, pQ1, MTOK, DD, DD, 0, DD,
        (long)MTOK * DD, (long)DD * DD, DD, (long)MTOK * DD);

    const __half* Xh = penc;
    for (int l = 0; l < LLAYERS; l++) {
        const float* feat = feats + (size_t)l * MTOK * DD;
        const size_t wOff = (size_t)l * DD * DD;
        const size_t fOff = (size_t)l * FF * DD;
        const size_t vOff = (size_t)l * DD;

        // ---- attn1: cross-attention (Q1[l], KV1[l], src_mask) ----
        attn_h<<<gA, blk, ATT_SMEM_BYTES>>>(
            pQ1 + (size_t)l * MTOK * DD,
            pKV1 + (size_t)l * 2 * DD,            // K cols at l*2048
            pKV1 + (size_t)l * 2 * DD + DD,       // V cols at l*2048+1024
            pT, src_mask, NKV1);
        gemm_h<<<gD, blk, GEMM_SMEM_BYTES>>>(pT, pwo1 + wOff, bo1 + vOff, feat,
            Y, nullptr, MTOK, DD, DD, 0, DD, 0, 0, 0, 0);
        layernorm_row<<<MTOK, blk>>>(Y, g1 + vOff, be1 + vOff, Y, pYh);

        // ---- attn2: decoder attention (trg_mask) ----
        gemm_h<<<gD, blk, GEMM_SMEM_BYTES>>>(pYh, pwq2 + wOff, bq2 + vOff, nullptr,
            nullptr, pQ, MTOK, DD, DD, 0, DD, 0, 0, 0, 0);
        gemm_h<<<gKV2, blk, GEMM_SMEM_BYTES>>>(Xh, pKV2w + 2 * wOff, pbKV2 + 2 * vOff,
            nullptr, nullptr, pKV2, MTOK, 2 * DD, DD, 0, 2 * DD, 0, 0, 0, 0);
        attn_h<<<gA, blk, ATT_SMEM_BYTES>>>(pQ, pKV2, pKV2 + DD, pT, trg_mask, 2 * DD);
        gemm_h<<<gD, blk, GEMM_SMEM_BYTES>>>(pT, pwo2 + wOff, bo2 + vOff, Y,
            Y, nullptr, MTOK, DD, DD, 0, DD, 0, 0, 0, 0);
        layernorm_row<<<MTOK, blk>>>(Y, g2 + vOff, be2 + vOff, Y, pYh);

        // ---- FFN ----
        gemm_h<<<gF, blk, GEMM_SMEM_BYTES>>>(pYh, pwf1 + fOff, bf1 + (size_t)l * FF,
            nullptr, nullptr, pHb, MTOK, FF, DD, 1, FF, 0, 0, 0, 0);
        gemm_h<<<gD, blk, GEMM_SMEM_BYTES>>>(pHb, pwf2 + fOff, bf2 + vOff, Y,
            Y, nullptr, MTOK, DD, FF, 0, DD, 0, 0, 0, 0);
        float* outl = out + (size_t)l * MTOK * DD;
        layernorm_row<<<MTOK, blk>>>(Y, g3 + vOff, be3 + vOff, outl, pX);

        Xh = pX;
    }
    (void)in_sizes; (void)n_in; (void)out_size;
}

// round 8
// speedup vs baseline: 3.5042x; 1.0567x over previous
#include <cuda_runtime.h>
#include <cuda_fp16.h>
#include <mma.h>
#include <cstddef>
#include <cstdint>

using namespace nvcuda;

#define LLAYERS 6
#define BB 4
#define NN 1024
#define DD 1024
#define HH 16
#define HDIM 64
#define FF 4096
#define MTOK (BB * NN)      /* 4096 */
#define LN_EPS 1e-5f

// ---------------- scratch (no allocations allowed) ----------------
__device__ float  g_Y[(size_t)MTOK * DD];
__device__ float  g_Y1[(size_t)LLAYERS * MTOK * DD];    // post-LN1 y1 (f32)
// fp16 mirrors
__device__ __half h_wq1[(size_t)LLAYERS * DD * DD];
__device__ __half h_wo1[(size_t)LLAYERS * DD * DD];
__device__ __half h_wq2[(size_t)LLAYERS * DD * DD];
__device__ __half h_wo2[(size_t)LLAYERS * DD * DD];
__device__ __half h_wf1[(size_t)LLAYERS * FF * DD];
__device__ __half h_wf2[(size_t)LLAYERS * DD * FF];
__device__ __half h_feats[(size_t)LLAYERS * MTOK * DD];
__device__ __half h_enc[(size_t)MTOK * DD];
// packed KV weights / biases
__device__ __half h_KV1w[(size_t)LLAYERS * 2 * DD * DD];
__device__ __half h_KV2w[(size_t)LLAYERS * 2 * DD * DD];
__device__ float  g_bKV1[(size_t)LLAYERS * 2 * DD];
__device__ float  g_bKV2[(size_t)LLAYERS * 2 * DD];
// activations
__device__ __half h_KV1[(size_t)LLAYERS * MTOK * 2 * DD];  // [l][tok][2048]
__device__ __half h_Q1[(size_t)LLAYERS * MTOK * DD];
__device__ __half h_T1[(size_t)LLAYERS * MTOK * DD];       // attn1 out per layer
__device__ __half h_Yh1[(size_t)LLAYERS * MTOK * DD];      // post-LN1 y1 (f16)
__device__ __half h_KV2[(size_t)MTOK * 2 * DD];
__device__ __half h_Q[(size_t)MTOK * DD];
__device__ __half h_T[(size_t)MTOK * DD];
__device__ __half h_Yh[(size_t)MTOK * DD];
__device__ __half h_X[(size_t)MTOK * DD];
__device__ __half h_Hb[(size_t)MTOK * FF];

// ---------------- cp.async helpers ----------------
__device__ __forceinline__ void cp16(void* sptr, const void* gptr) {
    uint32_t sa = (uint32_t)__cvta_generic_to_shared(sptr);
    asm volatile("cp.async.cg.shared.global [%0], [%1], 16;\n" :: "r"(sa), "l"(gptr));
}
#define CP_COMMIT() asm volatile("cp.async.commit_group;\n" ::: "memory")
#define CP_WAIT_0() asm volatile("cp.async.wait_group 0;\n" ::: "memory")
#define CP_WAIT_1() asm volatile("cp.async.wait_group 1;\n" ::: "memory")

// =====================================================================
// Conversion / packing kernels
// =====================================================================
__global__ __launch_bounds__(256) void cvt_f2h(
    const float* __restrict__ s, __half* __restrict__ d, long n)
{
    long i = ((long)blockIdx.x * 256 + threadIdx.x) * 8;
    if (i >= n) return;
    float4 a = *(const float4*)(s + i);
    float4 b = *(const float4*)(s + i + 4);
    uint4 u;
    ((__half2*)&u)[0] = __floats2half2_rn(a.x, a.y);
    ((__half2*)&u)[1] = __floats2half2_rn(a.z, a.w);
    ((__half2*)&u)[2] = __floats2half2_rn(b.x, b.y);
    ((__half2*)&u)[3] = __floats2half2_rn(b.z, b.w);
    *(uint4*)(d + i) = u;
}

__global__ __launch_bounds__(256) void pack_w(
    const float* __restrict__ a, const float* __restrict__ b,
    __half* __restrict__ dst, long perL)
{
    long i = ((long)blockIdx.x * 256 + threadIdx.x) * 8;
    long l = i / (2 * perL);
    long r = i - l * 2 * perL;
    const float* src = (r < perL) ? a + l * perL + r : b + l * perL + (r - perL);
    float4 x = *(const float4*)(src);
    float4 y = *(const float4*)(src + 4);
    uint4 u;
    ((__half2*)&u)[0] = __floats2half2_rn(x.x, x.y);
    ((__half2*)&u)[1] = __floats2half2_rn(x.z, x.w);
    ((__half2*)&u)[2] = __floats2half2_rn(y.x, y.y);
    ((__half2*)&u)[3] = __floats2half2_rn(y.z, y.w);
    *(uint4*)(dst + i) = u;
}

__global__ __launch_bounds__(256) void pack_b(
    const float* __restrict__ a, const float* __restrict__ b,
    float* __restrict__ dst, long perL)
{
    long i = ((long)blockIdx.x * 256 + threadIdx.x) * 4;
    long l = i / (2 * perL);
    long r = i - l * 2 * perL;
    const float* src = (r < perL) ? a + l * perL + r : b + l * perL + (r - perL);
    *(float4*)(dst + i) = *(const float4*)src;
}

// =====================================================================
// f16 TC GEMM: C = A[M,K] @ W[N,K]^T + bias (+res f32, stride ldc) (+relu)
// 128x128 CTA tile, BK=64, 2-stage cp.async, 8 warps, warp tile 64x32.
// =====================================================================
#define GBKH 64
#define GSTH 72
#define GBUFH (128 * GSTH)
#define GEMM_SMEM_BYTES (4 * GBUFH * 2)   /* 73728 B */

__global__ __launch_bounds__(256, 2) void gemm_h(
    const __half* __restrict__ A, const __half* __restrict__ W,
    const float* __restrict__ bias, const float* __restrict__ res,
    float* __restrict__ C, __half* __restrict__ Ch,
    int M, int N, int K, int doRelu, int ldc)
{
    extern __shared__ char dynb[];
    __half* hsm = (__half*)dynb;
    __shared__ float stage[8][16 * 16];

    const int tid  = threadIdx.x;
    const int warp = tid >> 5;
    const int lane = tid & 31;
    const int wm   = warp >> 2;
    const int wn   = warp & 3;

    const __half* Ab = A + (size_t)blockIdx.y * 128 * K;
    const __half* Wb = W + (size_t)blockIdx.x * 128 * K;
    const int KT = K / GBKH;

    wmma::fragment<wmma::accumulator, 16, 16, 16, float> acc[4][2];
#pragma unroll
    for (int i = 0; i < 4; i++)
#pragma unroll
        for (int j = 0; j < 2; j++) wmma::fill_fragment(acc[i][j], 0.f);

    {
        __half* As = hsm;
        __half* Ws = hsm + GBUFH;
#pragma unroll
        for (int t = 0; t < 4; t++) {
            int c = tid + t * 256;
            int row = c >> 3, col8 = c & 7;
            cp16(As + row * GSTH + col8 * 8, Ab + (size_t)row * K + col8 * 8);
            cp16(Ws + row * GSTH + col8 * 8, Wb + (size_t)row * K + col8 * 8);
        }
        CP_COMMIT();
    }

    for (int kt = 0; kt < KT; kt++) {
        if (kt + 1 < KT) {
            __half* As = hsm + ((kt + 1) & 1) * 2 * GBUFH;
            __half* Ws = As + GBUFH;
            const int k0 = (kt + 1) * GBKH;
#pragma unroll
            for (int t = 0; t < 4; t++) {
                int c = tid + t * 256;
                int row = c >> 3, col8 = c & 7;
                cp16(As + row * GSTH + col8 * 8, Ab + (size_t)row * K + k0 + col8 * 8);
                cp16(Ws + row * GSTH + col8 * 8, Wb + (size_t)row * K + k0 + col8 * 8);
            }
            CP_COMMIT();
            CP_WAIT_1();
        } else {
            CP_WAIT_0();
        }
        __syncthreads();

        const __half* As = hsm + (kt & 1) * 2 * GBUFH;
        const __half* Ws = As + GBUFH;
#pragma unroll
        for (int kk = 0; kk < 4; kk++) {
            wmma::fragment<wmma::matrix_a, 16, 16, 16, __half, wmma::row_major> af[4];
            wmma::fragment<wmma::matrix_b, 16, 16, 16, __half, wmma::col_major> bf[2];
#pragma unroll
            for (int i = 0; i < 4; i++)
                wmma::load_matrix_sync(af[i], &As[(wm * 64 + i * 16) * GSTH + kk * 16], GSTH);
#pragma unroll
            for (int j = 0; j < 2; j++)
                wmma::load_matrix_sync(bf[j], &Ws[(wn * 32 + j * 16) * GSTH + kk * 16], GSTH);
#pragma unroll
            for (int i = 0; i < 4; i++)
#pragma unroll
                for (int j = 0; j < 2; j++)
                    wmma::mma_sync(acc[i][j], af[i], bf[j], acc[i][j]);
        }
        __syncthreads();
    }

#pragma unroll
    for (int i = 0; i < 4; i++) {
#pragma unroll
        for (int j = 0; j < 2; j++) {
            wmma::store_matrix_sync(stage[warp], acc[i][j], 16, wmma::mem_row_major);
            __syncwarp();
            int r0 = blockIdx.y * 128 + wm * 64 + i * 16;
            int c0 = blockIdx.x * 128 + wn * 32 + j * 16;
#pragma unroll
            for (int e = 0; e < 2; e++) {
                int idx = lane + e * 32;
                int rr  = idx >> 2;
                int cc  = (idx & 3) << 2;
                float4 v  = *(float4*)&stage[warp][rr * 16 + cc];
                float4 b4 = *(const float4*)(bias + c0 + cc);
                v.x += b4.x; v.y += b4.y; v.z += b4.z; v.w += b4.w;
                size_t row = (size_t)(r0 + rr);
                if (res) {
                    float4 r = *(const float4*)(res + row * ldc + c0 + cc);
                    v.x += r.x; v.y += r.y; v.z += r.z; v.w += r.w;
                }
                if (doRelu) {
                    v.x = fmaxf(v.x, 0.f); v.y = fmaxf(v.y, 0.f);
                    v.z = fmaxf(v.z, 0.f); v.w = fmaxf(v.w, 0.f);
                }
                if (C) *(float4*)(C + row * ldc + c0 + cc) = v;
                if (Ch) {
                    uint2 u;
                    ((__half2*)&u)[0] = __floats2half2_rn(v.x, v.y);
                    ((__half2*)&u)[1] = __floats2half2_rn(v.z, v.w);
                    *(uint2*)(Ch + row * ldc + c0 + cc) = u;
                }
            }
            __syncwarp();
        }
    }
}

// =====================================================================
// Flash attention, f16 operands. 4 barriers per j-tile.
// K/V row stride = ldkv (packed KV blobs); Q/T stride = DD.
// =====================================================================
#define AST 72
#define FST 68
#define ATQ 0
#define ATK(s) (9216 + (s) * 9216)
#define ATV(s) (27648 + (s) * 9216)
#define ATS 46080
#define ATP 63488
#define ATO 72704
#define ATT_SMEM_BYTES 90112

__global__ __launch_bounds__(256, 2) void attn_h(
    const __half* __restrict__ Q, const __half* __restrict__ Kb,
    const __half* __restrict__ V, __half* __restrict__ T,
    const float* __restrict__ mask, int ldkv)
{
    extern __shared__ char dynb[];
    __half* Qs = (__half*)(dynb + ATQ);
    float*  Sf = (float*)(dynb + ATS);
    __half* Ph = (__half*)(dynb + ATP);
    float*  Os = (float*)(dynb + ATO);

    const int z = blockIdx.y;
    const int b = z >> 4, hh = z & 15;
    const __half* Qz = Q  + (size_t)b * NN * DD   + hh * HDIM;
    const __half* Kz = Kb + (size_t)b * NN * ldkv + hh * HDIM;
    const __half* Vz = V  + (size_t)b * NN * ldkv + hh * HDIM;
    __half*       Tz = T  + (size_t)b * NN * DD   + hh * HDIM;
    const int i0 = blockIdx.x * 64;

    const int tid  = threadIdx.x;
    const int warp = tid >> 5;
    const int wm   = warp >> 1;
    const int wn   = warp & 1;

    const int r  = tid >> 2;
    const int gq = tid & 3;
    const float* mrow = mask + (size_t)(i0 + r) * NN;
    float* orow = &Os[r * FST + gq * 16];

#pragma unroll
    for (int t = 0; t < 2; t++) {
        int c = tid + t * 256;
        int row = c >> 3, col8 = c & 7;
        cp16(Qs + row * AST + col8 * 8, Qz + (size_t)(i0 + row) * DD + col8 * 8);
    }
    CP_COMMIT();
    {
        __half* Ks = (__half*)(dynb + ATK(0));
        __half* Vs = (__half*)(dynb + ATV(0));
#pragma unroll
        for (int t = 0; t < 2; t++) {
            int c = tid + t * 256;
            int row = c >> 3, col8 = c & 7;
            cp16(Ks + row * AST + col8 * 8, Kz + (size_t)row * ldkv + col8 * 8);
            cp16(Vs + row * AST + col8 * 8, Vz + (size_t)row * ldkv + col8 * 8);
        }
        CP_COMMIT();
    }

#pragma unroll
    for (int t = 0; t < 16; t++) orow[t] = 0.f;

    CP_WAIT_1();
    __syncthreads();

    wmma::fragment<wmma::matrix_a, 16, 16, 16, __half, wmma::row_major> qf[4];
#pragma unroll
    for (int kk = 0; kk < 4; kk++)
        wmma::load_matrix_sync(qf[kk], &Qs[(wm * 16) * AST + kk * 16], AST);

    float m_run = -1e30f, s_run = 0.f;
    const int J = NN / 64;

    for (int j0 = 0; j0 < J; j0++) {
        if (j0 + 1 < J) {
            __half* Ks = (__half*)(dynb + ATK((j0 + 1) & 1));
            __half* Vs = (__half*)(dynb + ATV((j0 + 1) & 1));
            const size_t rbase = (size_t)(j0 + 1) * 64;
#pragma unroll
            for (int t = 0; t < 2; t++) {
                int c = tid + t * 256;
                int row = c >> 3, col8 = c & 7;
                cp16(Ks + row * AST + col8 * 8, Kz + (rbase + row) * ldkv + col8 * 8);
                cp16(Vs + row * AST + col8 * 8, Vz + (rbase + row) * ldkv + col8 * 8);
            }
            CP_COMMIT();
            CP_WAIT_1();
        } else {
            CP_WAIT_0();
        }
        __syncthreads();                          // [1]

        const __half* Ks = (__half*)(dynb + ATK(j0 & 1));
        const __half* Vs = (__half*)(dynb + ATV(j0 & 1));

        {
            wmma::fragment<wmma::accumulator, 16, 16, 16, float> sacc[2];
            wmma::fill_fragment(sacc[0], 0.f);
            wmma::fill_fragment(sacc[1], 0.f);
#pragma unroll
            for (int kk = 0; kk < 4; kk++) {
#pragma unroll
                for (int j = 0; j < 2; j++) {
                    wmma::fragment<wmma::matrix_b, 16, 16, 16, __half, wmma::col_major> bf;
                    wmma::load_matrix_sync(bf, &Ks[(wn * 32 + j * 16) * AST + kk * 16], AST);
                    wmma::mma_sync(sacc[j], qf[kk], bf, sacc[j]);
                }
            }
#pragma unroll
            for (int j = 0; j < 2; j++)
                wmma::store_matrix_sync(&Sf[(wm * 16) * FST + wn * 32 + j * 16],
                                        sacc[j], FST, wmma::mem_row_major);
        }
        __syncthreads();                          // [2]

        {
            float v[16];
            const float* srow = &Sf[r * FST + gq * 16];
            float tmax = -1e30f;
#pragma unroll
            for (int t = 0; t < 4; t++) {
                float4 sv = *(const float4*)(srow + t * 4);
                float4 mk = *(const float4*)(mrow + j0 * 64 + gq * 16 + t * 4);
                v[t*4+0] = sv.x * 0.125f + mk.x;
                v[t*4+1] = sv.y * 0.125f + mk.y;
                v[t*4+2] = sv.z * 0.125f + mk.z;
                v[t*4+3] = sv.w * 0.125f + mk.w;
                tmax = fmaxf(tmax, fmaxf(fmaxf(v[t*4+0], v[t*4+1]),
                                         fmaxf(v[t*4+2], v[t*4+3])));
            }
            tmax = fmaxf(tmax, __shfl_xor_sync(0xffffffffu, tmax, 1, 4));
            tmax = fmaxf(tmax, __shfl_xor_sync(0xffffffffu, tmax, 2, 4));
            float m_new = fmaxf(m_run, tmax);
            float corr  = __expf(m_run - m_new);

            float tsum = 0.f;
#pragma unroll
            for (int t = 0; t < 16; t++) {
                v[t] = __expf(v[t] - m_new);
                tsum += v[t];
            }
            tsum += __shfl_xor_sync(0xffffffffu, tsum, 1, 4);
            tsum += __shfl_xor_sync(0xffffffffu, tsum, 2, 4);
            s_run = s_run * corr + tsum;
            m_run = m_new;

            uint4 u0, u1;
#pragma unroll
            for (int t = 0; t < 4; t++) {
                ((__half2*)&u0)[t] = __floats2half2_rn(v[t*2+0], v[t*2+1]);
                ((__half2*)&u1)[t] = __floats2half2_rn(v[8+t*2+0], v[8+t*2+1]);
            }
            uint4* pd = (uint4*)(Ph + r * AST + gq * 16);
            pd[0] = u0; pd[1] = u1;

#pragma unroll
            for (int t = 0; t < 4; t++) {
                float4 o = *(float4*)(orow + t * 4);
                o.x *= corr; o.y *= corr; o.z *= corr; o.w *= corr;
                *(float4*)(orow + t * 4) = o;
            }
        }
        __syncthreads();                          // [3]

        {
            wmma::fragment<wmma::accumulator, 16, 16, 16, float> oacc[2];
            wmma::fill_fragment(oacc[0], 0.f);
            wmma::fill_fragment(oacc[1], 0.f);
#pragma unroll
            for (int kk = 0; kk < 4; kk++) {
                wmma::fragment<wmma::matrix_a, 16, 16, 16, __half, wmma::row_major> pf;
                wmma::load_matrix_sync(pf, &Ph[(wm * 16) * AST + kk * 16], AST);
#pragma unroll
                for (int j = 0; j < 2; j++) {
                    wmma::fragment<wmma::matrix_b, 16, 16, 16, __half, wmma::row_major> vf;
                    wmma::load_matrix_sync(vf, &Vs[(kk * 16) * AST + wn * 32 + j * 16], AST);
                    wmma::mma_sync(oacc[j], pf, vf, oacc[j]);
                }
            }
#pragma unroll
            for (int j = 0; j < 2; j++)
                wmma::store_matrix_sync(&Sf[(wm * 16) * FST + wn * 32 + j * 16],
                                        oacc[j], FST, wmma::mem_row_major);
        }
        __syncthreads();                          // [4]

        {
            const float* prow = &Sf[r * FST + gq * 16];
#pragma unroll
            for (int t = 0; t < 4; t++) {
                float4 o = *(float4*)(orow + t * 4);
                float4 p = *(const float4*)(prow + t * 4);
                o.x += p.x; o.y += p.y; o.z += p.z; o.w += p.w;
                *(float4*)(orow + t * 4) = o;
            }
        }
    }

    float inv = 1.f / s_run;
    float ov[16];
#pragma unroll
    for (int t = 0; t < 16; t++) ov[t] = orow[t] * inv;
    uint4 u0, u1;
#pragma unroll
    for (int t = 0; t < 4; t++) {
        ((__half2*)&u0)[t] = __floats2half2_rn(ov[t*2+0], ov[t*2+1]);
        ((__half2*)&u1)[t] = __floats2half2_rn(ov[8+t*2+0], ov[8+t*2+1]);
    }
    uint4* td = (uint4*)(Tz + (size_t)(i0 + r) * DD + gq * 16);
    td[0] = u0; td[1] = u1;
}

// =====================================================================
// LayerNorm over last dim (1024); f32 out + optional f16 out.
// =====================================================================
__global__ __launch_bounds__(256) void layernorm_row(
    const float* __restrict__ X, const float* __restrict__ g,
    const float* __restrict__ bta, float* __restrict__ Y,
    __half* __restrict__ Yh)
{
    __shared__ float red[256];
    const size_t base = (size_t)blockIdx.x * DD;
    const int tid = threadIdx.x;
    float4 v = *(const float4*)(X + base + tid * 4);

    red[tid] = v.x + v.y + v.z + v.w; __syncthreads();
    for (int s = 128; s > 0; s >>= 1) {
        if (tid < s) red[tid] += red[tid + s];
        __syncthreads();
    }
    float mean = red[0] * (1.f / DD); __syncthreads();

    float dx = v.x - mean, dy = v.y - mean, dz = v.z - mean, dw = v.w - mean;
    red[tid] = dx * dx + dy * dy + dz * dz + dw * dw; __syncthreads();
    for (int s = 128; s > 0; s >>= 1) {
        if (tid < s) red[tid] += red[tid + s];
        __syncthreads();
    }
    float inv = rsqrtf(red[0] * (1.f / DD) + LN_EPS);

    float4 gg = *(const float4*)(g + tid * 4);
    float4 bb = *(const float4*)(bta + tid * 4);
    float4 o;
    o.x = dx * inv * gg.x + bb.x;
    o.y = dy * inv * gg.y + bb.y;
    o.z = dz * inv * gg.z + bb.z;
    o.w = dw * inv * gg.w + bb.w;
    *(float4*)(Y + base + tid * 4) = o;
    if (Yh) {
        uint2 u;
        ((__half2*)&u)[0] = __floats2half2_rn(o.x, o.y);
        ((__half2*)&u)[1] = __floats2half2_rn(o.z, o.w);
        *(uint2*)(Yh + base + tid * 4) = u;
    }
}

// =====================================================================
// Host orchestration: dual-stream fork-join.
// Stream s2 computes the input-only attn1 branch (Q1,KV1,attn1,wo1,LN1)
// per layer; stream 0 runs the serial decoder chain, waiting on evL[l].
// =====================================================================
static inline void cvt(const float* src, __half* dst, long n) {
    cvt_f2h<<<(unsigned)(n / 2048), 256>>>(src, dst, n);
}

extern "C" void kernel_launch(void* const* d_in, const int* in_sizes, int n_in,
                              void* d_out, int out_size)
{
    const float* feats    = (const float*)d_in[0];
    const float* enc      = (const float*)d_in[1];
    const float* trg_mask = (const float*)d_in[2];
    const float* src_mask = (const float*)d_in[3];
    const float* wq1 = (const float*)d_in[4];  const float* bq1 = (const float*)d_in[5];
    const float* wk1 = (const float*)d_in[6];  const float* bk1 = (const float*)d_in[7];
    const float* wv1 = (const float*)d_in[8];  const float* bv1 = (const float*)d_in[9];
    const float* wo1 = (const float*)d_in[10]; const float* bo1 = (const float*)d_in[11];
    const float* wq2 = (const float*)d_in[12]; const float* bq2 = (const float*)d_in[13];
    const float* wk2 = (const float*)d_in[14]; const float* bk2 = (const float*)d_in[15];
    const float* wv2 = (const float*)d_in[16]; const float* bv2 = (const float*)d_in[17];
    const float* wo2 = (const float*)d_in[18]; const float* bo2 = (const float*)d_in[19];
    const float* wf1 = (const float*)d_in[20]; const float* bf1 = (const float*)d_in[21];
    const float* wf2 = (const float*)d_in[22]; const float* bf2 = (const float*)d_in[23];
    const float* g1  = (const float*)d_in[24]; const float* be1 = (const float*)d_in[25];
    const float* g2  = (const float*)d_in[26]; const float* be2 = (const float*)d_in[27];
    const float* g3  = (const float*)d_in[28]; const float* be3 = (const float*)d_in[29];
    float* out = (float*)d_out;

    static int init_done = 0;
    static cudaStream_t s2;
    static cudaEvent_t evF;
    static cudaEvent_t evL[LLAYERS];
    if (!init_done) {
        cudaFuncSetAttribute(gemm_h,
            cudaFuncAttributeMaxDynamicSharedMemorySize, GEMM_SMEM_BYTES);
        cudaFuncSetAttribute(attn_h,
            cudaFuncAttributeMaxDynamicSharedMemorySize, ATT_SMEM_BYTES);
        cudaStreamCreateWithFlags(&s2, cudaStreamNonBlocking);
        cudaEventCreateWithFlags(&evF, cudaEventDisableTiming);
        for (int l = 0; l < LLAYERS; l++)
            cudaEventCreateWithFlags(&evL[l], cudaEventDisableTiming);
        init_done = 1;
    }

    float *Y, *Y1, *pbKV1, *pbKV2;
    cudaGetSymbolAddress((void**)&Y,  g_Y);
    cudaGetSymbolAddress((void**)&Y1, g_Y1);
    cudaGetSymbolAddress((void**)&pbKV1, g_bKV1);
    cudaGetSymbolAddress((void**)&pbKV2, g_bKV2);
    __half *pwq1, *pwo1, *pwq2, *pwo2, *pwf1, *pwf2, *pfeats, *penc;
    __half *pKV1w, *pKV2w, *pKV1, *pQ1, *pT1, *pYh1, *pKV2, *pQ, *pT, *pYh, *pX, *pHb;
    cudaGetSymbolAddress((void**)&pwq1, h_wq1);
    cudaGetSymbolAddress((void**)&pwo1, h_wo1);
    cudaGetSymbolAddress((void**)&pwq2, h_wq2);
    cudaGetSymbolAddress((void**)&pwo2, h_wo2);
    cudaGetSymbolAddress((void**)&pwf1, h_wf1);
    cudaGetSymbolAddress((void**)&pwf2, h_wf2);
    cudaGetSymbolAddress((void**)&pfeats, h_feats);
    cudaGetSymbolAddress((void**)&penc, h_enc);
    cudaGetSymbolAddress((void**)&pKV1w, h_KV1w);
    cudaGetSymbolAddress((void**)&pKV2w, h_KV2w);
    cudaGetSymbolAddress((void**)&pKV1, h_KV1);
    cudaGetSymbolAddress((void**)&pQ1, h_Q1);
    cudaGetSymbolAddress((void**)&pT1, h_T1);
    cudaGetSymbolAddress((void**)&pYh1, h_Yh1);
    cudaGetSymbolAddress((void**)&pKV2, h_KV2);
    cudaGetSymbolAddress((void**)&pQ, h_Q);
    cudaGetSymbolAddress((void**)&pT, h_T);
    cudaGetSymbolAddress((void**)&pYh, h_Yh);
    cudaGetSymbolAddress((void**)&pX, h_X);
    cudaGetSymbolAddress((void**)&pHb, h_Hb);

    // ---- conversions + packing (stream 0) ----
    const long nDD = (long)LLAYERS * DD * DD;
    const long nFD = (long)LLAYERS * FF * DD;
    cvt(wq1, pwq1, nDD); cvt(wo1, pwo1, nDD);
    cvt(wq2, pwq2, nDD); cvt(wo2, pwo2, nDD);
    cvt(wf1, pwf1, nFD); cvt(wf2, pwf2, nFD);
    cvt(feats, pfeats, (long)LLAYERS * MTOK * DD);
    cvt(enc, penc, (long)MTOK * DD);
    pack_w<<<(unsigned)(2 * nDD / 2048), 256>>>(wk1, wv1, pKV1w, (long)DD * DD);
    pack_w<<<(unsigned)(2 * nDD / 2048), 256>>>(wk2, wv2, pKV2w, (long)DD * DD);
    pack_b<<<(unsigned)(2 * LLAYERS * DD / 1024), 256>>>(bk1, bv1, pbKV1, DD);
    pack_b<<<(unsigned)(2 * LLAYERS * DD / 1024), 256>>>(bk2, bv2, pbKV2, DD);

    dim3 blk(256);
    dim3 gD(DD / 128, MTOK / 128);             // 8 x 32
    dim3 gKV(2 * DD / 128, MTOK / 128);        // 16 x 32
    dim3 gF(FF / 128, MTOK / 128);             // 32 x 32
    dim3 gA(NN / 64, BB * HH);                 // 16 x 64

    // ---- fork: phase A (attn1 branch, input-only) on s2 ----
    cudaEventRecord(evF, 0);
    cudaStreamWaitEvent(s2, evF, 0);

    for (int l = 0; l < LLAYERS; l++) {
        const size_t wOff = (size_t)l * DD * DD;
        const size_t vOff = (size_t)l * DD;
        const size_t aOff = (size_t)l * MTOK * DD;
        const size_t kOff = (size_t)l * MTOK * 2 * DD;

        gemm_h<<<gD, blk, GEMM_SMEM_BYTES, s2>>>(
            pfeats + aOff, pwq1 + wOff, bq1 + vOff, nullptr,
            nullptr, pQ1 + aOff, MTOK, DD, DD, 0, DD);
        gemm_h<<<gKV, blk, GEMM_SMEM_BYTES, s2>>>(
            penc, pKV1w + 2 * wOff, pbKV1 + 2 * vOff, nullptr,
            nullptr, pKV1 + kOff, MTOK, 2 * DD, DD, 0, 2 * DD);
        attn_h<<<gA, blk, ATT_SMEM_BYTES, s2>>>(
            pQ1 + aOff, pKV1 + kOff, pKV1 + kOff + DD, pT1 + aOff,
            src_mask, 2 * DD);
        gemm_h<<<gD, blk, GEMM_SMEM_BYTES, s2>>>(
            pT1 + aOff, pwo1 + wOff, bo1 + vOff, feats + aOff,
            Y1 + aOff, nullptr, MTOK, DD, DD, 0, DD);
        layernorm_row<<<MTOK, blk, 0, s2>>>(
            Y1 + aOff, g1 + vOff, be1 + vOff, Y1 + aOff, pYh1 + aOff);
        cudaEventRecord(evL[l], s2);
    }

    // ---- phase B: serial decoder chain on stream 0 ----
    const __half* Xh = penc;
    for (int l = 0; l < LLAYERS; l++) {
        const size_t wOff = (size_t)l * DD * DD;
        const size_t fOff = (size_t)l * FF * DD;
        const size_t vOff = (size_t)l * DD;
        const size_t aOff = (size_t)l * MTOK * DD;

        cudaStreamWaitEvent(0, evL[l], 0);

        // attn2 (trg_mask): q from y1, k/v from decoder state Xh
        gemm_h<<<gD, blk, GEMM_SMEM_BYTES>>>(
            pYh1 + aOff, pwq2 + wOff, bq2 + vOff, nullptr,
            nullptr, pQ, MTOK, DD, DD, 0, DD);
        gemm_h<<<gKV, blk, GEMM_SMEM_BYTES>>>(
            Xh, pKV2w + 2 * wOff, pbKV2 + 2 * vOff, nullptr,
            nullptr, pKV2, MTOK, 2 * DD, DD, 0, 2 * DD);
        attn_h<<<gA, blk, ATT_SMEM_BYTES>>>(
            pQ, pKV2, pKV2 + DD, pT, trg_mask, 2 * DD);
        gemm_h<<<gD, blk, GEMM_SMEM_BYTES>>>(
            pT, pwo2 + wOff, bo2 + vOff, Y1 + aOff,
            Y, nullptr, MTOK, DD, DD, 0, DD);
        layernorm_row<<<MTOK, blk>>>(Y, g2 + vOff, be2 + vOff, Y, pYh);

        // FFN
        gemm_h<<<gF, blk, GEMM_SMEM_BYTES>>>(
            pYh, pwf1 + fOff, bf1 + (size_t)l * FF, nullptr,
            nullptr, pHb, MTOK, FF, DD, 1, FF);
        gemm_h<<<gD, blk, GEMM_SMEM_BYTES>>>(
            pHb, pwf2 + fOff, bf2 + vOff, Y,
            Y, nullptr, MTOK, DD, FF, 0, DD);
        float* outl = out + aOff;
        layernorm_row<<<MTOK, blk>>>(Y, g3 + vOff, be3 + vOff, outl, pX);

        Xh = pX;
    }
    (void)in_sizes; (void)n_in; (void)out_size;
}

// round 9
// speedup vs baseline: 3.5148x; 1.0030x over previous
#include <cuda_runtime.h>
#include <cuda_fp16.h>
#include <mma.h>
#include <cstddef>
#include <cstdint>

using namespace nvcuda;

#define LLAYERS 6
#define BB 4
#define NN 1024
#define DD 1024
#define HH 16
#define HDIM 64
#define FF 4096
#define MTOK (BB * NN)      /* 4096 */
#define LN_EPS 1e-5f

// ---------------- scratch (no allocations allowed) ----------------
__device__ float  g_Y[(size_t)MTOK * DD];
__device__ float  g_Y1[(size_t)LLAYERS * MTOK * DD];
// fp16 mirrors
__device__ __half h_wq1[(size_t)LLAYERS * DD * DD];
__device__ __half h_wo1[(size_t)LLAYERS * DD * DD];
__device__ __half h_wq2[(size_t)LLAYERS * DD * DD];
__device__ __half h_wo2[(size_t)LLAYERS * DD * DD];
__device__ __half h_wf1[(size_t)LLAYERS * FF * DD];
__device__ __half h_wf2[(size_t)LLAYERS * DD * FF];
__device__ __half h_feats[(size_t)LLAYERS * MTOK * DD];
__device__ __half h_enc[(size_t)MTOK * DD];
// packed KV weights / biases
__device__ __half h_KV1w[(size_t)LLAYERS * 2 * DD * DD];
__device__ __half h_KV2w[(size_t)LLAYERS * 2 * DD * DD];
__device__ float  g_bKV1[(size_t)LLAYERS * 2 * DD];
__device__ float  g_bKV2[(size_t)LLAYERS * 2 * DD];
// activations
__device__ __half h_KV1[(size_t)LLAYERS * MTOK * 2 * DD];
__device__ __half h_Q1[(size_t)LLAYERS * MTOK * DD];
__device__ __half h_T1[(size_t)LLAYERS * MTOK * DD];
__device__ __half h_Yh1[(size_t)LLAYERS * MTOK * DD];
__device__ __half h_KV2[(size_t)MTOK * 2 * DD];
__device__ __half h_Q[(size_t)MTOK * DD];
__device__ __half h_T[(size_t)MTOK * DD];
__device__ __half h_Yh[(size_t)MTOK * DD];
__device__ __half h_X[(size_t)MTOK * DD];
__device__ __half h_Hb[(size_t)MTOK * FF];

// ---------------- cp.async helpers ----------------
__device__ __forceinline__ void cp16(void* sptr, const void* gptr) {
    uint32_t sa = (uint32_t)__cvta_generic_to_shared(sptr);
    asm volatile("cp.async.cg.shared.global [%0], [%1], 16;\n" :: "r"(sa), "l"(gptr));
}
#define CP_COMMIT() asm volatile("cp.async.commit_group;\n" ::: "memory")
#define CP_WAIT_0() asm volatile("cp.async.wait_group 0;\n" ::: "memory")
#define CP_WAIT_1() asm volatile("cp.async.wait_group 1;\n" ::: "memory")

// =====================================================================
// Conversion / packing kernels
// =====================================================================
__global__ __launch_bounds__(256) void cvt_f2h(
    const float* __restrict__ s, __half* __restrict__ d, long n)
{
    long i = ((long)blockIdx.x * 256 + threadIdx.x) * 8;
    if (i >= n) return;
    float4 a = *(const float4*)(s + i);
    float4 b = *(const float4*)(s + i + 4);
    uint4 u;
    ((__half2*)&u)[0] = __floats2half2_rn(a.x, a.y);
    ((__half2*)&u)[1] = __floats2half2_rn(a.z, a.w);
    ((__half2*)&u)[2] = __floats2half2_rn(b.x, b.y);
    ((__half2*)&u)[3] = __floats2half2_rn(b.z, b.w);
    *(uint4*)(d + i) = u;
}

__global__ __launch_bounds__(256) void pack_w(
    const float* __restrict__ a, const float* __restrict__ b,
    __half* __restrict__ dst, long perL)
{
    long i = ((long)blockIdx.x * 256 + threadIdx.x) * 8;
    long l = i / (2 * perL);
    long r = i - l * 2 * perL;
    const float* src = (r < perL) ? a + l * perL + r : b + l * perL + (r - perL);
    float4 x = *(const float4*)(src);
    float4 y = *(const float4*)(src + 4);
    uint4 u;
    ((__half2*)&u)[0] = __floats2half2_rn(x.x, x.y);
    ((__half2*)&u)[1] = __floats2half2_rn(x.z, x.w);
    ((__half2*)&u)[2] = __floats2half2_rn(y.x, y.y);
    ((__half2*)&u)[3] = __floats2half2_rn(y.z, y.w);
    *(uint4*)(dst + i) = u;
}

__global__ __launch_bounds__(256) void pack_b(
    const float* __restrict__ a, const float* __restrict__ b,
    float* __restrict__ dst, long perL)
{
    long i = ((long)blockIdx.x * 256 + threadIdx.x) * 4;
    long l = i / (2 * perL);
    long r = i - l * 2 * perL;
    const float* src = (r < perL) ? a + l * perL + r : b + l * perL + (r - perL);
    *(float4*)(dst + i) = *(const float4*)src;
}

// =====================================================================
// f16 TC GEMM (unchanged from round 8)
// =====================================================================
#define GBKH 64
#define GSTH 72
#define GBUFH (128 * GSTH)
#define GEMM_SMEM_BYTES (4 * GBUFH * 2)   /* 73728 B */

__global__ __launch_bounds__(256, 2) void gemm_h(
    const __half* __restrict__ A, const __half* __restrict__ W,
    const float* __restrict__ bias, const float* __restrict__ res,
    float* __restrict__ C, __half* __restrict__ Ch,
    int M, int N, int K, int doRelu, int ldc)
{
    extern __shared__ char dynb[];
    __half* hsm = (__half*)dynb;
    __shared__ float stage[8][16 * 16];

    const int tid  = threadIdx.x;
    const int warp = tid >> 5;
    const int lane = tid & 31;
    const int wm   = warp >> 2;
    const int wn   = warp & 3;

    const __half* Ab = A + (size_t)blockIdx.y * 128 * K;
    const __half* Wb = W + (size_t)blockIdx.x * 128 * K;
    const int KT = K / GBKH;

    wmma::fragment<wmma::accumulator, 16, 16, 16, float> acc[4][2];
#pragma unroll
    for (int i = 0; i < 4; i++)
#pragma unroll
        for (int j = 0; j < 2; j++) wmma::fill_fragment(acc[i][j], 0.f);

    {
        __half* As = hsm;
        __half* Ws = hsm + GBUFH;
#pragma unroll
        for (int t = 0; t < 4; t++) {
            int c = tid + t * 256;
            int row = c >> 3, col8 = c & 7;
            cp16(As + row * GSTH + col8 * 8, Ab + (size_t)row * K + col8 * 8);
            cp16(Ws + row * GSTH + col8 * 8, Wb + (size_t)row * K + col8 * 8);
        }
        CP_COMMIT();
    }

    for (int kt = 0; kt < KT; kt++) {
        if (kt + 1 < KT) {
            __half* As = hsm + ((kt + 1) & 1) * 2 * GBUFH;
            __half* Ws = As + GBUFH;
            const int k0 = (kt + 1) * GBKH;
#pragma unroll
            for (int t = 0; t < 4; t++) {
                int c = tid + t * 256;
                int row = c >> 3, col8 = c & 7;
                cp16(As + row * GSTH + col8 * 8, Ab + (size_t)row * K + k0 + col8 * 8);
                cp16(Ws + row * GSTH + col8 * 8, Wb + (size_t)row * K + k0 + col8 * 8);
            }
            CP_COMMIT();
            CP_WAIT_1();
        } else {
            CP_WAIT_0();
        }
        __syncthreads();

        const __half* As = hsm + (kt & 1) * 2 * GBUFH;
        const __half* Ws = As + GBUFH;
#pragma unroll
        for (int kk = 0; kk < 4; kk++) {
            wmma::fragment<wmma::matrix_a, 16, 16, 16, __half, wmma::row_major> af[4];
            wmma::fragment<wmma::matrix_b, 16, 16, 16, __half, wmma::col_major> bf[2];
#pragma unroll
            for (int i = 0; i < 4; i++)
                wmma::load_matrix_sync(af[i], &As[(wm * 64 + i * 16) * GSTH + kk * 16], GSTH);
#pragma unroll
            for (int j = 0; j < 2; j++)
                wmma::load_matrix_sync(bf[j], &Ws[(wn * 32 + j * 16) * GSTH + kk * 16], GSTH);
#pragma unroll
            for (int i = 0; i < 4; i++)
#pragma unroll
                for (int j = 0; j < 2; j++)
                    wmma::mma_sync(acc[i][j], af[i], bf[j], acc[i][j]);
        }
        __syncthreads();
    }

#pragma unroll
    for (int i = 0; i < 4; i++) {
#pragma unroll
        for (int j = 0; j < 2; j++) {
            wmma::store_matrix_sync(stage[warp], acc[i][j], 16, wmma::mem_row_major);
            __syncwarp();
            int r0 = blockIdx.y * 128 + wm * 64 + i * 16;
            int c0 = blockIdx.x * 128 + wn * 32 + j * 16;
#pragma unroll
            for (int e = 0; e < 2; e++) {
                int idx = lane + e * 32;
                int rr  = idx >> 2;
                int cc  = (idx & 3) << 2;
                float4 v  = *(float4*)&stage[warp][rr * 16 + cc];
                float4 b4 = *(const float4*)(bias + c0 + cc);
                v.x += b4.x; v.y += b4.y; v.z += b4.z; v.w += b4.w;
                size_t row = (size_t)(r0 + rr);
                if (res) {
                    float4 r = *(const float4*)(res + row * ldc + c0 + cc);
                    v.x += r.x; v.y += r.y; v.z += r.z; v.w += r.w;
                }
                if (doRelu) {
                    v.x = fmaxf(v.x, 0.f); v.y = fmaxf(v.y, 0.f);
                    v.z = fmaxf(v.z, 0.f); v.w = fmaxf(v.w, 0.f);
                }
                if (C) *(float4*)(C + row * ldc + c0 + cc) = v;
                if (Ch) {
                    uint2 u;
                    ((__half2*)&u)[0] = __floats2half2_rn(v.x, v.y);
                    ((__half2*)&u)[1] = __floats2half2_rn(v.z, v.w);
                    *(uint2*)(Ch + row * ldc + c0 + cc) = u;
                }
            }
            __syncwarp();
        }
    }
}

// =====================================================================
// Flash attention v3: warp-private ownership.
// Block = 128 Q rows, 8 warps; warp w owns rows w*16..w*16+15 (full 64
// cols). S / PV-result live in a warp-private f32 slab; P in warp rows
// of a shared f16 slab; O in registers (lane owns row lane>>1 of its
// warp's 16, col half lane&1). 2 block barriers per j-tile.
// grid: (N/128, B*H)
// =====================================================================
#define AQ_ST 72   /* halves */
#define AS_ST 68   /* floats */
#define NATQ   0                           /* Q: 128*72*2 = 18432 */
#define NATP   18432                       /* P: 128*72*2 = 18432 */
#define NATS   36864                       /* Swork: 8*16*68*4 = 34816 */
#define NATK(s) (71680 + (s) * 9216)
#define NATV(s) (90112 + (s) * 9216)
#define ATT_SMEM_BYTES 108544

__global__ __launch_bounds__(256, 2) void attn_h(
    const __half* __restrict__ Q, const __half* __restrict__ Kb,
    const __half* __restrict__ V, __half* __restrict__ T,
    const float* __restrict__ mask, int ldkv)
{
    extern __shared__ char dynb[];
    __half* Qs = (__half*)(dynb + NATQ);
    __half* Ps = (__half*)(dynb + NATP);

    const int z = blockIdx.y;
    const int b = z >> 4, hh = z & 15;
    const __half* Qz = Q  + (size_t)b * NN * DD   + hh * HDIM;
    const __half* Kz = Kb + (size_t)b * NN * ldkv + hh * HDIM;
    const __half* Vz = V  + (size_t)b * NN * ldkv + hh * HDIM;
    __half*       Tz = T  + (size_t)b * NN * DD   + hh * HDIM;
    const int i0 = blockIdx.x * 128;

    const int tid  = threadIdx.x;
    const int warp = tid >> 5;
    const int lane = tid & 31;
    const int rw   = lane >> 1;          // row within warp's 16
    const int ch   = lane & 1;           // col half (32 cols)
    const int rloc = warp * 16 + rw;     // block-local row

    float* Sw = (float*)(dynb + NATS) + warp * 16 * AS_ST;
    const float* mrow = mask + (size_t)(i0 + rloc) * NN + ch * 32;

    // ---- group 0: Q tile (128 x 64 halves = 1024 x 16B chunks) ----
#pragma unroll
    for (int t = 0; t < 4; t++) {
        int c = tid + t * 256;
        int row = c >> 3, col8 = c & 7;
        cp16(Qs + row * AQ_ST + col8 * 8, Qz + (size_t)(i0 + row) * DD + col8 * 8);
    }
    CP_COMMIT();
    // ---- group 1: K/V tile 0 ----
    {
        __half* Ks = (__half*)(dynb + NATK(0));
        __half* Vs = (__half*)(dynb + NATV(0));
#pragma unroll
        for (int t = 0; t < 2; t++) {
            int c = tid + t * 256;
            int row = c >> 3, col8 = c & 7;
            cp16(Ks + row * AQ_ST + col8 * 8, Kz + (size_t)row * ldkv + col8 * 8);
            cp16(Vs + row * AQ_ST + col8 * 8, Vz + (size_t)row * ldkv + col8 * 8);
        }
        CP_COMMIT();
    }

    float O[32];
#pragma unroll
    for (int t = 0; t < 32; t++) O[t] = 0.f;
    float m_run = -1e30f, s_run = 0.f;

    CP_WAIT_1();            // Q ready
    __syncthreads();        // Qs visible to all warps

    const int J = NN / 64;
    for (int j0 = 0; j0 < J; j0++) {
        if (j0 > 0) __syncthreads();   // all reads of the target stage done
        if (j0 + 1 < J) {
            __half* Ks = (__half*)(dynb + NATK((j0 + 1) & 1));
            __half* Vs = (__half*)(dynb + NATV((j0 + 1) & 1));
            const size_t rbase = (size_t)(j0 + 1) * 64;
#pragma unroll
            for (int t = 0; t < 2; t++) {
                int c = tid + t * 256;
                int row = c >> 3, col8 = c & 7;
                cp16(Ks + row * AQ_ST + col8 * 8, Kz + (rbase + row) * ldkv + col8 * 8);
                cp16(Vs + row * AQ_ST + col8 * 8, Vz + (rbase + row) * ldkv + col8 * 8);
            }
            CP_COMMIT();
            CP_WAIT_1();
        } else {
            CP_WAIT_0();
        }
        __syncthreads();    // tile j0 visible

        const __half* Ks = (__half*)(dynb + NATK(j0 & 1));
        const __half* Vs = (__half*)(dynb + NATV(j0 & 1));

        // ---- S = Q @ K^T for this warp's 16 rows x 64 cols ----
#pragma unroll
        for (int nc = 0; nc < 4; nc++) {
            wmma::fragment<wmma::accumulator, 16, 16, 16, float> sacc;
            wmma::fill_fragment(sacc, 0.f);
#pragma unroll
            for (int kk = 0; kk < 4; kk++) {
                wmma::fragment<wmma::matrix_a, 16, 16, 16, __half, wmma::row_major> af;
                wmma::fragment<wmma::matrix_b, 16, 16, 16, __half, wmma::col_major> bf;
                wmma::load_matrix_sync(af, &Qs[(warp * 16) * AQ_ST + kk * 16], AQ_ST);
                wmma::load_matrix_sync(bf, &Ks[(nc * 16) * AQ_ST + kk * 16], AQ_ST);
                wmma::mma_sync(sacc, af, bf, sacc);
            }
            wmma::store_matrix_sync(&Sw[nc * 16], sacc, AS_ST, wmma::mem_row_major);
        }
        __syncwarp();

        // ---- online softmax (lane owns row rw, cols ch*32..+31) ----
        {
            float* srow = Sw + rw * AS_ST + ch * 32;
            const float* mj = mrow + j0 * 64;

            float tmax = -1e30f;
#pragma unroll
            for (int t = 0; t < 8; t++) {
                float4 sv = *(const float4*)(srow + t * 4);
                float4 mk = *(const float4*)(mj + t * 4);
                float a0 = sv.x * 0.125f + mk.x;
                float a1 = sv.y * 0.125f + mk.y;
                float a2 = sv.z * 0.125f + mk.z;
                float a3 = sv.w * 0.125f + mk.w;
                tmax = fmaxf(tmax, fmaxf(fmaxf(a0, a1), fmaxf(a2, a3)));
            }
            tmax = fmaxf(tmax, __shfl_xor_sync(0xffffffffu, tmax, 1));
            float m_new = fmaxf(m_run, tmax);
            float corr  = __expf(m_run - m_new);

            __half* prow = Ps + rloc * AQ_ST + ch * 32;
            float tsum = 0.f;
#pragma unroll
            for (int t = 0; t < 4; t++) {
                float4 s0 = *(const float4*)(srow + t * 8);
                float4 s1 = *(const float4*)(srow + t * 8 + 4);
                float4 m0 = *(const float4*)(mj + t * 8);
                float4 m1 = *(const float4*)(mj + t * 8 + 4);
                float p0 = __expf(s0.x * 0.125f + m0.x - m_new);
                float p1 = __expf(s0.y * 0.125f + m0.y - m_new);
                float p2 = __expf(s0.z * 0.125f + m0.z - m_new);
                float p3 = __expf(s0.w * 0.125f + m0.w - m_new);
                float p4 = __expf(s1.x * 0.125f + m1.x - m_new);
                float p5 = __expf(s1.y * 0.125f + m1.y - m_new);
                float p6 = __expf(s1.z * 0.125f + m1.z - m_new);
                float p7 = __expf(s1.w * 0.125f + m1.w - m_new);
                tsum += p0 + p1 + p2 + p3 + p4 + p5 + p6 + p7;
                uint4 u;
                ((__half2*)&u)[0] = __floats2half2_rn(p0, p1);
                ((__half2*)&u)[1] = __floats2half2_rn(p2, p3);
                ((__half2*)&u)[2] = __floats2half2_rn(p4, p5);
                ((__half2*)&u)[3] = __floats2half2_rn(p6, p7);
                *(uint4*)(prow + t * 8) = u;
            }
            tsum += __shfl_xor_sync(0xffffffffu, tsum, 1);
            s_run = s_run * corr + tsum;
            m_run = m_new;

#pragma unroll
            for (int t = 0; t < 32; t++) O[t] *= corr;
        }
        __syncwarp();

        // ---- PV for this warp's rows -> Sw ----
#pragma unroll
        for (int nc = 0; nc < 4; nc++) {
            wmma::fragment<wmma::accumulator, 16, 16, 16, float> oacc;
            wmma::fill_fragment(oacc, 0.f);
#pragma unroll
            for (int kk = 0; kk < 4; kk++) {
                wmma::fragment<wmma::matrix_a, 16, 16, 16, __half, wmma::row_major> pf;
                wmma::fragment<wmma::matrix_b, 16, 16, 16, __half, wmma::row_major> vf;
                wmma::load_matrix_sync(pf, &Ps[(warp * 16) * AQ_ST + kk * 16], AQ_ST);
                wmma::load_matrix_sync(vf, &Vs[(kk * 16) * AQ_ST + nc * 16], AQ_ST);
                wmma::mma_sync(oacc, pf, vf, oacc);
            }
            wmma::store_matrix_sync(&Sw[nc * 16], oacc, AS_ST, wmma::mem_row_major);
        }
        __syncwarp();

        // ---- O += owned PV segment ----
        {
            const float* prow = Sw + rw * AS_ST + ch * 32;
#pragma unroll
            for (int t = 0; t < 8; t++) {
                float4 p = *(const float4*)(prow + t * 4);
                O[t * 4 + 0] += p.x; O[t * 4 + 1] += p.y;
                O[t * 4 + 2] += p.z; O[t * 4 + 3] += p.w;
            }
        }
    }

    // ---- epilogue ----
    float inv = 1.f / s_run;
    __half* td = Tz + (size_t)(i0 + rloc) * DD + ch * 32;
#pragma unroll
    for (int t = 0; t < 4; t++) {
        uint4 u;
        ((__half2*)&u)[0] = __floats2half2_rn(O[t*8+0] * inv, O[t*8+1] * inv);
        ((__half2*)&u)[1] = __floats2half2_rn(O[t*8+2] * inv, O[t*8+3] * inv);
        ((__half2*)&u)[2] = __floats2half2_rn(O[t*8+4] * inv, O[t*8+5] * inv);
        ((__half2*)&u)[3] = __floats2half2_rn(O[t*8+6] * inv, O[t*8+7] * inv);
        *(uint4*)(td + t * 8) = u;
    }
}

// =====================================================================
// LayerNorm over last dim (1024); f32 out + optional f16 out.
// =====================================================================
__global__ __launch_bounds__(256) void layernorm_row(
    const float* __restrict__ X, const float* __restrict__ g,
    const float* __restrict__ bta, float* __restrict__ Y,
    __half* __restrict__ Yh)
{
    __shared__ float red[256];
    const size_t base = (size_t)blockIdx.x * DD;
    const int tid = threadIdx.x;
    float4 v = *(const float4*)(X + base + tid * 4);

    red[tid] = v.x + v.y + v.z + v.w; __syncthreads();
    for (int s = 128; s > 0; s >>= 1) {
        if (tid < s) red[tid] += red[tid + s];
        __syncthreads();
    }
    float mean = red[0] * (1.f / DD); __syncthreads();

    float dx = v.x - mean, dy = v.y - mean, dz = v.z - mean, dw = v.w - mean;
    red[tid] = dx * dx + dy * dy + dz * dz + dw * dw; __syncthreads();
    for (int s = 128; s > 0; s >>= 1) {
        if (tid < s) red[tid] += red[tid + s];
        __syncthreads();
    }
    float inv = rsqrtf(red[0] * (1.f / DD) + LN_EPS);

    float4 gg = *(const float4*)(g + tid * 4);
    float4 bb = *(const float4*)(bta + tid * 4);
    float4 o;
    o.x = dx * inv * gg.x + bb.x;
    o.y = dy * inv * gg.y + bb.y;
    o.z = dz * inv * gg.z + bb.z;
    o.w = dw * inv * gg.w + bb.w;
    *(float4*)(Y + base + tid * 4) = o;
    if (Yh) {
        uint2 u;
        ((__half2*)&u)[0] = __floats2half2_rn(o.x, o.y);
        ((__half2*)&u)[1] = __floats2half2_rn(o.z, o.w);
        *(uint2*)(Yh + base + tid * 4) = u;
    }
}

// =====================================================================
// Host orchestration: dual-stream fork-join; B-set conversions overlap
// phase A.
// =====================================================================
static inline void cvt(const float* src, __half* dst, long n) {
    cvt_f2h<<<(unsigned)(n / 2048), 256>>>(src, dst, n);
}

extern "C" void kernel_launch(void* const* d_in, const int* in_sizes, int n_in,
                              void* d_out, int out_size)
{
    const float* feats    = (const float*)d_in[0];
    const float* enc      = (const float*)d_in[1];
    const float* trg_mask = (const float*)d_in[2];
    const float* src_mask = (const float*)d_in[3];
    const float* wq1 = (const float*)d_in[4];  const float* bq1 = (const float*)d_in[5];
    const float* wk1 = (const float*)d_in[6];  const float* bk1 = (const float*)d_in[7];
    const float* wv1 = (const float*)d_in[8];  const float* bv1 = (const float*)d_in[9];
    const float* wo1 = (const float*)d_in[10]; const float* bo1 = (const float*)d_in[11];
    const float* wq2 = (const float*)d_in[12]; const float* bq2 = (const float*)d_in[13];
    const float* wk2 = (const float*)d_in[14]; const float* bk2 = (const float*)d_in[15];
    const float* wv2 = (const float*)d_in[16]; const float* bv2 = (const float*)d_in[17];
    const float* wo2 = (const float*)d_in[18]; const float* bo2 = (const float*)d_in[19];
    const float* wf1 = (const float*)d_in[20]; const float* bf1 = (const float*)d_in[21];
    const float* wf2 = (const float*)d_in[22]; const float* bf2 = (const float*)d_in[23];
    const float* g1  = (const float*)d_in[24]; const float* be1 = (const float*)d_in[25];
    const float* g2  = (const float*)d_in[26]; const float* be2 = (const float*)d_in[27];
    const float* g3  = (const float*)d_in[28]; const float* be3 = (const float*)d_in[29];
    float* out = (float*)d_out;

    static int init_done = 0;
    static cudaStream_t s2;
    static cudaEvent_t evF;
    static cudaEvent_t evL[LLAYERS];
    if (!init_done) {
        cudaFuncSetAttribute(gemm_h,
            cudaFuncAttributeMaxDynamicSharedMemorySize, GEMM_SMEM_BYTES);
        cudaFuncSetAttribute(attn_h,
            cudaFuncAttributeMaxDynamicSharedMemorySize, ATT_SMEM_BYTES);
        cudaStreamCreateWithFlags(&s2, cudaStreamNonBlocking);
        cudaEventCreateWithFlags(&evF, cudaEventDisableTiming);
        for (int l = 0; l < LLAYERS; l++)
            cudaEventCreateWithFlags(&evL[l], cudaEventDisableTiming);
        init_done = 1;
    }

    float *Y, *Y1, *pbKV1, *pbKV2;
    cudaGetSymbolAddress((void**)&Y,  g_Y);
    cudaGetSymbolAddress((void**)&Y1, g_Y1);
    cudaGetSymbolAddress((void**)&pbKV1, g_bKV1);
    cudaGetSymbolAddress((void**)&pbKV2, g_bKV2);
    __half *pwq1, *pwo1, *pwq2, *pwo2, *pwf1, *pwf2, *pfeats, *penc;
    __half *pKV1w, *pKV2w, *pKV1, *pQ1, *pT1, *pYh1, *pKV2, *pQ, *pT, *pYh, *pX, *pHb;
    cudaGetSymbolAddress((void**)&pwq1, h_wq1);
    cudaGetSymbolAddress((void**)&pwo1, h_wo1);
    cudaGetSymbolAddress((void**)&pwq2, h_wq2);
    cudaGetSymbolAddress((void**)&pwo2, h_wo2);
    cudaGetSymbolAddress((void**)&pwf1, h_wf1);
    cudaGetSymbolAddress((void**)&pwf2, h_wf2);
    cudaGetSymbolAddress((void**)&pfeats, h_feats);
    cudaGetSymbolAddress((void**)&penc, h_enc);
    cudaGetSymbolAddress((void**)&pKV1w, h_KV1w);
    cudaGetSymbolAddress((void**)&pKV2w, h_KV2w);
    cudaGetSymbolAddress((void**)&pKV1, h_KV1);
    cudaGetSymbolAddress((void**)&pQ1, h_Q1);
    cudaGetSymbolAddress((void**)&pT1, h_T1);
    cudaGetSymbolAddress((void**)&pYh1, h_Yh1);
    cudaGetSymbolAddress((void**)&pKV2, h_KV2);
    cudaGetSymbolAddress((void**)&pQ, h_Q);
    cudaGetSymbolAddress((void**)&pT, h_T);
    cudaGetSymbolAddress((void**)&pYh, h_Yh);
    cudaGetSymbolAddress((void**)&pX, h_X);
    cudaGetSymbolAddress((void**)&pHb, h_Hb);

    const long nDD = (long)LLAYERS * DD * DD;
    const long nFD = (long)LLAYERS * FF * DD;

    // ---- A-set conversions (needed by phase A) on stream 0 ----
    cvt(enc, penc, (long)MTOK * DD);
    cvt(feats, pfeats, (long)LLAYERS * MTOK * DD);
    cvt(wq1, pwq1, nDD);
    cvt(wo1, pwo1, nDD);
    pack_w<<<(unsigned)(2 * nDD / 2048), 256>>>(wk1, wv1, pKV1w, (long)DD * DD);
    pack_b<<<(unsigned)(2 * LLAYERS * DD / 1024), 256>>>(bk1, bv1, pbKV1, DD);

    dim3 blk(256);
    dim3 gD(DD / 128, MTOK / 128);             // 8 x 32
    dim3 gKV(2 * DD / 128, MTOK / 128);        // 16 x 32
    dim3 gF(FF / 128, MTOK / 128);             // 32 x 32
    dim3 gA(NN / 128, BB * HH);                // 8 x 64

    // ---- fork: phase A (attn1 branch) on s2 ----
    cudaEventRecord(evF, 0);
    cudaStreamWaitEvent(s2, evF, 0);

    for (int l = 0; l < LLAYERS; l++) {
        const size_t wOff = (size_t)l * DD * DD;
        const size_t vOff = (size_t)l * DD;
        const size_t aOff = (size_t)l * MTOK * DD;
        const size_t kOff = (size_t)l * MTOK * 2 * DD;

        gemm_h<<<gD, blk, GEMM_SMEM_BYTES, s2>>>(
            pfeats + aOff, pwq1 + wOff, bq1 + vOff, nullptr,
            nullptr, pQ1 + aOff, MTOK, DD, DD, 0, DD);
        gemm_h<<<gKV, blk, GEMM_SMEM_BYTES, s2>>>(
            penc, pKV1w + 2 * wOff, pbKV1 + 2 * vOff, nullptr,
            nullptr, pKV1 + kOff, MTOK, 2 * DD, DD, 0, 2 * DD);
        attn_h<<<gA, blk, ATT_SMEM_BYTES, s2>>>(
            pQ1 + aOff, pKV1 + kOff, pKV1 + kOff + DD, pT1 + aOff,
            src_mask, 2 * DD);
        gemm_h<<<gD, blk, GEMM_SMEM_BYTES, s2>>>(
            pT1 + aOff, pwo1 + wOff, bo1 + vOff, feats + aOff,
            Y1 + aOff, nullptr, MTOK, DD, DD, 0, DD);
        layernorm_row<<<MTOK, blk, 0, s2>>>(
            Y1 + aOff, g1 + vOff, be1 + vOff, Y1 + aOff, pYh1 + aOff);
        cudaEventRecord(evL[l], s2);
    }

    // ---- B-set conversions on stream 0 (overlap phase A) ----
    cvt(wq2, pwq2, nDD);
    cvt(wo2, pwo2, nDD);
    cvt(wf1, pwf1, nFD);
    cvt(wf2, pwf2, nFD);
    pack_w<<<(unsigned)(2 * nDD / 2048), 256>>>(wk2, wv2, pKV2w, (long)DD * DD);
    pack_b<<<(unsigned)(2 * LLAYERS * DD / 1024), 256>>>(bk2, bv2, pbKV2, DD);

    // ---- phase B: serial decoder chain on stream 0 ----
    const __half* Xh = penc;
    for (int l = 0; l < LLAYERS; l++) {
        const size_t wOff = (size_t)l * DD * DD;
        const size_t fOff = (size_t)l * FF * DD;
        const size_t vOff = (size_t)l * DD;
        const size_t aOff = (size_t)l * MTOK * DD;

        cudaStreamWaitEvent(0, evL[l], 0);

        gemm_h<<<gD, blk, GEMM_SMEM_BYTES>>>(
            pYh1 + aOff, pwq2 + wOff, bq2 + vOff, nullptr,
            nullptr, pQ, MTOK, DD, DD, 0, DD);
        gemm_h<<<gKV, blk, GEMM_SMEM_BYTES>>>(
            Xh, pKV2w + 2 * wOff, pbKV2 + 2 * vOff, nullptr,
            nullptr, pKV2, MTOK, 2 * DD, DD, 0, 2 * DD);
        attn_h<<<gA, blk, ATT_SMEM_BYTES>>>(
            pQ, pKV2, pKV2 + DD, pT, trg_mask, 2 * DD);
        gemm_h<<<gD, blk, GEMM_SMEM_BYTES>>>(
            pT, pwo2 + wOff, bo2 + vOff, Y1 + aOff,
            Y, nullptr, MTOK, DD, DD, 0, DD);
        layernorm_row<<<MTOK, blk>>>(Y, g2 + vOff, be2 + vOff, Y, pYh);

        gemm_h<<<gF, blk, GEMM_SMEM_BYTES>>>(
            pYh, pwf1 + fOff, bf1 + (size_t)l * FF, nullptr,
            nullptr, pHb, MTOK, FF, DD, 1, FF);
        gemm_h<<<gD, blk, GEMM_SMEM_BYTES>>>(
            pHb, pwf2 + fOff, bf2 + vOff, Y,
            Y, nullptr, MTOK, DD, FF, 0, DD);
        float* outl = out + aOff;
        layernorm_row<<<MTOK, blk>>>(Y, g3 + vOff, be3 + vOff, outl, pX);

        Xh = pX;
    }
    (void)in_sizes; (void)n_in; (void)out_size;
}

// round 10
// speedup vs baseline: 5.0080x; 1.4248x over previous
#include <cuda_runtime.h>
#include <cuda_fp16.h>
#include <mma.h>
#include <cstddef>
#include <cstdint>

using namespace nvcuda;

#define LLAYERS 6
#define BB 4
#define NN 1024
#define DD 1024
#define HH 16
#define HDIM 64
#define FF 4096
#define MTOK (BB * NN)      /* 4096 */
#define LN_EPS 1e-5f

// ---------------- scratch (no allocations allowed) ----------------
__device__ float  g_Y[(size_t)MTOK * DD];
__device__ float  g_Y1[(size_t)LLAYERS * MTOK * DD];
// fp16 mirrors
__device__ __half h_wq1[(size_t)LLAYERS * DD * DD];
__device__ __half h_wo1[(size_t)LLAYERS * DD * DD];
__device__ __half h_wq2[(size_t)LLAYERS * DD * DD];
__device__ __half h_wo2[(size_t)LLAYERS * DD * DD];
__device__ __half h_wf1[(size_t)LLAYERS * FF * DD];
__device__ __half h_wf2[(size_t)LLAYERS * DD * FF];
__device__ __half h_feats[(size_t)LLAYERS * MTOK * DD];
__device__ __half h_enc[(size_t)MTOK * DD];
// packed KV weights / biases
__device__ __half h_KV1w[(size_t)LLAYERS * 2 * DD * DD];
__device__ __half h_KV2w[(size_t)LLAYERS * 2 * DD * DD];
__device__ float  g_bKV1[(size_t)LLAYERS * 2 * DD];
__device__ float  g_bKV2[(size_t)LLAYERS * 2 * DD];
// activations
__device__ __half h_KV1[(size_t)LLAYERS * MTOK * 2 * DD];
__device__ __half h_Q1[(size_t)LLAYERS * MTOK * DD];
__device__ __half h_T1[(size_t)LLAYERS * MTOK * DD];
__device__ __half h_Yh1[(size_t)LLAYERS * MTOK * DD];
__device__ __half h_KV2[(size_t)MTOK * 2 * DD];
__device__ __half h_Q[(size_t)MTOK * DD];
__device__ __half h_T[(size_t)MTOK * DD];
__device__ __half h_Yh[(size_t)MTOK * DD];
__device__ __half h_X[(size_t)MTOK * DD];
__device__ __half h_Hb[(size_t)MTOK * FF];

// ---------------- cp.async helpers ----------------
__device__ __forceinline__ void cp16(void* sptr, const void* gptr) {
    uint32_t sa = (uint32_t)__cvta_generic_to_shared(sptr);
    asm volatile("cp.async.cg.shared.global [%0], [%1], 16;\n" :: "r"(sa), "l"(gptr));
}
#define CP_COMMIT() asm volatile("cp.async.commit_group;\n" ::: "memory")
#define CP_WAIT_0() asm volatile("cp.async.wait_group 0;\n" ::: "memory")
#define CP_WAIT_1() asm volatile("cp.async.wait_group 1;\n" ::: "memory")

// ---------------- raw mma / ldmatrix helpers ----------------
__device__ __forceinline__ void mma16816(float* d, const uint32_t* a, const uint32_t* b) {
    asm volatile(
        "mma.sync.aligned.m16n8k16.row.col.f32.f16.f16.f32 "
        "{%0,%1,%2,%3}, {%4,%5,%6,%7}, {%8,%9}, {%0,%1,%2,%3};\n"
        : "+f"(d[0]), "+f"(d[1]), "+f"(d[2]), "+f"(d[3])
        : "r"(a[0]), "r"(a[1]), "r"(a[2]), "r"(a[3]), "r"(b[0]), "r"(b[1]));
}
__device__ __forceinline__ void ldsm4(uint32_t* r, uint32_t addr) {
    asm volatile("ldmatrix.sync.aligned.m8n8.x4.shared.b16 {%0,%1,%2,%3}, [%4];\n"
        : "=r"(r[0]), "=r"(r[1]), "=r"(r[2]), "=r"(r[3]) : "r"(addr));
}
__device__ __forceinline__ void ldsm4t(uint32_t* r, uint32_t addr) {
    asm volatile("ldmatrix.sync.aligned.m8n8.x4.trans.shared.b16 {%0,%1,%2,%3}, [%4];\n"
        : "=r"(r[0]), "=r"(r[1]), "=r"(r[2]), "=r"(r[3]) : "r"(addr));
}
__device__ __forceinline__ uint32_t h2pack(float a, float b) {
    __half2 h = __floats2half2_rn(a, b);
    return *(uint32_t*)&h;
}

// =====================================================================
// Conversion / packing kernels
// =====================================================================
__global__ __launch_bounds__(256) void cvt_f2h(
    const float* __restrict__ s, __half* __restrict__ d, long n)
{
    long i = ((long)blockIdx.x * 256 + threadIdx.x) * 8;
    if (i >= n) return;
    float4 a = *(const float4*)(s + i);
    float4 b = *(const float4*)(s + i + 4);
    uint4 u;
    ((__half2*)&u)[0] = __floats2half2_rn(a.x, a.y);
    ((__half2*)&u)[1] = __floats2half2_rn(a.z, a.w);
    ((__half2*)&u)[2] = __floats2half2_rn(b.x, b.y);
    ((__half2*)&u)[3] = __floats2half2_rn(b.z, b.w);
    *(uint4*)(d + i) = u;
}

__global__ __launch_bounds__(256) void pack_w(
    const float* __restrict__ a, const float* __restrict__ b,
    __half* __restrict__ dst, long perL)
{
    long i = ((long)blockIdx.x * 256 + threadIdx.x) * 8;
    long l = i / (2 * perL);
    long r = i - l * 2 * perL;
    const float* src = (r < perL) ? a + l * perL + r : b + l * perL + (r - perL);
    float4 x = *(const float4*)(src);
    float4 y = *(const float4*)(src + 4);
    uint4 u;
    ((__half2*)&u)[0] = __floats2half2_rn(x.x, x.y);
    ((__half2*)&u)[1] = __floats2half2_rn(x.z, x.w);
    ((__half2*)&u)[2] = __floats2half2_rn(y.x, y.y);
    ((__half2*)&u)[3] = __floats2half2_rn(y.z, y.w);
    *(uint4*)(dst + i) = u;
}

__global__ __launch_bounds__(256) void pack_b(
    const float* __restrict__ a, const float* __restrict__ b,
    float* __restrict__ dst, long perL)
{
    long i = ((long)blockIdx.x * 256 + threadIdx.x) * 4;
    long l = i / (2 * perL);
    long r = i - l * 2 * perL;
    const float* src = (r < perL) ? a + l * perL + r : b + l * perL + (r - perL);
    *(float4*)(dst + i) = *(const float4*)src;
}

// =====================================================================
// f16 TC GEMM (unchanged from round 8/9)
// =====================================================================
#define GBKH 64
#define GSTH 72
#define GBUFH (128 * GSTH)
#define GEMM_SMEM_BYTES (4 * GBUFH * 2)   /* 73728 B */

__global__ __launch_bounds__(256, 2) void gemm_h(
    const __half* __restrict__ A, const __half* __restrict__ W,
    const float* __restrict__ bias, const float* __restrict__ res,
    float* __restrict__ C, __half* __restrict__ Ch,
    int M, int N, int K, int doRelu, int ldc)
{
    extern __shared__ char dynb[];
    __half* hsm = (__half*)dynb;
    __shared__ float stage[8][16 * 16];

    const int tid  = threadIdx.x;
    const int warp = tid >> 5;
    const int lane = tid & 31;
    const int wm   = warp >> 2;
    const int wn   = warp & 3;

    const __half* Ab = A + (size_t)blockIdx.y * 128 * K;
    const __half* Wb = W + (size_t)blockIdx.x * 128 * K;
    const int KT = K / GBKH;

    wmma::fragment<wmma::accumulator, 16, 16, 16, float> acc[4][2];
#pragma unroll
    for (int i = 0; i < 4; i++)
#pragma unroll
        for (int j = 0; j < 2; j++) wmma::fill_fragment(acc[i][j], 0.f);

    {
        __half* As = hsm;
        __half* Ws = hsm + GBUFH;
#pragma unroll
        for (int t = 0; t < 4; t++) {
            int c = tid + t * 256;
            int row = c >> 3, col8 = c & 7;
            cp16(As + row * GSTH + col8 * 8, Ab + (size_t)row * K + col8 * 8);
            cp16(Ws + row * GSTH + col8 * 8, Wb + (size_t)row * K + col8 * 8);
        }
        CP_COMMIT();
    }

    for (int kt = 0; kt < KT; kt++) {
        if (kt + 1 < KT) {
            __half* As = hsm + ((kt + 1) & 1) * 2 * GBUFH;
            __half* Ws = As + GBUFH;
            const int k0 = (kt + 1) * GBKH;
#pragma unroll
            for (int t = 0; t < 4; t++) {
                int c = tid + t * 256;
                int row = c >> 3, col8 = c & 7;
                cp16(As + row * GSTH + col8 * 8, Ab + (size_t)row * K + k0 + col8 * 8);
                cp16(Ws + row * GSTH + col8 * 8, Wb + (size_t)row * K + k0 + col8 * 8);
            }
            CP_COMMIT();
            CP_WAIT_1();
        } else {
            CP_WAIT_0();
        }
        __syncthreads();

        const __half* As = hsm + (kt & 1) * 2 * GBUFH;
        const __half* Ws = As + GBUFH;
#pragma unroll
        for (int kk = 0; kk < 4; kk++) {
            wmma::fragment<wmma::matrix_a, 16, 16, 16, __half, wmma::row_major> af[4];
            wmma::fragment<wmma::matrix_b, 16, 16, 16, __half, wmma::col_major> bf[2];
#pragma unroll
            for (int i = 0; i < 4; i++)
                wmma::load_matrix_sync(af[i], &As[(wm * 64 + i * 16) * GSTH + kk * 16], GSTH);
#pragma unroll
            for (int j = 0; j < 2; j++)
                wmma::load_matrix_sync(bf[j], &Ws[(wn * 32 + j * 16) * GSTH + kk * 16], GSTH);
#pragma unroll
            for (int i = 0; i < 4; i++)
#pragma unroll
                for (int j = 0; j < 2; j++)
                    wmma::mma_sync(acc[i][j], af[i], bf[j], acc[i][j]);
        }
        __syncthreads();
    }

#pragma unroll
    for (int i = 0; i < 4; i++) {
#pragma unroll
        for (int j = 0; j < 2; j++) {
            wmma::store_matrix_sync(stage[warp], acc[i][j], 16, wmma::mem_row_major);
            __syncwarp();
            int r0 = blockIdx.y * 128 + wm * 64 + i * 16;
            int c0 = blockIdx.x * 128 + wn * 32 + j * 16;
#pragma unroll
            for (int e = 0; e < 2; e++) {
                int idx = lane + e * 32;
                int rr  = idx >> 2;
                int cc  = (idx & 3) << 2;
                float4 v  = *(float4*)&stage[warp][rr * 16 + cc];
                float4 b4 = *(const float4*)(bias + c0 + cc);
                v.x += b4.x; v.y += b4.y; v.z += b4.z; v.w += b4.w;
                size_t row = (size_t)(r0 + rr);
                if (res) {
                    float4 r = *(const float4*)(res + row * ldc + c0 + cc);
                    v.x += r.x; v.y += r.y; v.z += r.z; v.w += r.w;
                }
                if (doRelu) {
                    v.x = fmaxf(v.x, 0.f); v.y = fmaxf(v.y, 0.f);
                    v.z = fmaxf(v.z, 0.f); v.w = fmaxf(v.w, 0.f);
                }
                if (C) *(float4*)(C + row * ldc + c0 + cc) = v;
                if (Ch) {
                    uint2 u;
                    ((__half2*)&u)[0] = __floats2half2_rn(v.x, v.y);
                    ((__half2*)&u)[1] = __floats2half2_rn(v.z, v.w);
                    *(uint2*)(Ch + row * ldc + c0 + cc) = u;
                }
            }
            __syncwarp();
        }
    }
}

// =====================================================================
// Flash attention v4: register-resident S/P/O (FA2 style, raw mma).
// Block = 128 Q rows, 8 warps; warp w owns rows w*16..w*16+15.
// Lane l: g=l>>2 (rows g, g+8 of the warp tile), t=l&3.
// S accum: 8 n-tiles x 4 f32; P packed reg->A-operand identity; O in regs.
// K/V triple-buffered cp.async; ONE __syncthreads per j-tile.
// grid: (N/128, B*H)
// =====================================================================
#define AQ_ST 72                       /* halves; row = 144 B */
#define ATQ_OFF 0                      /* Q: 128*144 = 18432 */
#define ATK_OFF(s) (18432 + (s) * 9216)
#define ATV_OFF(s) (46080 + (s) * 9216)
#define ATT_SMEM_BYTES 73728

__global__ __launch_bounds__(256, 2) void attn_h(
    const __half* __restrict__ Q, const __half* __restrict__ Kb,
    const __half* __restrict__ V, __half* __restrict__ T,
    const float* __restrict__ mask, int ldkv)
{
    extern __shared__ char dynb[];
    const uint32_t sb = (uint32_t)__cvta_generic_to_shared(dynb);

    const int z = blockIdx.y;
    const int b = z >> 4, hh = z & 15;
    const __half* Qz = Q  + (size_t)b * NN * DD   + hh * HDIM;
    const __half* Kz = Kb + (size_t)b * NN * ldkv + hh * HDIM;
    const __half* Vz = V  + (size_t)b * NN * ldkv + hh * HDIM;
    __half*       Tz = T  + (size_t)b * NN * DD   + hh * HDIM;
    const int i0 = blockIdx.x * 128;

    const int tid  = threadIdx.x;
    const int warp = tid >> 5;
    const int lane = tid & 31;
    const int g    = lane >> 2;          // row in warp tile (and +8)
    const int t    = lane & 3;
    const int q    = lane >> 3;          // ldmatrix quad
    const int qr   = lane & 7;           // row within quad

    // per-lane ldmatrix byte offsets (within a tile)
    const uint32_t qlane = (uint32_t)(((q & 1) * 8 + qr + warp * 16) * 144 + (q >> 1) * 16);
    const uint32_t klane = (uint32_t)(((q >> 1) * 8 + qr) * 144 + (q & 1) * 16);
    const uint32_t vlane = (uint32_t)(((q & 1) * 8 + qr) * 144 + (q >> 1) * 16);

    const float* mrow0 = mask + (size_t)(i0 + warp * 16 + g) * NN;
    const float* mrow1 = mrow0 + 8 * NN;

    // ---- preload: group0 = {Q, K0, V0}, group1 = {K1, V1} ----
    {
        __half* Qs = (__half*)(dynb + ATQ_OFF);
#pragma unroll
        for (int c0 = 0; c0 < 4; c0++) {
            int c = tid + c0 * 256;          // 1024 chunks
            int row = c >> 3, col8 = c & 7;
            cp16(Qs + row * AQ_ST + col8 * 8, Qz + (size_t)(i0 + row) * DD + col8 * 8);
        }
        __half* Ks = (__half*)(dynb + ATK_OFF(0));
        __half* Vs = (__half*)(dynb + ATV_OFF(0));
#pragma unroll
        for (int c0 = 0; c0 < 2; c0++) {
            int c = tid + c0 * 256;          // 512 chunks
            int row = c >> 3, col8 = c & 7;
            cp16(Ks + row * AQ_ST + col8 * 8, Kz + (size_t)row * ldkv + col8 * 8);
            cp16(Vs + row * AQ_ST + col8 * 8, Vz + (size_t)row * ldkv + col8 * 8);
        }
        CP_COMMIT();
        Ks = (__half*)(dynb + ATK_OFF(1));
        Vs = (__half*)(dynb + ATV_OFF(1));
#pragma unroll
        for (int c0 = 0; c0 < 2; c0++) {
            int c = tid + c0 * 256;
            int row = c >> 3, col8 = c & 7;
            cp16(Ks + row * AQ_ST + col8 * 8, Kz + (size_t)(64 + row) * ldkv + col8 * 8);
            cp16(Vs + row * AQ_ST + col8 * 8, Vz + (size_t)(64 + row) * ldkv + col8 * 8);
        }
        CP_COMMIT();
    }

    CP_WAIT_1();          // Q + stage 0 complete (this thread)
    __syncthreads();      // visible block-wide

    // Q fragments (constant across j-tiles)
    uint32_t qa[4][4];
#pragma unroll
    for (int kk = 0; kk < 4; kk++)
        ldsm4(qa[kk], sb + ATQ_OFF + qlane + kk * 32);

    float o[8][4];
#pragma unroll
    for (int i = 0; i < 8; i++) { o[i][0] = o[i][1] = o[i][2] = o[i][3] = 0.f; }
    float m0 = -1e30f, m1 = -1e30f, sr0 = 0.f, sr1 = 0.f;

    const int J = NN / 64;
    for (int j0 = 0; j0 < J; j0++) {
        if (j0 > 0) {
            if (j0 + 1 < J) { CP_WAIT_1(); } else { CP_WAIT_0(); }
            __syncthreads();     // stage j0 visible; iter j0-1 reads done
        }
        if (j0 + 2 < J) {
            const int st = (j0 + 2) % 3;
            __half* Ks = (__half*)(dynb + ATK_OFF(st));
            __half* Vs = (__half*)(dynb + ATV_OFF(st));
            const size_t rbase = (size_t)(j0 + 2) * 64;
#pragma unroll
            for (int c0 = 0; c0 < 2; c0++) {
                int c = tid + c0 * 256;
                int row = c >> 3, col8 = c & 7;
                cp16(Ks + row * AQ_ST + col8 * 8, Kz + (rbase + row) * ldkv + col8 * 8);
                cp16(Vs + row * AQ_ST + col8 * 8, Vz + (rbase + row) * ldkv + col8 * 8);
            }
            CP_COMMIT();
        }

        const uint32_t ksb = sb + ATK_OFF(j0 % 3);
        const uint32_t vsb = sb + ATV_OFF(j0 % 3);

        // ---- S = Q @ K^T (register accum) ----
        float s[8][4];
#pragma unroll
        for (int i = 0; i < 8; i++) { s[i][0] = s[i][1] = s[i][2] = s[i][3] = 0.f; }
#pragma unroll
        for (int nt2 = 0; nt2 < 4; nt2++) {
#pragma unroll
            for (int kk = 0; kk < 4; kk++) {
                uint32_t kb[4];
                ldsm4(kb, ksb + (uint32_t)(nt2 * 2304 + kk * 32) + klane);
                mma16816(s[2 * nt2],     qa[kk], kb);
                mma16816(s[2 * nt2 + 1], qa[kk], kb + 2);
            }
        }

        // ---- online softmax in registers ----
        float mx0 = m0, mx1 = m1;
#pragma unroll
        for (int nt = 0; nt < 8; nt++) {
            int col = j0 * 64 + nt * 8 + 2 * t;
            float2 k0 = *(const float2*)(mrow0 + col);
            float2 k1 = *(const float2*)(mrow1 + col);
            s[nt][0] = fmaf(s[nt][0], 0.125f, k0.x);
            s[nt][1] = fmaf(s[nt][1], 0.125f, k0.y);
            s[nt][2] = fmaf(s[nt][2], 0.125f, k1.x);
            s[nt][3] = fmaf(s[nt][3], 0.125f, k1.y);
            mx0 = fmaxf(mx0, fmaxf(s[nt][0], s[nt][1]));
            mx1 = fmaxf(mx1, fmaxf(s[nt][2], s[nt][3]));
        }
        mx0 = fmaxf(mx0, __shfl_xor_sync(0xffffffffu, mx0, 1));
        mx0 = fmaxf(mx0, __shfl_xor_sync(0xffffffffu, mx0, 2));
        mx1 = fmaxf(mx1, __shfl_xor_sync(0xffffffffu, mx1, 1));
        mx1 = fmaxf(mx1, __shfl_xor_sync(0xffffffffu, mx1, 2));
        const float c0 = __expf(m0 - mx0);
        const float c1 = __expf(m1 - mx1);

        uint32_t pa[4][4];
        float sum0 = 0.f, sum1 = 0.f;
#pragma unroll
        for (int nt = 0; nt < 8; nt++) {
            float p0 = __expf(s[nt][0] - mx0);
            float p1 = __expf(s[nt][1] - mx0);
            float p2 = __expf(s[nt][2] - mx1);
            float p3 = __expf(s[nt][3] - mx1);
            sum0 += p0 + p1; sum1 += p2 + p3;
            pa[nt >> 1][(nt & 1) * 2 + 0] = h2pack(p0, p1);
            pa[nt >> 1][(nt & 1) * 2 + 1] = h2pack(p2, p3);
        }
        sum0 += __shfl_xor_sync(0xffffffffu, sum0, 1);
        sum0 += __shfl_xor_sync(0xffffffffu, sum0, 2);
        sum1 += __shfl_xor_sync(0xffffffffu, sum1, 1);
        sum1 += __shfl_xor_sync(0xffffffffu, sum1, 2);
        sr0 = sr0 * c0 + sum0;
        sr1 = sr1 * c1 + sum1;
        m0 = mx0; m1 = mx1;
#pragma unroll
        for (int nt = 0; nt < 8; nt++) {
            o[nt][0] *= c0; o[nt][1] *= c0;
            o[nt][2] *= c1; o[nt][3] *= c1;
        }

        // ---- O += P @ V ----
#pragma unroll
        for (int nt2 = 0; nt2 < 4; nt2++) {
#pragma unroll
            for (int kt = 0; kt < 4; kt++) {
                uint32_t vb[4];
                ldsm4t(vb, vsb + (uint32_t)(kt * 2304 + nt2 * 32) + vlane);
                mma16816(o[2 * nt2],     pa[kt], vb);
                mma16816(o[2 * nt2 + 1], pa[kt], vb + 2);
            }
        }
    }

    // ---- epilogue: scale by 1/sum, scatter half2 stores ----
    const float inv0 = 1.f / sr0;
    const float inv1 = 1.f / sr1;
    __half* tr0 = Tz + (size_t)(i0 + warp * 16 + g) * DD + 2 * t;
    __half* tr1 = tr0 + 8 * DD;
#pragma unroll
    for (int nt = 0; nt < 8; nt++) {
        uint32_t u0 = h2pack(o[nt][0] * inv0, o[nt][1] * inv0);
        uint32_t u1 = h2pack(o[nt][2] * inv1, o[nt][3] * inv1);
        *(uint32_t*)(tr0 + nt * 8) = u0;
        *(uint32_t*)(tr1 + nt * 8) = u1;
    }
}

// =====================================================================
// LayerNorm over last dim (1024); f32 out + optional f16 out.
// =====================================================================
__global__ __launch_bounds__(256) void layernorm_row(
    const float* __restrict__ X, const float* __restrict__ g,
    const float* __restrict__ bta, float* __restrict__ Y,
    __half* __restrict__ Yh)
{
    __shared__ float red[256];
    const size_t base = (size_t)blockIdx.x * DD;
    const int tid = threadIdx.x;
    float4 v = *(const float4*)(X + base + tid * 4);

    red[tid] = v.x + v.y + v.z + v.w; __syncthreads();
    for (int s = 128; s > 0; s >>= 1) {
        if (tid < s) red[tid] += red[tid + s];
        __syncthreads();
    }
    float mean = red[0] * (1.f / DD); __syncthreads();

    float dx = v.x - mean, dy = v.y - mean, dz = v.z - mean, dw = v.w - mean;
    red[tid] = dx * dx + dy * dy + dz * dz + dw * dw; __syncthreads();
    for (int s = 128; s > 0; s >>= 1) {
        if (tid < s) red[tid] += red[tid + s];
        __syncthreads();
    }
    float inv = rsqrtf(red[0] * (1.f / DD) + LN_EPS);

    float4 gg = *(const float4*)(g + tid * 4);
    float4 bb = *(const float4*)(bta + tid * 4);
    float4 o;
    o.x = dx * inv * gg.x + bb.x;
    o.y = dy * inv * gg.y + bb.y;
    o.z = dz * inv * gg.z + bb.z;
    o.w = dw * inv * gg.w + bb.w;
    *(float4*)(Y + base + tid * 4) = o;
    if (Yh) {
        uint2 u;
        ((__half2*)&u)[0] = __floats2half2_rn(o.x, o.y);
        ((__half2*)&u)[1] = __floats2half2_rn(o.z, o.w);
        *(uint2*)(Yh + base + tid * 4) = u;
    }
}

// =====================================================================
// Host orchestration: dual-stream fork-join (unchanged from round 9)
// =====================================================================
static inline void cvt(const float* src, __half* dst, long n) {
    cvt_f2h<<<(unsigned)(n / 2048), 256>>>(src, dst, n);
}

extern "C" void kernel_launch(void* const* d_in, const int* in_sizes, int n_in,
                              void* d_out, int out_size)
{
    const float* feats    = (const float*)d_in[0];
    const float* enc      = (const float*)d_in[1];
    const float* trg_mask = (const float*)d_in[2];
    const float* src_mask = (const float*)d_in[3];
    const float* wq1 = (const float*)d_in[4];  const float* bq1 = (const float*)d_in[5];
    const float* wk1 = (const float*)d_in[6];  const float* bk1 = (const float*)d_in[7];
    const float* wv1 = (const float*)d_in[8];  const float* bv1 = (const float*)d_in[9];
    const float* wo1 = (const float*)d_in[10]; const float* bo1 = (const float*)d_in[11];
    const float* wq2 = (const float*)d_in[12]; const float* bq2 = (const float*)d_in[13];
    const float* wk2 = (const float*)d_in[14]; const float* bk2 = (const float*)d_in[15];
    const float* wv2 = (const float*)d_in[16]; const float* bv2 = (const float*)d_in[17];
    const float* wo2 = (const float*)d_in[18]; const float* bo2 = (const float*)d_in[19];
    const float* wf1 = (const float*)d_in[20]; const float* bf1 = (const float*)d_in[21];
    const float* wf2 = (const float*)d_in[22]; const float* bf2 = (const float*)d_in[23];
    const float* g1  = (const float*)d_in[24]; const float* be1 = (const float*)d_in[25];
    const float* g2  = (const float*)d_in[26]; const float* be2 = (const float*)d_in[27];
    const float* g3  = (const float*)d_in[28]; const float* be3 = (const float*)d_in[29];
    float* out = (float*)d_out;

    static int init_done = 0;
    static cudaStream_t s2;
    static cudaEvent_t evF;
    static cudaEvent_t evL[LLAYERS];
    if (!init_done) {
        cudaFuncSetAttribute(gemm_h,
            cudaFuncAttributeMaxDynamicSharedMemorySize, GEMM_SMEM_BYTES);
        cudaFuncSetAttribute(attn_h,
            cudaFuncAttributeMaxDynamicSharedMemorySize, ATT_SMEM_BYTES);
        cudaStreamCreateWithFlags(&s2, cudaStreamNonBlocking);
        cudaEventCreateWithFlags(&evF, cudaEventDisableTiming);
        for (int l = 0; l < LLAYERS; l++)
            cudaEventCreateWithFlags(&evL[l], cudaEventDisableTiming);
        init_done = 1;
    }

    float *Y, *Y1, *pbKV1, *pbKV2;
    cudaGetSymbolAddress((void**)&Y,  g_Y);
    cudaGetSymbolAddress((void**)&Y1, g_Y1);
    cudaGetSymbolAddress((void**)&pbKV1, g_bKV1);
    cudaGetSymbolAddress((void**)&pbKV2, g_bKV2);
    __half *pwq1, *pwo1, *pwq2, *pwo2, *pwf1, *pwf2, *pfeats, *penc;
    __half *pKV1w, *pKV2w, *pKV1, *pQ1, *pT1, *pYh1, *pKV2, *pQ, *pT, *pYh, *pX, *pHb;
    cudaGetSymbolAddress((void**)&pwq1, h_wq1);
    cudaGetSymbolAddress((void**)&pwo1, h_wo1);
    cudaGetSymbolAddress((void**)&pwq2, h_wq2);
    cudaGetSymbolAddress((void**)&pwo2, h_wo2);
    cudaGetSymbolAddress((void**)&pwf1, h_wf1);
    cudaGetSymbolAddress((void**)&pwf2, h_wf2);
    cudaGetSymbolAddress((void**)&pfeats, h_feats);
    cudaGetSymbolAddress((void**)&penc, h_enc);
    cudaGetSymbolAddress((void**)&pKV1w, h_KV1w);
    cudaGetSymbolAddress((void**)&pKV2w, h_KV2w);
    cudaGetSymbolAddress((void**)&pKV1, h_KV1);
    cudaGetSymbolAddress((void**)&pQ1, h_Q1);
    cudaGetSymbolAddress((void**)&pT1, h_T1);
    cudaGetSymbolAddress((void**)&pYh1, h_Yh1);
    cudaGetSymbolAddress((void**)&pKV2, h_KV2);
    cudaGetSymbolAddress((void**)&pQ, h_Q);
    cudaGetSymbolAddress((void**)&pT, h_T);
    cudaGetSymbolAddress((void**)&pYh, h_Yh);
    cudaGetSymbolAddress((void**)&pX, h_X);
    cudaGetSymbolAddress((void**)&pHb, h_Hb);

    const long nDD = (long)LLAYERS * DD * DD;
    const long nFD = (long)LLAYERS * FF * DD;

    // ---- A-set conversions on stream 0 ----
    cvt(enc, penc, (long)MTOK * DD);
    cvt(feats, pfeats, (long)LLAYERS * MTOK * DD);
    cvt(wq1, pwq1, nDD);
    cvt(wo1, pwo1, nDD);
    pack_w<<<(unsigned)(2 * nDD / 2048), 256>>>(wk1, wv1, pKV1w, (long)DD * DD);
    pack_b<<<(unsigned)(2 * LLAYERS * DD / 1024), 256>>>(bk1, bv1, pbKV1, DD);

    dim3 blk(256);
    dim3 gD(DD / 128, MTOK / 128);             // 8 x 32
    dim3 gKV(2 * DD / 128, MTOK / 128);        // 16 x 32
    dim3 gF(FF / 128, MTOK / 128);             // 32 x 32
    dim3 gA(NN / 128, BB * HH);                // 8 x 64

    // ---- fork: phase A (attn1 branch) on s2 ----
    cudaEventRecord(evF, 0);
    cudaStreamWaitEvent(s2, evF, 0);

    for (int l = 0; l < LLAYERS; l++) {
        const size_t wOff = (size_t)l * DD * DD;
        const size_t vOff = (size_t)l * DD;
        const size_t aOff = (size_t)l * MTOK * DD;
        const size_t kOff = (size_t)l * MTOK * 2 * DD;

        gemm_h<<<gD, blk, GEMM_SMEM_BYTES, s2>>>(
            pfeats + aOff, pwq1 + wOff, bq1 + vOff, nullptr,
            nullptr, pQ1 + aOff, MTOK, DD, DD, 0, DD);
        gemm_h<<<gKV, blk, GEMM_SMEM_BYTES, s2>>>(
            penc, pKV1w + 2 * wOff, pbKV1 + 2 * vOff, nullptr,
            nullptr, pKV1 + kOff, MTOK, 2 * DD, DD, 0, 2 * DD);
        attn_h<<<gA, blk, ATT_SMEM_BYTES, s2>>>(
            pQ1 + aOff, pKV1 + kOff, pKV1 + kOff + DD, pT1 + aOff,
            src_mask, 2 * DD);
        gemm_h<<<gD, blk, GEMM_SMEM_BYTES, s2>>>(
            pT1 + aOff, pwo1 + wOff, bo1 + vOff, feats + aOff,
            Y1 + aOff, nullptr, MTOK, DD, DD, 0, DD);
        layernorm_row<<<MTOK, blk, 0, s2>>>(
            Y1 + aOff, g1 + vOff, be1 + vOff, Y1 + aOff, pYh1 + aOff);
        cudaEventRecord(evL[l], s2);
    }

    // ---- B-set conversions on stream 0 (overlap phase A) ----
    cvt(wq2, pwq2, nDD);
    cvt(wo2, pwo2, nDD);
    cvt(wf1, pwf1, nFD);
    cvt(wf2, pwf2, nFD);
    pack_w<<<(unsigned)(2 * nDD / 2048), 256>>>(wk2, wv2, pKV2w, (long)DD * DD);
    pack_b<<<(unsigned)(2 * LLAYERS * DD / 1024), 256>>>(bk2, bv2, pbKV2, DD);

    // ---- phase B: serial decoder chain on stream 0 ----
    const __half* Xh = penc;
    for (int l = 0; l < LLAYERS; l++) {
        const size_t wOff = (size_t)l * DD * DD;
        const size_t fOff = (size_t)l * FF * DD;
        const size_t vOff = (size_t)l * DD;
        const size_t aOff = (size_t)l * MTOK * DD;

        cudaStreamWaitEvent(0, evL[l], 0);

        gemm_h<<<gD, blk, GEMM_SMEM_BYTES>>>(
            pYh1 + aOff, pwq2 + wOff, bq2 + vOff, nullptr,
            nullptr, pQ, MTOK, DD, DD, 0, DD);
        gemm_h<<<gKV, blk, GEMM_SMEM_BYTES>>>(
            Xh, pKV2w + 2 * wOff, pbKV2 + 2 * vOff, nullptr,
            nullptr, pKV2, MTOK, 2 * DD, DD, 0, 2 * DD);
        attn_h<<<gA, blk, ATT_SMEM_BYTES>>>(
            pQ, pKV2, pKV2 + DD, pT, trg_mask, 2 * DD);
        gemm_h<<<gD, blk, GEMM_SMEM_BYTES>>>(
            pT, pwo2 + wOff, bo2 + vOff, Y1 + aOff,
            Y, nullptr, MTOK, DD, DD, 0, DD);
        layernorm_row<<<MTOK, blk>>>(Y, g2 + vOff, be2 + vOff, Y, pYh);

        gemm_h<<<gF, blk, GEMM_SMEM_BYTES>>>(
            pYh, pwf1 + fOff, bf1 + (size_t)l * FF, nullptr,
            nullptr, pHb, MTOK, FF, DD, 1, FF);
        gemm_h<<<gD, blk, GEMM_SMEM_BYTES>>>(
            pHb, pwf2 + fOff, bf2 + vOff, Y,
            Y, nullptr, MTOK, DD, FF, 0, DD);
        float* outl = out + aOff;
        layernorm_row<<<MTOK, blk>>>(Y, g3 + vOff, be3 + vOff, outl, pX);

        Xh = pX;
    }
    (void)in_sizes; (void)n_in; (void)out_size;
}